// round 7
// baseline (speedup 1.0000x reference)
#include <cuda_runtime.h>
#include <cstdint>
#include <math.h>

// ---------------------------------------------------------------------------
// Swin stage on GB300 (compute_103: mma.sync tf32 path).
// R7: batched-head attention (coalesced qkv reads), stats-phase fix, 1 transpose.
// ---------------------------------------------------------------------------

#define TOK 200704          // 64*56*56
#define DSTOK 50176         // 64*28*28

__device__ float g_x  [(size_t)TOK * 128];
__device__ float g_qkv[(size_t)TOK * 384];
__device__ float g_o  [(size_t)TOK * 128];
__device__ float g_hid[(size_t)TOK * 512];
__device__ float g_ds [(size_t)DSTOK * 512];
__device__ float g_wt [524288];   // transposed weights [N,K] K-major, tf32-rounded

__device__ __forceinline__ uint32_t f2tf32(float f) {
    uint32_t u; asm("cvt.rna.tf32.f32 %0, %1;" : "=r"(u) : "f"(f)); return u;
}
__device__ __forceinline__ uint32_t smem_u32(const void* p) {
    uint32_t a;
    asm("{ .reg .u64 t; cvta.to.shared.u64 t, %1; cvt.u32.u64 %0, t; }" : "=r"(a) : "l"(p));
    return a;
}

#define CP_ASYNC16(dst, src) \
    asm volatile("cp.async.cg.shared.global [%0], [%1], 16;" :: "r"(dst), "l"(src))
#define CP_COMMIT() asm volatile("cp.async.commit_group;" ::: "memory")
#define CP_WAITG(n) asm volatile("cp.async.wait_group %0;" :: "n"(n) : "memory")

#define MMA_TF32(d, a, b) \
    asm volatile("mma.sync.aligned.m16n8k8.row.col.f32.tf32.tf32.f32 " \
        "{%0,%1,%2,%3}, {%4,%5,%6,%7}, {%8,%9}, {%0,%1,%2,%3};" \
        : "+f"((d)[0]), "+f"((d)[1]), "+f"((d)[2]), "+f"((d)[3]) \
        : "r"((a)[0]), "r"((a)[1]), "r"((a)[2]), "r"((a)[3]), \
          "r"((b)[0]), "r"((b)[1]))

__device__ __forceinline__ float gelu_tanh(float v) {
    float u = 0.7978845608028654f * (v + 0.044715f * v * v * v);
    return 0.5f * v * (1.0f + tanhf(u));
}

// ===================== fused (LN +) GEMM, K=128 ==============================
#define BSTAGE 4608
#define LG_SMEM ((16896 + 2 * BSTAGE + 256) * 4)   // 105472 bytes

template <bool LN, bool GELU, bool RES>
__global__ void __launch_bounds__(256, 2)
ln_gemm128(const float* __restrict__ A, const float* __restrict__ WT,
           const float* __restrict__ lng, const float* __restrict__ lnb,
           const float* __restrict__ bias, const float* __restrict__ R,
           float* __restrict__ C, int N)
{
    extern __shared__ float sm[];
    float* Af     = sm;                    // [128][132]
    float* Bsm    = sm + 16896;            // 2 x [128][36]
    float* s_rstd = sm + 16896 + 2 * BSTAGE;
    float* s_mrs  = s_rstd + 128;
    const uint32_t sm0 = smem_u32(sm);
    const uint32_t AfB = sm0;
    const uint32_t BsB = sm0 + 16896 * 4;

    const int tid  = threadIdx.x;
    const int wid  = tid >> 5, lane = tid & 31;
    const int gID  = lane >> 2, tig = lane & 3;
    const int warpM = wid & 3, warpN = wid >> 2;
    const int rowBase = blockIdx.y << 7;
    const int colBase = blockIdx.x << 7;

    // ---- issue full A tile (group 0)
#pragma unroll
    for (int i = 0; i < 16; i++) {
        int seg = tid + (i << 8);
        int r = seg >> 5, c4 = (seg & 31) << 2;
        CP_ASYNC16(AfB + (uint32_t)(r * 132 + c4) * 4,
                   A + (size_t)(rowBase + r) * 128 + c4);
    }
    CP_COMMIT();

    const int lrB = tid >> 3, lcB = (tid & 7) << 2;
#define ISSUE_B(c_, s_) do {                                                  \
        const int k0_ = (c_) << 5;                                           \
        const uint32_t so_ = BsB + (uint32_t)(s_) * (BSTAGE * 4);             \
        _Pragma("unroll")                                                     \
        for (int i_ = 0; i_ < 4; i_++) {                                      \
            int rB_ = lrB + (i_ << 5);                                        \
            CP_ASYNC16(so_ + (uint32_t)(rB_ * 36 + lcB) * 4,                  \
                       WT + (size_t)(colBase + rB_) * 128 + k0_ + lcB);       \
        }                                                                     \
        CP_COMMIT();                                                          \
    } while (0)

    ISSUE_B(0, 0);
    ISSUE_B(1, 1);

    float d[2][8][4];
#pragma unroll
    for (int mi = 0; mi < 2; mi++)
#pragma unroll
        for (int ni = 0; ni < 8; ni++)
#pragma unroll
            for (int e = 0; e < 4; e++) d[mi][ni][e] = 0.f;

    // ---- wait A, compute LN stats (256 threads, half row each + shfl pair)
    CP_WAITG(2);
    __syncthreads();
    if (LN) {
        const int row = tid >> 1, half = tid & 1;
        const float* rp = Af + row * 132 + half * 64;
        float s = 0.f, q = 0.f;
#pragma unroll 16
        for (int c = 0; c < 64; c++) { float v = rp[c]; s += v; q += v * v; }
        s += __shfl_xor_sync(0xffffffffu, s, 1);
        q += __shfl_xor_sync(0xffffffffu, q, 1);
        if (half == 0) {
            float mean = s * (1.0f / 128.0f);
            float var  = q * (1.0f / 128.0f) - mean * mean;
            float rstd = rsqrtf(var + 1e-5f);
            s_rstd[row] = rstd;
            s_mrs[row]  = mean * rstd;
        }
        __syncthreads();
    }

    const int rA = warpM * 32 + gID;
    const int cB = warpN * 64 + gID;

    float rstd_r[4], mrs_r[4];
    if (LN) {
#pragma unroll
        for (int h = 0; h < 4; h++) {
            rstd_r[h] = s_rstd[rA + h * 8];
            mrs_r[h]  = s_mrs[rA + h * 8];
        }
    }

#pragma unroll
    for (int c = 0; c < 4; c++) {
        const int s = c & 1;
        if (c == 3) { CP_WAITG(0); } else { CP_WAITG(1); }
        __syncthreads();
        const float* Bsl = Bsm + s * BSTAGE;
#pragma unroll
        for (int ksl = 0; ksl < 4; ksl++) {
            const int kk = ksl << 3;
            const int klo = (c << 5) + kk + tig;
            const int khi = klo + 4;
            uint32_t af[2][4], bf[8][2];
            if (LN) {
                float gl = __ldg(lng + klo), bl = __ldg(lnb + klo);
                float gh = __ldg(lng + khi), bh = __ldg(lnb + khi);
#pragma unroll
                for (int mi = 0; mi < 2; mi++) {
                    float r0lo = Af[(rA + mi * 16) * 132 + klo];
                    float r1lo = Af[(rA + mi * 16 + 8) * 132 + klo];
                    float r0hi = Af[(rA + mi * 16) * 132 + khi];
                    float r1hi = Af[(rA + mi * 16 + 8) * 132 + khi];
                    af[mi][0] = f2tf32(fmaf(fmaf(r0lo, rstd_r[mi * 2], -mrs_r[mi * 2]), gl, bl));
                    af[mi][1] = f2tf32(fmaf(fmaf(r1lo, rstd_r[mi * 2 + 1], -mrs_r[mi * 2 + 1]), gl, bl));
                    af[mi][2] = f2tf32(fmaf(fmaf(r0hi, rstd_r[mi * 2], -mrs_r[mi * 2]), gh, bh));
                    af[mi][3] = f2tf32(fmaf(fmaf(r1hi, rstd_r[mi * 2 + 1], -mrs_r[mi * 2 + 1]), gh, bh));
                }
            } else {
#pragma unroll
                for (int mi = 0; mi < 2; mi++) {
                    af[mi][0] = f2tf32(Af[(rA + mi * 16) * 132 + klo]);
                    af[mi][1] = f2tf32(Af[(rA + mi * 16 + 8) * 132 + klo]);
                    af[mi][2] = f2tf32(Af[(rA + mi * 16) * 132 + khi]);
                    af[mi][3] = f2tf32(Af[(rA + mi * 16 + 8) * 132 + khi]);
                }
            }
#pragma unroll
            for (int ni = 0; ni < 8; ni++) {
                bf[ni][0] = __float_as_uint(Bsl[(cB + ni * 8) * 36 + kk + tig]);
                bf[ni][1] = __float_as_uint(Bsl[(cB + ni * 8) * 36 + kk + tig + 4]);
            }
#pragma unroll
            for (int mi = 0; mi < 2; mi++)
#pragma unroll
                for (int ni = 0; ni < 8; ni++)
                    MMA_TF32(d[mi][ni], af[mi], bf[ni]);
        }
        __syncthreads();
        if (c + 2 < 4) ISSUE_B(c + 2, s);
    }
#undef ISSUE_B

    const int row0 = rowBase + warpM * 32 + gID;
    const int colW = colBase + warpN * 64 + (tig << 1);
#pragma unroll
    for (int ni = 0; ni < 8; ni++) {
        const int col = colW + ni * 8;
        float bx = 0.f, by = 0.f;
        if (bias) { bx = bias[col]; by = bias[col + 1]; }
#pragma unroll
        for (int mi = 0; mi < 2; mi++) {
#pragma unroll
            for (int half = 0; half < 2; half++) {
                int r = row0 + mi * 16 + half * 8;
                float vx = d[mi][ni][half * 2 + 0] + bx;
                float vy = d[mi][ni][half * 2 + 1] + by;
                if (GELU) { vx = gelu_tanh(vx); vy = gelu_tanh(vy); }
                size_t off = (size_t)r * N + col;
                if (RES) {
                    float2 rr = *(const float2*)(R + off);
                    vx += rr.x; vy += rr.y;
                }
                float2 o = { vx, vy };
                *(float2*)(C + off) = o;
            }
        }
    }
}

// ===================== generic K GEMM (K=512 paths) ==========================
#define GSTAGE 4608
#define GEMM_SMEM (2 * 2 * GSTAGE * 4)   // 73728 bytes

template <bool GELU, bool RES>
__global__ void __launch_bounds__(256, 2)
gemm_mma(const float* __restrict__ A, const float* __restrict__ WT,
         const float* __restrict__ bias, const float* __restrict__ R,
         float* __restrict__ C, int N, int K)
{
    extern __shared__ float sm[];
    const uint32_t sm0 = smem_u32(sm);
    const int tid  = threadIdx.x;
    const int wid  = tid >> 5, lane = tid & 31;
    const int gID  = lane >> 2, tig = lane & 3;
    const int warpM = wid & 3, warpN = wid >> 2;
    const int rowBase = blockIdx.y << 7;
    const int colBase = blockIdx.x << 7;
    const int lr = tid >> 3;
    const int lc = (tid & 7) << 2;

    const float* Ab  = A  + (size_t)(rowBase + lr) * K + lc;
    const float* Wb  = WT + (size_t)(colBase + lr) * K + lc;
    const uint32_t dstA = sm0 + (uint32_t)(lr * 36 + lc) * 4;
    const uint32_t dstB = dstA + GSTAGE * 4;

    float d[2][8][4];
#pragma unroll
    for (int mi = 0; mi < 2; mi++)
#pragma unroll
        for (int ni = 0; ni < 8; ni++)
#pragma unroll
            for (int e = 0; e < 4; e++) d[mi][ni][e] = 0.f;

    const int nch = K >> 5;

#define ISSUE(c_, s_) do {                                                   \
        const int k0_ = (c_) << 5;                                          \
        const uint32_t so_ = (uint32_t)(s_) * (2 * GSTAGE * 4);             \
        _Pragma("unroll")                                                    \
        for (int i_ = 0; i_ < 4; i_++) {                                     \
            CP_ASYNC16(dstA + so_ + i_ * (32 * 36 * 4),                      \
                       Ab + (size_t)(i_ << 5) * K + k0_);                    \
            CP_ASYNC16(dstB + so_ + i_ * (32 * 36 * 4),                      \
                       Wb + (size_t)(i_ << 5) * K + k0_);                    \
        }                                                                    \
        CP_COMMIT();                                                         \
    } while (0)

    ISSUE(0, 0);
    ISSUE(1, 1);

    const int rA = warpM * 32 + gID;
    const int cB = warpN * 64 + gID;

    for (int c = 0; c < nch; c++) {
        const int s = c & 1;
        if (c == nch - 1) { CP_WAITG(0); } else { CP_WAITG(1); }
        __syncthreads();
        const float* As = sm + s * (2 * GSTAGE);
        const float* Bs = As + GSTAGE;
#pragma unroll
        for (int ks = 0; ks < 4; ks++) {
            const int kk = ks << 3;
            uint32_t af[2][4], bf[8][2];
#pragma unroll
            for (int mi = 0; mi < 2; mi++) {
                af[mi][0] = f2tf32(As[(rA + mi * 16) * 36 + kk + tig]);
                af[mi][1] = f2tf32(As[(rA + mi * 16 + 8) * 36 + kk + tig]);
                af[mi][2] = f2tf32(As[(rA + mi * 16) * 36 + kk + tig + 4]);
                af[mi][3] = f2tf32(As[(rA + mi * 16 + 8) * 36 + kk + tig + 4]);
            }
#pragma unroll
            for (int ni = 0; ni < 8; ni++) {
                bf[ni][0] = __float_as_uint(Bs[(cB + ni * 8) * 36 + kk + tig]);
                bf[ni][1] = __float_as_uint(Bs[(cB + ni * 8) * 36 + kk + tig + 4]);
            }
#pragma unroll
            for (int mi = 0; mi < 2; mi++)
#pragma unroll
                for (int ni = 0; ni < 8; ni++)
                    MMA_TF32(d[mi][ni], af[mi], bf[ni]);
        }
        __syncthreads();
        if (c + 2 < nch) ISSUE(c + 2, s);
    }
#undef ISSUE

    const int row0 = rowBase + warpM * 32 + gID;
    const int colW = colBase + warpN * 64 + (tig << 1);
#pragma unroll
    for (int ni = 0; ni < 8; ni++) {
        const int col = colW + ni * 8;
        float bx = 0.f, by = 0.f;
        if (bias) { bx = bias[col]; by = bias[col + 1]; }
#pragma unroll
        for (int mi = 0; mi < 2; mi++) {
#pragma unroll
            for (int half = 0; half < 2; half++) {
                int r = row0 + mi * 16 + half * 8;
                float vx = d[mi][ni][half * 2 + 0] + bx;
                float vy = d[mi][ni][half * 2 + 1] + by;
                if (GELU) { vx = gelu_tanh(vx); vy = gelu_tanh(vy); }
                size_t off = (size_t)r * N + col;
                if (RES) {
                    float2 rr = *(const float2*)(R + off);
                    vx += rr.x; vy += rr.y;
                }
                float2 o = { vx, vy };
                *(float2*)(C + off) = o;
            }
        }
    }
}

// ---------------- ONE transpose+round kernel for all weights -----------------
// out layout: qkvT 0 (+l*49152) | projT 98304 (+l*16384) | mlp1T 131072 (+l*65536)
//             mlp2T 262144 (+l*65536) | dsT 393216.  524288 total elements.
__global__ void transpose_all(const float* __restrict__ qkv_w,
                              const float* __restrict__ proj_w,
                              const float* __restrict__ mlp_w1,
                              const float* __restrict__ mlp_w2,
                              const float* __restrict__ ds_w,
                              float* __restrict__ out)
{
    int i = blockIdx.x * 256 + threadIdx.x;
    const float* in; int K, N, base;
    if (i < 98304)       { base = 0;      in = qkv_w;  K = 128; N = 384; }
    else if (i < 131072) { base = 98304;  in = proj_w; K = 128; N = 128; }
    else if (i < 262144) { base = 131072; in = mlp_w1; K = 128; N = 512; }
    else if (i < 393216) { base = 262144; in = mlp_w2; K = 512; N = 128; }
    else                 { base = 393216; in = ds_w;   K = 512; N = 256; }
    int r = i - base;
    int per = K * N;
    int l = r / per; r -= l * per;
    int n = r / K, k = r - n * K;
    out[i] = __uint_as_float(f2tf32(in[(size_t)l * per + k * N + n]));
}

// ------------------------------ Window attention (all 4 heads per block) ----
// smem: qs/ks/vs [4][49][33] + sc [49][56]
#define AQ (4 * 49 * 33)
#define ATTN_SMEM ((3 * AQ + 49 * 56) * 4)

__global__ void __launch_bounds__(256, 2)
attn_kernel(const float* __restrict__ qkv, float* __restrict__ o,
            int shift, int use_mask)
{
    extern __shared__ float asmem[];
    float* qs = asmem;
    float* ks = asmem + AQ;
    float* vs = asmem + 2 * AQ;
    float* sc = asmem + 3 * AQ;     // [49][56]
    __shared__ int tok[49];
    __shared__ int regn[49];

    const int tid  = threadIdx.x;
    const int wid  = tid >> 5, lane = tid & 31;
    const int bg   = blockIdx.x;
    const int b    = bg >> 6;
    const int g    = bg & 63;
    const int gy   = g >> 3, gx = g & 7;

    if (tid < 49) {
        int wy = tid / 7, wx = tid - (tid / 7) * 7;
        int ph = gy * 7 + wy, pw = gx * 7 + wx;
        int hh = ph + shift; if (hh >= 56) hh -= 56;
        int ww = pw + shift; if (ww >= 56) ww -= 56;
        tok[tid] = b * 3136 + hh * 56 + ww;
        int rh = (ph < 49) ? 0 : ((ph < 53) ? 1 : 2);
        int rw = (pw < 49) ? 0 : ((pw < 53) ? 1 : 2);
        regn[tid] = rh * 3 + rw;
    }
    __syncthreads();

    // coalesced load: 49 rows x 96 float4 segments, demux into per-head tiles
    for (int idx = tid; idx < 49 * 96; idx += 256) {
        int row = idx / 96, seg = idx - row * 96;
        float4 v4 = *(const float4*)(qkv + (size_t)tok[row] * 384 + seg * 4);
        int fld = seg << 2;            // 0..380
        int which = fld >> 7;          // 0=q 1=k 2=v
        int rem = fld & 127;
        int head = rem >> 5, c = rem & 31;
        float* dst = (which == 0 ? qs : which == 1 ? ks : vs)
                     + (head * 49 + row) * 33 + c;
        dst[0] = v4.x; dst[1] = v4.y; dst[2] = v4.z; dst[3] = v4.w;
    }

    const float scale = 0.17677669529663689f;
#pragma unroll 1
    for (int h = 0; h < 4; h++) {
        const float* qh = qs + h * 49 * 33;
        const float* kh = ks + h * 49 * 33;
        const float* vh = vs + h * 49 * 33;
        __syncthreads();   // load done (h=0) / prev head's AV done (h>0)

        for (int e = tid; e < 2401; e += 256) {
            int i = e / 49, j = e - i * 49;
            float s = 0.f;
#pragma unroll
            for (int c = 0; c < 32; c++) s += qh[i * 33 + c] * kh[j * 33 + c];
            s *= scale;
            if (use_mask && (regn[i] != regn[j])) s -= 100.f;
            sc[i * 56 + j] = s;
        }
        __syncthreads();

        // softmax: 8 warps over rows
        for (int i = wid; i < 49; i += 8) {
            float v0 = (lane < 49) ? sc[i * 56 + lane] : -1e30f;
            float v1 = (lane + 32 < 49) ? sc[i * 56 + lane + 32] : -1e30f;
            float m = fmaxf(v0, v1);
#pragma unroll
            for (int o2 = 16; o2; o2 >>= 1) m = fmaxf(m, __shfl_xor_sync(0xffffffffu, m, o2));
            float e0 = (lane < 49) ? __expf(v0 - m) : 0.f;
            float e1 = (lane + 32 < 49) ? __expf(v1 - m) : 0.f;
            float s = e0 + e1;
#pragma unroll
            for (int o2 = 16; o2; o2 >>= 1) s += __shfl_xor_sync(0xffffffffu, s, o2);
            float inv = 1.0f / s;
            if (lane < 49) sc[i * 56 + lane] = e0 * inv;
            if (lane + 32 < 49) sc[i * 56 + lane + 32] = e1 * inv;
        }
        __syncthreads();

        for (int e = tid; e < 49 * 32; e += 256) {
            int i = e >> 5, c = e & 31;
            float s = 0.f;
#pragma unroll 7
            for (int j = 0; j < 49; j++) s += sc[i * 56 + j] * vh[j * 33 + c];
            o[(size_t)tok[i] * 128 + h * 32 + c] = s;
        }
    }
}

// ------------------------------ 2x2 patch merge + LN(512) -------------------
__global__ void __launch_bounds__(256)
merge_ln_kernel(const float* __restrict__ x, float* __restrict__ y,
                const float* __restrict__ g, const float* __restrict__ b)
{
    int warp = (blockIdx.x * blockDim.x + threadIdx.x) >> 5;
    int lane = threadIdx.x & 31;
    int bI = warp / 784;
    int r  = warp - bI * 784;
    int i  = r / 28;
    int j  = r - i * 28;
    int grp = lane >> 3;
    int hh  = grp >> 1, ww = grp & 1;
    int d0  = (lane & 7) << 4;
    const float* src =
        x + (((size_t)(bI * 56 + 2 * i + hh)) * 56 + (2 * j + ww)) * 128 + d0;

    float v[16];
#pragma unroll
    for (int t = 0; t < 4; t++) {
        float4 f = ((const float4*)src)[t];
        v[t * 4 + 0] = f.x; v[t * 4 + 1] = f.y; v[t * 4 + 2] = f.z; v[t * 4 + 3] = f.w;
    }
    float s = 0.f;
#pragma unroll
    for (int t = 0; t < 16; t++) s += v[t];
#pragma unroll
    for (int o = 16; o; o >>= 1) s += __shfl_xor_sync(0xffffffffu, s, o);
    float mean = s * (1.0f / 512.0f);
    float q = 0.f;
#pragma unroll
    for (int t = 0; t < 16; t++) { float dd = v[t] - mean; q += dd * dd; }
#pragma unroll
    for (int o = 16; o; o >>= 1) q += __shfl_xor_sync(0xffffffffu, q, o);
    float rstd = rsqrtf(q * (1.0f / 512.0f) + 1e-5f);

    int c0 = lane << 4;
    float* dst = y + (size_t)warp * 512 + c0;
#pragma unroll
    for (int t = 0; t < 4; t++) {
        float4 gg = ((const float4*)(g + c0))[t];
        float4 bb = ((const float4*)(b + c0))[t];
        float4 out;
        out.x = (v[t * 4 + 0] - mean) * rstd * gg.x + bb.x;
        out.y = (v[t * 4 + 1] - mean) * rstd * gg.y + bb.y;
        out.z = (v[t * 4 + 2] - mean) * rstd * gg.z + bb.z;
        out.w = (v[t * 4 + 3] - mean) * rstd * gg.w + bb.w;
        ((float4*)dst)[t] = out;
    }
}

// ---------------------------------------------------------------------------
extern "C" void kernel_launch(void* const* d_in, const int* in_sizes, int n_in,
                              void* d_out, int out_size)
{
    const float* x       = (const float*)d_in[0];
    const float* ln1_g   = (const float*)d_in[1];
    const float* ln1_b   = (const float*)d_in[2];
    const float* qkv_w   = (const float*)d_in[3];
    const float* qkv_b   = (const float*)d_in[4];
    const float* proj_w  = (const float*)d_in[5];
    const float* proj_b  = (const float*)d_in[6];
    const float* ln2_g   = (const float*)d_in[7];
    const float* ln2_b   = (const float*)d_in[8];
    const float* mlp_w1  = (const float*)d_in[9];
    const float* mlp_b1  = (const float*)d_in[10];
    const float* mlp_w2  = (const float*)d_in[11];
    const float* mlp_b2  = (const float*)d_in[12];
    const float* dsn_g   = (const float*)d_in[13];
    const float* dsn_b   = (const float*)d_in[14];
    const float* ds_w    = (const float*)d_in[15];
    float* out           = (float*)d_out;

    float *gx, *gq, *go, *ghid, *gds, *gwt;
    cudaGetSymbolAddress((void**)&gx,   g_x);
    cudaGetSymbolAddress((void**)&gq,   g_qkv);
    cudaGetSymbolAddress((void**)&go,   g_o);
    cudaGetSymbolAddress((void**)&ghid, g_hid);
    cudaGetSymbolAddress((void**)&gds,  g_ds);
    cudaGetSymbolAddress((void**)&gwt,  g_wt);

    cudaFuncSetAttribute(ln_gemm128<true, false, false>, cudaFuncAttributeMaxDynamicSharedMemorySize, LG_SMEM);
    cudaFuncSetAttribute(ln_gemm128<false, false, true>, cudaFuncAttributeMaxDynamicSharedMemorySize, LG_SMEM);
    cudaFuncSetAttribute(ln_gemm128<true, true, false>,  cudaFuncAttributeMaxDynamicSharedMemorySize, LG_SMEM);
    cudaFuncSetAttribute(gemm_mma<false, true>,  cudaFuncAttributeMaxDynamicSharedMemorySize, GEMM_SMEM);
    cudaFuncSetAttribute(gemm_mma<false, false>, cudaFuncAttributeMaxDynamicSharedMemorySize, GEMM_SMEM);
    cudaFuncSetAttribute(attn_kernel, cudaFuncAttributeMaxDynamicSharedMemorySize, ATTN_SMEM);

    transpose_all<<<524288 / 256, 256>>>(qkv_w, proj_w, mlp_w1, mlp_w2, ds_w, gwt);

    for (int layer = 0; layer < 2; layer++) {
        const float* res_in = (layer == 0) ? x : gx;
        int shift   = (layer == 1) ? 3 : 0;
        int useMask = (layer == 1) ? 1 : 0;

        // LN1 + QKV
        ln_gemm128<true, false, false><<<dim3(3, TOK / 128), 256, LG_SMEM>>>(
            res_in, gwt + 0 + layer * 49152, ln1_g + layer * 128, ln1_b + layer * 128,
            qkv_b + layer * 384, nullptr, gq, 384);
        attn_kernel<<<4096, 256, ATTN_SMEM>>>(gq, go, shift, useMask);
        // proj + residual
        ln_gemm128<false, false, true><<<dim3(1, TOK / 128), 256, LG_SMEM>>>(
            go, gwt + 98304 + layer * 16384, nullptr, nullptr,
            proj_b + layer * 128, res_in, gx, 128);
        // LN2 + MLP1 + GELU
        ln_gemm128<true, true, false><<<dim3(4, TOK / 128), 256, LG_SMEM>>>(
            gx, gwt + 131072 + layer * 65536, ln2_g + layer * 128, ln2_b + layer * 128,
            mlp_b1 + layer * 512, nullptr, ghid, 512);
        // MLP2 + residual (K=512)
        gemm_mma<false, true><<<dim3(1, TOK / 128), 256, GEMM_SMEM>>>(
            ghid, gwt + 262144 + layer * 65536, mlp_b2 + layer * 128, gx, gx, 128, 512);
    }

    merge_ln_kernel<<<DSTOK / 8, 256>>>(gx, gds, dsn_g, dsn_b);
    gemm_mma<false, false><<<dim3(2, DSTOK / 128), 256, GEMM_SMEM>>>(
        gds, gwt + 393216, nullptr, nullptr, out, 256, 512);
}

// round 8
// speedup vs baseline: 1.0535x; 1.0535x over previous
#include <cuda_runtime.h>
#include <cstdint>
#include <math.h>

// ---------------------------------------------------------------------------
// Swin stage on GB300 (compute_103: mma.sync tf32 path).
// R8: R4 attention revert + pre-rounded activations (lean MMA mainloops).
// ---------------------------------------------------------------------------

#define TOK 200704          // 64*56*56
#define DSTOK 50176         // 64*28*28

__device__ float g_x  [(size_t)TOK * 128];
__device__ float g_qkv[(size_t)TOK * 384];
__device__ float g_o  [(size_t)TOK * 128];
__device__ float g_hid[(size_t)TOK * 512];
__device__ float g_ds [(size_t)DSTOK * 512];
__device__ float g_wt [524288];   // transposed weights [N,K] K-major, tf32-rounded

__device__ __forceinline__ uint32_t f2tf32(float f) {
    uint32_t u; asm("cvt.rna.tf32.f32 %0, %1;" : "=r"(u) : "f"(f)); return u;
}
__device__ __forceinline__ float rnd_tf32(float f) {
    return __uint_as_float(f2tf32(f));
}
__device__ __forceinline__ uint32_t smem_u32(const void* p) {
    uint32_t a;
    asm("{ .reg .u64 t; cvta.to.shared.u64 t, %1; cvt.u32.u64 %0, t; }" : "=r"(a) : "l"(p));
    return a;
}

#define CP_ASYNC16(dst, src) \
    asm volatile("cp.async.cg.shared.global [%0], [%1], 16;" :: "r"(dst), "l"(src))
#define CP_COMMIT() asm volatile("cp.async.commit_group;" ::: "memory")
#define CP_WAITG(n) asm volatile("cp.async.wait_group %0;" :: "n"(n) : "memory")

#define MMA_TF32(d, a, b) \
    asm volatile("mma.sync.aligned.m16n8k8.row.col.f32.tf32.tf32.f32 " \
        "{%0,%1,%2,%3}, {%4,%5,%6,%7}, {%8,%9}, {%0,%1,%2,%3};" \
        : "+f"((d)[0]), "+f"((d)[1]), "+f"((d)[2]), "+f"((d)[3]) \
        : "r"((a)[0]), "r"((a)[1]), "r"((a)[2]), "r"((a)[3]), \
          "r"((b)[0]), "r"((b)[1]))

__device__ __forceinline__ float gelu_tanh(float v) {
    float u = 0.7978845608028654f * (v + 0.044715f * v * v * v);
    return 0.5f * v * (1.0f + tanhf(u));
}

// ===================== fused (LN +) GEMM, K=128 ==============================
// LN=true : A raw fp32; stats computed, tile normalized+tf32-rounded in smem.
// LN=false: A assumed PRE-ROUNDED tf32 (producer rounds at store).
#define BSTAGE 4608
#define LG_SMEM ((16896 + 2 * BSTAGE) * 4)   // 104448 bytes

template <bool LN, bool GELU, bool RES>
__global__ void __launch_bounds__(256, 2)
ln_gemm128(const float* __restrict__ A, const float* __restrict__ WT,
           const float* __restrict__ lng, const float* __restrict__ lnb,
           const float* __restrict__ bias, const float* __restrict__ R,
           float* __restrict__ C, int N)
{
    extern __shared__ float sm[];
    float* Af  = sm;                    // [128][132]
    float* Bsm = sm + 16896;            // 2 x [128][36]
    const uint32_t sm0 = smem_u32(sm);
    const uint32_t AfB = sm0;
    const uint32_t BsB = sm0 + 16896 * 4;

    const int tid  = threadIdx.x;
    const int wid  = tid >> 5, lane = tid & 31;
    const int gID  = lane >> 2, tig = lane & 3;
    const int warpM = wid & 3, warpN = wid >> 2;
    const int rowBase = blockIdx.y << 7;
    const int colBase = blockIdx.x << 7;

    // ---- issue full A tile (group 0)
#pragma unroll
    for (int i = 0; i < 16; i++) {
        int seg = tid + (i << 8);
        int r = seg >> 5, c4 = (seg & 31) << 2;
        CP_ASYNC16(AfB + (uint32_t)(r * 132 + c4) * 4,
                   A + (size_t)(rowBase + r) * 128 + c4);
    }
    CP_COMMIT();

    const int lrB = tid >> 3, lcB = (tid & 7) << 2;
#define ISSUE_B(c_, s_) do {                                                  \
        const int k0_ = (c_) << 5;                                           \
        const uint32_t so_ = BsB + (uint32_t)(s_) * (BSTAGE * 4);             \
        _Pragma("unroll")                                                     \
        for (int i_ = 0; i_ < 4; i_++) {                                      \
            int rB_ = lrB + (i_ << 5);                                        \
            CP_ASYNC16(so_ + (uint32_t)(rB_ * 36 + lcB) * 4,                  \
                       WT + (size_t)(colBase + rB_) * 128 + k0_ + lcB);       \
        }                                                                     \
        CP_COMMIT();                                                          \
    } while (0)

    ISSUE_B(0, 0);
    ISSUE_B(1, 1);

    // ---- wait A; LN: stats + in-place normalize + tf32-round (float4 passes)
    CP_WAITG(2);
    __syncthreads();
    if (LN) {
        const int row = tid >> 1, half = tid & 1;
        float4* rp = (float4*)(Af + row * 132 + half * 64);
        float4 vv[16];
        float s = 0.f, q = 0.f;
#pragma unroll
        for (int i = 0; i < 16; i++) {
            float4 v = rp[i];
            vv[i] = v;
            s += v.x + v.y + v.z + v.w;
            q += v.x * v.x + v.y * v.y + v.z * v.z + v.w * v.w;
        }
        s += __shfl_xor_sync(0xffffffffu, s, 1);
        q += __shfl_xor_sync(0xffffffffu, q, 1);
        float mean = s * (1.0f / 128.0f);
        float var  = q * (1.0f / 128.0f) - mean * mean;
        float rstd = rsqrtf(var + 1e-5f);
        float mrs  = mean * rstd;
        const float4* g4 = (const float4*)(lng + half * 64);
        const float4* b4 = (const float4*)(lnb + half * 64);
#pragma unroll
        for (int i = 0; i < 16; i++) {
            float4 g = __ldg(g4 + i), b = __ldg(b4 + i);
            float4 v = vv[i];
            v.x = rnd_tf32(fmaf(fmaf(v.x, rstd, -mrs), g.x, b.x));
            v.y = rnd_tf32(fmaf(fmaf(v.y, rstd, -mrs), g.y, b.y));
            v.z = rnd_tf32(fmaf(fmaf(v.z, rstd, -mrs), g.z, b.z));
            v.w = rnd_tf32(fmaf(fmaf(v.w, rstd, -mrs), g.w, b.w));
            rp[i] = v;
        }
        __syncthreads();
    }

    float d[2][8][4];
#pragma unroll
    for (int mi = 0; mi < 2; mi++)
#pragma unroll
        for (int ni = 0; ni < 8; ni++)
#pragma unroll
            for (int e = 0; e < 4; e++) d[mi][ni][e] = 0.f;

    const int rA = warpM * 32 + gID;
    const int cB = warpN * 64 + gID;

    // ---- 4 K-chunks of 32; mainloop = pure LDS + MMA
#pragma unroll
    for (int c = 0; c < 4; c++) {
        const int s = c & 1;
        if (c == 3) { CP_WAITG(0); } else { CP_WAITG(1); }
        __syncthreads();
        const float* Bsl = Bsm + s * BSTAGE;
#pragma unroll
        for (int ksl = 0; ksl < 4; ksl++) {
            const int kk = ksl << 3;
            const int klo = (c << 5) + kk + tig;
            const int khi = klo + 4;
            uint32_t af[2][4], bf[8][2];
#pragma unroll
            for (int mi = 0; mi < 2; mi++) {
                af[mi][0] = __float_as_uint(Af[(rA + mi * 16) * 132 + klo]);
                af[mi][1] = __float_as_uint(Af[(rA + mi * 16 + 8) * 132 + klo]);
                af[mi][2] = __float_as_uint(Af[(rA + mi * 16) * 132 + khi]);
                af[mi][3] = __float_as_uint(Af[(rA + mi * 16 + 8) * 132 + khi]);
            }
#pragma unroll
            for (int ni = 0; ni < 8; ni++) {
                bf[ni][0] = __float_as_uint(Bsl[(cB + ni * 8) * 36 + kk + tig]);
                bf[ni][1] = __float_as_uint(Bsl[(cB + ni * 8) * 36 + kk + tig + 4]);
            }
#pragma unroll
            for (int mi = 0; mi < 2; mi++)
#pragma unroll
                for (int ni = 0; ni < 8; ni++)
                    MMA_TF32(d[mi][ni], af[mi], bf[ni]);
        }
        __syncthreads();
        if (c + 2 < 4) ISSUE_B(c + 2, s);
    }
#undef ISSUE_B

    // ---- epilogue (GELU output is tf32-rounded for the next GEMM)
    const int row0 = rowBase + warpM * 32 + gID;
    const int colW = colBase + warpN * 64 + (tig << 1);
#pragma unroll
    for (int ni = 0; ni < 8; ni++) {
        const int col = colW + ni * 8;
        float bx = 0.f, by = 0.f;
        if (bias) { bx = bias[col]; by = bias[col + 1]; }
#pragma unroll
        for (int mi = 0; mi < 2; mi++) {
#pragma unroll
            for (int half = 0; half < 2; half++) {
                int r = row0 + mi * 16 + half * 8;
                float vx = d[mi][ni][half * 2 + 0] + bx;
                float vy = d[mi][ni][half * 2 + 1] + by;
                if (GELU) { vx = rnd_tf32(gelu_tanh(vx)); vy = rnd_tf32(gelu_tanh(vy)); }
                size_t off = (size_t)r * N + col;
                if (RES) {
                    float2 rr = *(const float2*)(R + off);
                    vx += rr.x; vy += rr.y;
                }
                float2 o = { vx, vy };
                *(float2*)(C + off) = o;
            }
        }
    }
}

// ===================== generic K GEMM (K=512 paths) ==========================
// CVTA=false: A pre-rounded tf32 by its producer.
#define GSTAGE 4608
#define GEMM_SMEM (2 * 2 * GSTAGE * 4)   // 73728 bytes

template <bool CVTA, bool GELU, bool RES>
__global__ void __launch_bounds__(256, 2)
gemm_mma(const float* __restrict__ A, const float* __restrict__ WT,
         const float* __restrict__ bias, const float* __restrict__ R,
         float* __restrict__ C, int N, int K)
{
    extern __shared__ float sm[];
    const uint32_t sm0 = smem_u32(sm);
    const int tid  = threadIdx.x;
    const int wid  = tid >> 5, lane = tid & 31;
    const int gID  = lane >> 2, tig = lane & 3;
    const int warpM = wid & 3, warpN = wid >> 2;
    const int rowBase = blockIdx.y << 7;
    const int colBase = blockIdx.x << 7;
    const int lr = tid >> 3;
    const int lc = (tid & 7) << 2;

    const float* Ab  = A  + (size_t)(rowBase + lr) * K + lc;
    const float* Wb  = WT + (size_t)(colBase + lr) * K + lc;
    const uint32_t dstA = sm0 + (uint32_t)(lr * 36 + lc) * 4;
    const uint32_t dstB = dstA + GSTAGE * 4;

    float d[2][8][4];
#pragma unroll
    for (int mi = 0; mi < 2; mi++)
#pragma unroll
        for (int ni = 0; ni < 8; ni++)
#pragma unroll
            for (int e = 0; e < 4; e++) d[mi][ni][e] = 0.f;

    const int nch = K >> 5;

#define ISSUE(c_, s_) do {                                                   \
        const int k0_ = (c_) << 5;                                          \
        const uint32_t so_ = (uint32_t)(s_) * (2 * GSTAGE * 4);             \
        _Pragma("unroll")                                                    \
        for (int i_ = 0; i_ < 4; i_++) {                                     \
            CP_ASYNC16(dstA + so_ + i_ * (32 * 36 * 4),                      \
                       Ab + (size_t)(i_ << 5) * K + k0_);                    \
            CP_ASYNC16(dstB + so_ + i_ * (32 * 36 * 4),                      \
                       Wb + (size_t)(i_ << 5) * K + k0_);                    \
        }                                                                    \
        CP_COMMIT();                                                         \
    } while (0)

    ISSUE(0, 0);
    ISSUE(1, 1);

    const int rA = warpM * 32 + gID;
    const int cB = warpN * 64 + gID;

    for (int c = 0; c < nch; c++) {
        const int s = c & 1;
        if (c == nch - 1) { CP_WAITG(0); } else { CP_WAITG(1); }
        __syncthreads();
        const float* As = sm + s * (2 * GSTAGE);
        const float* Bs = As + GSTAGE;
#pragma unroll
        for (int ks = 0; ks < 4; ks++) {
            const int kk = ks << 3;
            uint32_t af[2][4], bf[8][2];
#pragma unroll
            for (int mi = 0; mi < 2; mi++) {
                if (CVTA) {
                    af[mi][0] = f2tf32(As[(rA + mi * 16) * 36 + kk + tig]);
                    af[mi][1] = f2tf32(As[(rA + mi * 16 + 8) * 36 + kk + tig]);
                    af[mi][2] = f2tf32(As[(rA + mi * 16) * 36 + kk + tig + 4]);
                    af[mi][3] = f2tf32(As[(rA + mi * 16 + 8) * 36 + kk + tig + 4]);
                } else {
                    af[mi][0] = __float_as_uint(As[(rA + mi * 16) * 36 + kk + tig]);
                    af[mi][1] = __float_as_uint(As[(rA + mi * 16 + 8) * 36 + kk + tig]);
                    af[mi][2] = __float_as_uint(As[(rA + mi * 16) * 36 + kk + tig + 4]);
                    af[mi][3] = __float_as_uint(As[(rA + mi * 16 + 8) * 36 + kk + tig + 4]);
                }
            }
#pragma unroll
            for (int ni = 0; ni < 8; ni++) {
                bf[ni][0] = __float_as_uint(Bs[(cB + ni * 8) * 36 + kk + tig]);
                bf[ni][1] = __float_as_uint(Bs[(cB + ni * 8) * 36 + kk + tig + 4]);
            }
#pragma unroll
            for (int mi = 0; mi < 2; mi++)
#pragma unroll
                for (int ni = 0; ni < 8; ni++)
                    MMA_TF32(d[mi][ni], af[mi], bf[ni]);
        }
        __syncthreads();
        if (c + 2 < nch) ISSUE(c + 2, s);
    }
#undef ISSUE

    const int row0 = rowBase + warpM * 32 + gID;
    const int colW = colBase + warpN * 64 + (tig << 1);
#pragma unroll
    for (int ni = 0; ni < 8; ni++) {
        const int col = colW + ni * 8;
        float bx = 0.f, by = 0.f;
        if (bias) { bx = bias[col]; by = bias[col + 1]; }
#pragma unroll
        for (int mi = 0; mi < 2; mi++) {
#pragma unroll
            for (int half = 0; half < 2; half++) {
                int r = row0 + mi * 16 + half * 8;
                float vx = d[mi][ni][half * 2 + 0] + bx;
                float vy = d[mi][ni][half * 2 + 1] + by;
                if (GELU) { vx = rnd_tf32(gelu_tanh(vx)); vy = rnd_tf32(gelu_tanh(vy)); }
                size_t off = (size_t)r * N + col;
                if (RES) {
                    float2 rr = *(const float2*)(R + off);
                    vx += rr.x; vy += rr.y;
                }
                float2 o = { vx, vy };
                *(float2*)(C + off) = o;
            }
        }
    }
}

// ---------------- ONE transpose+round kernel for all weights -----------------
__global__ void transpose_all(const float* __restrict__ qkv_w,
                              const float* __restrict__ proj_w,
                              const float* __restrict__ mlp_w1,
                              const float* __restrict__ mlp_w2,
                              const float* __restrict__ ds_w,
                              float* __restrict__ out)
{
    int i = blockIdx.x * 256 + threadIdx.x;
    const float* in; int K, N, base;
    if (i < 98304)       { base = 0;      in = qkv_w;  K = 128; N = 384; }
    else if (i < 131072) { base = 98304;  in = proj_w; K = 128; N = 128; }
    else if (i < 262144) { base = 131072; in = mlp_w1; K = 128; N = 512; }
    else if (i < 393216) { base = 262144; in = mlp_w2; K = 512; N = 128; }
    else                 { base = 393216; in = ds_w;   K = 512; N = 256; }
    int r = i - base;
    int per = K * N;
    int l = r / per; r -= l * per;
    int n = r / K, k = r - n * K;
    out[i] = __uint_as_float(f2tf32(in[(size_t)l * per + k * N + n]));
}

// ------------------------------ Window attention (R4 layout) ----------------
// One block per (b, window, head); output tf32-rounded for proj GEMM.
__global__ void __launch_bounds__(128)
attn_kernel(const float* __restrict__ qkv, float* __restrict__ o,
            int shift, int use_mask)
{
    __shared__ float qs[49][33], ks[49][33], vs[49][33];
    __shared__ float sc[49][49];
    __shared__ int   tok[49];
    __shared__ int   regn[49];

    const int tid  = threadIdx.x;
    const int wid  = tid >> 5, lane = tid & 31;
    const int head = blockIdx.y;
    const int bg   = blockIdx.x;
    const int b    = bg >> 6;
    const int g    = bg & 63;
    const int gy   = g >> 3, gx = g & 7;

    if (tid < 49) {
        int wy = tid / 7, wx = tid - (tid / 7) * 7;
        int ph = gy * 7 + wy, pw = gx * 7 + wx;
        int hh = ph + shift; if (hh >= 56) hh -= 56;
        int ww = pw + shift; if (ww >= 56) ww -= 56;
        tok[tid] = b * 3136 + hh * 56 + ww;
        int rh = (ph < 49) ? 0 : ((ph < 53) ? 1 : 2);
        int rw = (pw < 49) ? 0 : ((pw < 53) ? 1 : 2);
        regn[tid] = rh * 3 + rw;
    }
    __syncthreads();

    for (int i = tid; i < 49 * 8; i += 128) {
        int r = i >> 3, c4 = (i & 7) << 2;
        const float* base = qkv + (size_t)tok[r] * 384 + head * 32 + c4;
        float4 q4 = *(const float4*)(base);
        float4 k4 = *(const float4*)(base + 128);
        float4 v4 = *(const float4*)(base + 256);
        qs[r][c4] = q4.x; qs[r][c4 + 1] = q4.y; qs[r][c4 + 2] = q4.z; qs[r][c4 + 3] = q4.w;
        ks[r][c4] = k4.x; ks[r][c4 + 1] = k4.y; ks[r][c4 + 2] = k4.z; ks[r][c4 + 3] = k4.w;
        vs[r][c4] = v4.x; vs[r][c4 + 1] = v4.y; vs[r][c4 + 2] = v4.z; vs[r][c4 + 3] = v4.w;
    }
    __syncthreads();

    const float scale = 0.17677669529663689f;
    for (int e = tid; e < 2401; e += 128) {
        int i = e / 49, j = e - i * 49;
        float s = 0.f;
#pragma unroll
        for (int c = 0; c < 32; c++) s += qs[i][c] * ks[j][c];
        s *= scale;
        if (use_mask && (regn[i] != regn[j])) s -= 100.f;
        sc[i][j] = s;
    }
    __syncthreads();

    for (int i = wid; i < 49; i += 4) {
        float v0 = (lane < 49) ? sc[i][lane] : -1e30f;
        float v1 = (lane + 32 < 49) ? sc[i][lane + 32] : -1e30f;
        float m = fmaxf(v0, v1);
#pragma unroll
        for (int o2 = 16; o2; o2 >>= 1) m = fmaxf(m, __shfl_xor_sync(0xffffffffu, m, o2));
        float e0 = (lane < 49) ? __expf(v0 - m) : 0.f;
        float e1 = (lane + 32 < 49) ? __expf(v1 - m) : 0.f;
        float s = e0 + e1;
#pragma unroll
        for (int o2 = 16; o2; o2 >>= 1) s += __shfl_xor_sync(0xffffffffu, s, o2);
        float inv = 1.0f / s;
        if (lane < 49) sc[i][lane] = e0 * inv;
        if (lane + 32 < 49) sc[i][lane + 32] = e1 * inv;
    }
    __syncthreads();

    for (int e = tid; e < 49 * 32; e += 128) {
        int i = e >> 5, c = e & 31;
        float s = 0.f;
#pragma unroll 7
        for (int j = 0; j < 49; j++) s += sc[i][j] * vs[j][c];
        o[(size_t)tok[i] * 128 + head * 32 + c] = rnd_tf32(s);
    }
}

// ------------------------------ 2x2 patch merge + LN(512) -------------------
// Output tf32-rounded (feeds ds GEMM with CVTA=false).
__global__ void __launch_bounds__(256)
merge_ln_kernel(const float* __restrict__ x, float* __restrict__ y,
                const float* __restrict__ g, const float* __restrict__ b)
{
    int warp = (blockIdx.x * blockDim.x + threadIdx.x) >> 5;
    int lane = threadIdx.x & 31;
    int bI = warp / 784;
    int r  = warp - bI * 784;
    int i  = r / 28;
    int j  = r - i * 28;
    int grp = lane >> 3;
    int hh  = grp >> 1, ww = grp & 1;
    int d0  = (lane & 7) << 4;
    const float* src =
        x + (((size_t)(bI * 56 + 2 * i + hh)) * 56 + (2 * j + ww)) * 128 + d0;

    float v[16];
#pragma unroll
    for (int t = 0; t < 4; t++) {
        float4 f = ((const float4*)src)[t];
        v[t * 4 + 0] = f.x; v[t * 4 + 1] = f.y; v[t * 4 + 2] = f.z; v[t * 4 + 3] = f.w;
    }
    float s = 0.f;
#pragma unroll
    for (int t = 0; t < 16; t++) s += v[t];
#pragma unroll
    for (int o = 16; o; o >>= 1) s += __shfl_xor_sync(0xffffffffu, s, o);
    float mean = s * (1.0f / 512.0f);
    float q = 0.f;
#pragma unroll
    for (int t = 0; t < 16; t++) { float dd = v[t] - mean; q += dd * dd; }
#pragma unroll
    for (int o = 16; o; o >>= 1) q += __shfl_xor_sync(0xffffffffu, q, o);
    float rstd = rsqrtf(q * (1.0f / 512.0f) + 1e-5f);

    int c0 = lane << 4;
    float* dst = y + (size_t)warp * 512 + c0;
#pragma unroll
    for (int t = 0; t < 4; t++) {
        float4 gg = ((const float4*)(g + c0))[t];
        float4 bb = ((const float4*)(b + c0))[t];
        float4 out;
        out.x = rnd_tf32((v[t * 4 + 0] - mean) * rstd * gg.x + bb.x);
        out.y = rnd_tf32((v[t * 4 + 1] - mean) * rstd * gg.y + bb.y);
        out.z = rnd_tf32((v[t * 4 + 2] - mean) * rstd * gg.z + bb.z);
        out.w = rnd_tf32((v[t * 4 + 3] - mean) * rstd * gg.w + bb.w);
        ((float4*)dst)[t] = out;
    }
}

// ---------------------------------------------------------------------------
extern "C" void kernel_launch(void* const* d_in, const int* in_sizes, int n_in,
                              void* d_out, int out_size)
{
    const float* x       = (const float*)d_in[0];
    const float* ln1_g   = (const float*)d_in[1];
    const float* ln1_b   = (const float*)d_in[2];
    const float* qkv_w   = (const float*)d_in[3];
    const float* qkv_b   = (const float*)d_in[4];
    const float* proj_w  = (const float*)d_in[5];
    const float* proj_b  = (const float*)d_in[6];
    const float* ln2_g   = (const float*)d_in[7];
    const float* ln2_b   = (const float*)d_in[8];
    const float* mlp_w1  = (const float*)d_in[9];
    const float* mlp_b1  = (const float*)d_in[10];
    const float* mlp_w2  = (const float*)d_in[11];
    const float* mlp_b2  = (const float*)d_in[12];
    const float* dsn_g   = (const float*)d_in[13];
    const float* dsn_b   = (const float*)d_in[14];
    const float* ds_w    = (const float*)d_in[15];
    float* out           = (float*)d_out;

    float *gx, *gq, *go, *ghid, *gds, *gwt;
    cudaGetSymbolAddress((void**)&gx,   g_x);
    cudaGetSymbolAddress((void**)&gq,   g_qkv);
    cudaGetSymbolAddress((void**)&go,   g_o);
    cudaGetSymbolAddress((void**)&ghid, g_hid);
    cudaGetSymbolAddress((void**)&gds,  g_ds);
    cudaGetSymbolAddress((void**)&gwt,  g_wt);

    cudaFuncSetAttribute(ln_gemm128<true, false, false>, cudaFuncAttributeMaxDynamicSharedMemorySize, LG_SMEM);
    cudaFuncSetAttribute(ln_gemm128<false, false, true>, cudaFuncAttributeMaxDynamicSharedMemorySize, LG_SMEM);
    cudaFuncSetAttribute(ln_gemm128<true, true, false>,  cudaFuncAttributeMaxDynamicSharedMemorySize, LG_SMEM);
    cudaFuncSetAttribute(gemm_mma<false, false, true>,  cudaFuncAttributeMaxDynamicSharedMemorySize, GEMM_SMEM);
    cudaFuncSetAttribute(gemm_mma<false, false, false>, cudaFuncAttributeMaxDynamicSharedMemorySize, GEMM_SMEM);

    transpose_all<<<524288 / 256, 256>>>(qkv_w, proj_w, mlp_w1, mlp_w2, ds_w, gwt);

    const dim3 attnGrid(4096, 4);

    for (int layer = 0; layer < 2; layer++) {
        const float* res_in = (layer == 0) ? x : gx;
        int shift   = (layer == 1) ? 3 : 0;
        int useMask = (layer == 1) ? 1 : 0;

        // LN1 + QKV
        ln_gemm128<true, false, false><<<dim3(3, TOK / 128), 256, LG_SMEM>>>(
            res_in, gwt + 0 + layer * 49152, ln1_g + layer * 128, ln1_b + layer * 128,
            qkv_b + layer * 384, nullptr, gq, 384);
        attn_kernel<<<attnGrid, 128>>>(gq, go, shift, useMask);
        // proj + residual (A = o, pre-rounded)
        ln_gemm128<false, false, true><<<dim3(1, TOK / 128), 256, LG_SMEM>>>(
            go, gwt + 98304 + layer * 16384, nullptr, nullptr,
            proj_b + layer * 128, res_in, gx, 128);
        // LN2 + MLP1 + GELU (hid stored pre-rounded)
        ln_gemm128<true, true, false><<<dim3(4, TOK / 128), 256, LG_SMEM>>>(
            gx, gwt + 131072 + layer * 65536, ln2_g + layer * 128, ln2_b + layer * 128,
            mlp_b1 + layer * 512, nullptr, ghid, 512);
        // MLP2 + residual (K=512, A pre-rounded)
        gemm_mma<false, false, true><<<dim3(1, TOK / 128), 256, GEMM_SMEM>>>(
            ghid, gwt + 262144 + layer * 65536, mlp_b2 + layer * 128, gx, gx, 128, 512);
    }

    merge_ln_kernel<<<DSTOK / 8, 256>>>(gx, gds, dsn_g, dsn_b);
    gemm_mma<false, false, false><<<dim3(2, DSTOK / 128), 256, GEMM_SMEM>>>(
        gds, gwt + 393216, nullptr, nullptr, out, 256, 512);
}

// round 9
// speedup vs baseline: 1.0995x; 1.0437x over previous
#include <cuda_runtime.h>
#include <cstdint>
#include <math.h>

// ---------------------------------------------------------------------------
// Swin stage on GB300 (compute_103: mma.sync tf32 path).
// R9: R4 champion skeleton + pre-rounded producers (lean mainloops), 1 transpose.
// ---------------------------------------------------------------------------

#define TOK 200704          // 64*56*56
#define DSTOK 50176         // 64*28*28

__device__ float g_x  [(size_t)TOK * 128];
__device__ float g_h  [(size_t)TOK * 128];
__device__ float g_qkv[(size_t)TOK * 384];
__device__ float g_o  [(size_t)TOK * 128];
__device__ float g_hid[(size_t)TOK * 512];
__device__ float g_ds [(size_t)DSTOK * 512];
__device__ float g_wt [524288];   // transposed weights [N,K] K-major, tf32-rounded

__device__ __forceinline__ uint32_t f2tf32(float f) {
    uint32_t u; asm("cvt.rna.tf32.f32 %0, %1;" : "=r"(u) : "f"(f)); return u;
}
__device__ __forceinline__ float rnd_tf32(float f) {
    return __uint_as_float(f2tf32(f));
}
__device__ __forceinline__ uint32_t smem_u32(const void* p) {
    uint32_t a;
    asm("{ .reg .u64 t; cvta.to.shared.u64 t, %1; cvt.u32.u64 %0, t; }" : "=r"(a) : "l"(p));
    return a;
}

#define CP_ASYNC16(dst, src) \
    asm volatile("cp.async.cg.shared.global [%0], [%1], 16;" :: "r"(dst), "l"(src))
#define CP_COMMIT() asm volatile("cp.async.commit_group;" ::: "memory")
#define CP_WAITG(n) asm volatile("cp.async.wait_group %0;" :: "n"(n) : "memory")

#define MMA_TF32(d, a, b) \
    asm volatile("mma.sync.aligned.m16n8k8.row.col.f32.tf32.tf32.f32 " \
        "{%0,%1,%2,%3}, {%4,%5,%6,%7}, {%8,%9}, {%0,%1,%2,%3};" \
        : "+f"((d)[0]), "+f"((d)[1]), "+f"((d)[2]), "+f"((d)[3]) \
        : "r"((a)[0]), "r"((a)[1]), "r"((a)[2]), "r"((a)[3]), \
          "r"((b)[0]), "r"((b)[1]))

__device__ __forceinline__ float gelu_tanh(float v) {
    float u = 0.7978845608028654f * (v + 0.044715f * v * v * v);
    return 0.5f * v * (1.0f + tanhf(u));
}

// ===================== tf32 mma GEMM, cp.async double-buffered ===============
// A is PRE-ROUNDED tf32 by its producer; mainloop = pure LDS + MMA.
#define GSTAGE 4608               // floats per tile (128*36)
#define GEMM_SMEM (2 * 2 * GSTAGE * 4)   // 73728 bytes

template <bool GELU, bool RES>
__global__ void __launch_bounds__(256, 2)
gemm_mma(const float* __restrict__ A, const float* __restrict__ WT,
         const float* __restrict__ bias, const float* __restrict__ R,
         float* __restrict__ C, int N, int K)
{
    extern __shared__ float sm[];
    const uint32_t sm0 = smem_u32(sm);
    const int tid  = threadIdx.x;
    const int wid  = tid >> 5, lane = tid & 31;
    const int gID  = lane >> 2, tig = lane & 3;
    const int warpM = wid & 3, warpN = wid >> 2;
    const int rowBase = blockIdx.y << 7;
    const int colBase = blockIdx.x << 7;
    const int lr = tid >> 3;
    const int lc = (tid & 7) << 2;

    const float* Ab  = A  + (size_t)(rowBase + lr) * K + lc;
    const float* Wb  = WT + (size_t)(colBase + lr) * K + lc;
    const uint32_t dstA = sm0 + (uint32_t)(lr * 36 + lc) * 4;
    const uint32_t dstB = dstA + GSTAGE * 4;

    float d[2][8][4];
#pragma unroll
    for (int mi = 0; mi < 2; mi++)
#pragma unroll
        for (int ni = 0; ni < 8; ni++)
#pragma unroll
            for (int e = 0; e < 4; e++) d[mi][ni][e] = 0.f;

    const int nch = K >> 5;

#define ISSUE(c_, s_) do {                                                   \
        const int k0_ = (c_) << 5;                                          \
        const uint32_t so_ = (uint32_t)(s_) * (2 * GSTAGE * 4);             \
        _Pragma("unroll")                                                    \
        for (int i_ = 0; i_ < 4; i_++) {                                     \
            CP_ASYNC16(dstA + so_ + i_ * (32 * 36 * 4),                      \
                       Ab + (size_t)(i_ << 5) * K + k0_);                    \
            CP_ASYNC16(dstB + so_ + i_ * (32 * 36 * 4),                      \
                       Wb + (size_t)(i_ << 5) * K + k0_);                    \
        }                                                                    \
        CP_COMMIT();                                                         \
    } while (0)

    ISSUE(0, 0);
    ISSUE(1, 1);

    const int rA = warpM * 32 + gID;
    const int cB = warpN * 64 + gID;

    for (int c = 0; c < nch; c++) {
        const int s = c & 1;
        if (c == nch - 1) { CP_WAITG(0); } else { CP_WAITG(1); }
        __syncthreads();
        const float* As = sm + s * (2 * GSTAGE);
        const float* Bs = As + GSTAGE;
#pragma unroll
        for (int ks = 0; ks < 4; ks++) {
            const int kk = ks << 3;
            uint32_t af[2][4], bf[8][2];
#pragma unroll
            for (int mi = 0; mi < 2; mi++) {
                af[mi][0] = __float_as_uint(As[(rA + mi * 16) * 36 + kk + tig]);
                af[mi][1] = __float_as_uint(As[(rA + mi * 16 + 8) * 36 + kk + tig]);
                af[mi][2] = __float_as_uint(As[(rA + mi * 16) * 36 + kk + tig + 4]);
                af[mi][3] = __float_as_uint(As[(rA + mi * 16 + 8) * 36 + kk + tig + 4]);
            }
#pragma unroll
            for (int ni = 0; ni < 8; ni++) {
                bf[ni][0] = __float_as_uint(Bs[(cB + ni * 8) * 36 + kk + tig]);
                bf[ni][1] = __float_as_uint(Bs[(cB + ni * 8) * 36 + kk + tig + 4]);
            }
#pragma unroll
            for (int mi = 0; mi < 2; mi++)
#pragma unroll
                for (int ni = 0; ni < 8; ni++)
                    MMA_TF32(d[mi][ni], af[mi], bf[ni]);
        }
        __syncthreads();
        if (c + 2 < nch) ISSUE(c + 2, s);
    }
#undef ISSUE

    const int row0 = rowBase + warpM * 32 + gID;
    const int colW = colBase + warpN * 64 + (tig << 1);
#pragma unroll
    for (int ni = 0; ni < 8; ni++) {
        const int col = colW + ni * 8;
        float bx = 0.f, by = 0.f;
        if (bias) { bx = bias[col]; by = bias[col + 1]; }
#pragma unroll
        for (int mi = 0; mi < 2; mi++) {
#pragma unroll
            for (int half = 0; half < 2; half++) {
                int r = row0 + mi * 16 + half * 8;
                float vx = d[mi][ni][half * 2 + 0] + bx;
                float vy = d[mi][ni][half * 2 + 1] + by;
                if (GELU) { vx = rnd_tf32(gelu_tanh(vx)); vy = rnd_tf32(gelu_tanh(vy)); }
                size_t off = (size_t)r * N + col;
                if (RES) {
                    float2 rr = *(const float2*)(R + off);
                    vx += rr.x; vy += rr.y;
                }
                float2 o = { vx, vy };
                *(float2*)(C + off) = o;
            }
        }
    }
}

// ---------------- ONE transpose+round kernel for all weights -----------------
__global__ void transpose_all(const float* __restrict__ qkv_w,
                              const float* __restrict__ proj_w,
                              const float* __restrict__ mlp_w1,
                              const float* __restrict__ mlp_w2,
                              const float* __restrict__ ds_w,
                              float* __restrict__ out)
{
    int i = blockIdx.x * 256 + threadIdx.x;
    const float* in; int K, N, base;
    if (i < 98304)       { base = 0;      in = qkv_w;  K = 128; N = 384; }
    else if (i < 131072) { base = 98304;  in = proj_w; K = 128; N = 128; }
    else if (i < 262144) { base = 131072; in = mlp_w1; K = 128; N = 512; }
    else if (i < 393216) { base = 262144; in = mlp_w2; K = 512; N = 128; }
    else                 { base = 393216; in = ds_w;   K = 512; N = 256; }
    int r = i - base;
    int per = K * N;
    int l = r / per; r -= l * per;
    int n = r / K, k = r - n * K;
    out[i] = __uint_as_float(f2tf32(in[(size_t)l * per + k * N + n]));
}

// ------------------------------ LayerNorm (D=128), one warp per token -------
// Output tf32-rounded (feeds GEMM A pre-rounded).
__global__ void __launch_bounds__(256)
ln128_kernel(const float* __restrict__ in, float* __restrict__ out,
             const float* __restrict__ g, const float* __restrict__ b)
{
    int warp = (blockIdx.x * blockDim.x + threadIdx.x) >> 5;
    int lane = threadIdx.x & 31;
    const float4 v = ((const float4*)(in + (size_t)warp * 128))[lane];
    float s = v.x + v.y + v.z + v.w;
#pragma unroll
    for (int o = 16; o; o >>= 1) s += __shfl_xor_sync(0xffffffffu, s, o);
    float mean = s * (1.0f / 128.0f);
    float dx = v.x - mean, dy = v.y - mean, dz = v.z - mean, dw = v.w - mean;
    float q = dx * dx + dy * dy + dz * dz + dw * dw;
#pragma unroll
    for (int o = 16; o; o >>= 1) q += __shfl_xor_sync(0xffffffffu, q, o);
    float rstd = rsqrtf(q * (1.0f / 128.0f) + 1e-5f);
    float4 gg = ((const float4*)g)[lane];
    float4 bb = ((const float4*)b)[lane];
    float4 r;
    r.x = rnd_tf32(dx * rstd * gg.x + bb.x);
    r.y = rnd_tf32(dy * rstd * gg.y + bb.y);
    r.z = rnd_tf32(dz * rstd * gg.z + bb.z);
    r.w = rnd_tf32(dw * rstd * gg.w + bb.w);
    ((float4*)(out + (size_t)warp * 128))[lane] = r;
}

// ------------------------------ Window attention (R4 layout) ----------------
__global__ void __launch_bounds__(128)
attn_kernel(const float* __restrict__ qkv, float* __restrict__ o,
            int shift, int use_mask)
{
    __shared__ float qs[49][33], ks[49][33], vs[49][33];
    __shared__ float sc[49][49];
    __shared__ int   tok[49];
    __shared__ int   regn[49];

    const int tid  = threadIdx.x;
    const int wid  = tid >> 5, lane = tid & 31;
    const int head = blockIdx.y;
    const int bg   = blockIdx.x;
    const int b    = bg >> 6;
    const int g    = bg & 63;
    const int gy   = g >> 3, gx = g & 7;

    if (tid < 49) {
        int wy = tid / 7, wx = tid - (tid / 7) * 7;
        int ph = gy * 7 + wy, pw = gx * 7 + wx;
        int hh = ph + shift; if (hh >= 56) hh -= 56;
        int ww = pw + shift; if (ww >= 56) ww -= 56;
        tok[tid] = b * 3136 + hh * 56 + ww;
        int rh = (ph < 49) ? 0 : ((ph < 53) ? 1 : 2);
        int rw = (pw < 49) ? 0 : ((pw < 53) ? 1 : 2);
        regn[tid] = rh * 3 + rw;
    }
    __syncthreads();

    for (int i = tid; i < 49 * 8; i += 128) {
        int r = i >> 3, c4 = (i & 7) << 2;
        const float* base = qkv + (size_t)tok[r] * 384 + head * 32 + c4;
        float4 q4 = *(const float4*)(base);
        float4 k4 = *(const float4*)(base + 128);
        float4 v4 = *(const float4*)(base + 256);
        qs[r][c4] = q4.x; qs[r][c4 + 1] = q4.y; qs[r][c4 + 2] = q4.z; qs[r][c4 + 3] = q4.w;
        ks[r][c4] = k4.x; ks[r][c4 + 1] = k4.y; ks[r][c4 + 2] = k4.z; ks[r][c4 + 3] = k4.w;
        vs[r][c4] = v4.x; vs[r][c4 + 1] = v4.y; vs[r][c4 + 2] = v4.z; vs[r][c4 + 3] = v4.w;
    }
    __syncthreads();

    const float scale = 0.17677669529663689f;
    for (int e = tid; e < 2401; e += 128) {
        int i = e / 49, j = e - i * 49;
        float s = 0.f;
#pragma unroll
        for (int c = 0; c < 32; c++) s += qs[i][c] * ks[j][c];
        s *= scale;
        if (use_mask && (regn[i] != regn[j])) s -= 100.f;
        sc[i][j] = s;
    }
    __syncthreads();

    for (int i = wid; i < 49; i += 4) {
        float v0 = (lane < 49) ? sc[i][lane] : -1e30f;
        float v1 = (lane + 32 < 49) ? sc[i][lane + 32] : -1e30f;
        float m = fmaxf(v0, v1);
#pragma unroll
        for (int o2 = 16; o2; o2 >>= 1) m = fmaxf(m, __shfl_xor_sync(0xffffffffu, m, o2));
        float e0 = (lane < 49) ? __expf(v0 - m) : 0.f;
        float e1 = (lane + 32 < 49) ? __expf(v1 - m) : 0.f;
        float s = e0 + e1;
#pragma unroll
        for (int o2 = 16; o2; o2 >>= 1) s += __shfl_xor_sync(0xffffffffu, s, o2);
        float inv = 1.0f / s;
        if (lane < 49) sc[i][lane] = e0 * inv;
        if (lane + 32 < 49) sc[i][lane + 32] = e1 * inv;
    }
    __syncthreads();

    for (int e = tid; e < 49 * 32; e += 128) {
        int i = e >> 5, c = e & 31;
        float s = 0.f;
#pragma unroll 7
        for (int j = 0; j < 49; j++) s += sc[i][j] * vs[j][c];
        o[(size_t)tok[i] * 128 + head * 32 + c] = rnd_tf32(s);
    }
}

// ------------------------------ 2x2 patch merge + LN(512) -------------------
// Output tf32-rounded.
__global__ void __launch_bounds__(256)
merge_ln_kernel(const float* __restrict__ x, float* __restrict__ y,
                const float* __restrict__ g, const float* __restrict__ b)
{
    int warp = (blockIdx.x * blockDim.x + threadIdx.x) >> 5;
    int lane = threadIdx.x & 31;
    int bI = warp / 784;
    int r  = warp - bI * 784;
    int i  = r / 28;
    int j  = r - i * 28;
    int grp = lane >> 3;
    int hh  = grp >> 1, ww = grp & 1;
    int d0  = (lane & 7) << 4;
    const float* src =
        x + (((size_t)(bI * 56 + 2 * i + hh)) * 56 + (2 * j + ww)) * 128 + d0;

    float v[16];
#pragma unroll
    for (int t = 0; t < 4; t++) {
        float4 f = ((const float4*)src)[t];
        v[t * 4 + 0] = f.x; v[t * 4 + 1] = f.y; v[t * 4 + 2] = f.z; v[t * 4 + 3] = f.w;
    }
    float s = 0.f;
#pragma unroll
    for (int t = 0; t < 16; t++) s += v[t];
#pragma unroll
    for (int o = 16; o; o >>= 1) s += __shfl_xor_sync(0xffffffffu, s, o);
    float mean = s * (1.0f / 512.0f);
    float q = 0.f;
#pragma unroll
    for (int t = 0; t < 16; t++) { float dd = v[t] - mean; q += dd * dd; }
#pragma unroll
    for (int o = 16; o; o >>= 1) q += __shfl_xor_sync(0xffffffffu, q, o);
    float rstd = rsqrtf(q * (1.0f / 512.0f) + 1e-5f);

    int c0 = lane << 4;
    float* dst = y + (size_t)warp * 512 + c0;
#pragma unroll
    for (int t = 0; t < 4; t++) {
        float4 gg = ((const float4*)(g + c0))[t];
        float4 bb = ((const float4*)(b + c0))[t];
        float4 out;
        out.x = rnd_tf32((v[t * 4 + 0] - mean) * rstd * gg.x + bb.x);
        out.y = rnd_tf32((v[t * 4 + 1] - mean) * rstd * gg.y + bb.y);
        out.z = rnd_tf32((v[t * 4 + 2] - mean) * rstd * gg.z + bb.z);
        out.w = rnd_tf32((v[t * 4 + 3] - mean) * rstd * gg.w + bb.w);
        ((float4*)dst)[t] = out;
    }
}

// ---------------------------------------------------------------------------
extern "C" void kernel_launch(void* const* d_in, const int* in_sizes, int n_in,
                              void* d_out, int out_size)
{
    const float* x       = (const float*)d_in[0];
    const float* ln1_g   = (const float*)d_in[1];
    const float* ln1_b   = (const float*)d_in[2];
    const float* qkv_w   = (const float*)d_in[3];
    const float* qkv_b   = (const float*)d_in[4];
    const float* proj_w  = (const float*)d_in[5];
    const float* proj_b  = (const float*)d_in[6];
    const float* ln2_g   = (const float*)d_in[7];
    const float* ln2_b   = (const float*)d_in[8];
    const float* mlp_w1  = (const float*)d_in[9];
    const float* mlp_b1  = (const float*)d_in[10];
    const float* mlp_w2  = (const float*)d_in[11];
    const float* mlp_b2  = (const float*)d_in[12];
    const float* dsn_g   = (const float*)d_in[13];
    const float* dsn_b   = (const float*)d_in[14];
    const float* ds_w    = (const float*)d_in[15];
    float* out           = (float*)d_out;

    float *gx, *gh, *gq, *go, *ghid, *gds, *gwt;
    cudaGetSymbolAddress((void**)&gx,   g_x);
    cudaGetSymbolAddress((void**)&gh,   g_h);
    cudaGetSymbolAddress((void**)&gq,   g_qkv);
    cudaGetSymbolAddress((void**)&go,   g_o);
    cudaGetSymbolAddress((void**)&ghid, g_hid);
    cudaGetSymbolAddress((void**)&gds,  g_ds);
    cudaGetSymbolAddress((void**)&gwt,  g_wt);

    cudaFuncSetAttribute(gemm_mma<false, false>, cudaFuncAttributeMaxDynamicSharedMemorySize, GEMM_SMEM);
    cudaFuncSetAttribute(gemm_mma<false, true>,  cudaFuncAttributeMaxDynamicSharedMemorySize, GEMM_SMEM);
    cudaFuncSetAttribute(gemm_mma<true, false>,  cudaFuncAttributeMaxDynamicSharedMemorySize, GEMM_SMEM);

    transpose_all<<<524288 / 256, 256>>>(qkv_w, proj_w, mlp_w1, mlp_w2, ds_w, gwt);

    const int lnBlocks = TOK / 8;
    const dim3 attnGrid(4096, 4);

    for (int layer = 0; layer < 2; layer++) {
        const float* res_in = (layer == 0) ? x : gx;
        int shift   = (layer == 1) ? 3 : 0;
        int useMask = (layer == 1) ? 1 : 0;

        ln128_kernel<<<lnBlocks, 256>>>(res_in, gh,
                                        ln1_g + layer * 128, ln1_b + layer * 128);
        gemm_mma<false, false><<<dim3(3, TOK / 128), 256, GEMM_SMEM>>>(
            gh, gwt + 0 + layer * 49152, qkv_b + layer * 384, nullptr, gq, 384, 128);
        attn_kernel<<<attnGrid, 128>>>(gq, go, shift, useMask);
        gemm_mma<false, true><<<dim3(1, TOK / 128), 256, GEMM_SMEM>>>(
            go, gwt + 98304 + layer * 16384, proj_b + layer * 128, res_in, gx, 128, 128);
        ln128_kernel<<<lnBlocks, 256>>>(gx, gh,
                                        ln2_g + layer * 128, ln2_b + layer * 128);
        gemm_mma<true, false><<<dim3(4, TOK / 128), 256, GEMM_SMEM>>>(
            gh, gwt + 131072 + layer * 65536, mlp_b1 + layer * 512, nullptr, ghid, 512, 128);
        gemm_mma<false, true><<<dim3(1, TOK / 128), 256, GEMM_SMEM>>>(
            ghid, gwt + 262144 + layer * 65536, mlp_b2 + layer * 128, gx, gx, 128, 512);
    }

    merge_ln_kernel<<<DSTOK / 8, 256>>>(gx, gds, dsn_g, dsn_b);
    gemm_mma<false, false><<<dim3(2, DSTOK / 128), 256, GEMM_SMEM>>>(
        gds, gwt + 393216, nullptr, nullptr, out, 256, 512);
}

// round 10
// speedup vs baseline: 1.5753x; 1.4327x over previous
#include <cuda_runtime.h>
#include <cstdint>
#include <math.h>

// ---------------------------------------------------------------------------
// Swin stage on GB300 (compute_103: mma.sync tf32 path).
// R10: R9 skeleton + tensor-core window attention (QK^T and AV on mma.sync).
// ---------------------------------------------------------------------------

#define TOK 200704          // 64*56*56
#define DSTOK 50176         // 64*28*28

__device__ float g_x  [(size_t)TOK * 128];
__device__ float g_h  [(size_t)TOK * 128];
__device__ float g_qkv[(size_t)TOK * 384];
__device__ float g_o  [(size_t)TOK * 128];
__device__ float g_hid[(size_t)TOK * 512];
__device__ float g_ds [(size_t)DSTOK * 512];
__device__ float g_wt [524288];   // transposed weights [N,K] K-major, tf32-rounded

__device__ __forceinline__ uint32_t f2tf32(float f) {
    uint32_t u; asm("cvt.rna.tf32.f32 %0, %1;" : "=r"(u) : "f"(f)); return u;
}
__device__ __forceinline__ float rnd_tf32(float f) {
    return __uint_as_float(f2tf32(f));
}
__device__ __forceinline__ uint32_t smem_u32(const void* p) {
    uint32_t a;
    asm("{ .reg .u64 t; cvta.to.shared.u64 t, %1; cvt.u32.u64 %0, t; }" : "=r"(a) : "l"(p));
    return a;
}

#define CP_ASYNC16(dst, src) \
    asm volatile("cp.async.cg.shared.global [%0], [%1], 16;" :: "r"(dst), "l"(src))
#define CP_COMMIT() asm volatile("cp.async.commit_group;" ::: "memory")
#define CP_WAITG(n) asm volatile("cp.async.wait_group %0;" :: "n"(n) : "memory")

#define MMA_TF32(d, a, b) \
    asm volatile("mma.sync.aligned.m16n8k8.row.col.f32.tf32.tf32.f32 " \
        "{%0,%1,%2,%3}, {%4,%5,%6,%7}, {%8,%9}, {%0,%1,%2,%3};" \
        : "+f"((d)[0]), "+f"((d)[1]), "+f"((d)[2]), "+f"((d)[3]) \
        : "r"((a)[0]), "r"((a)[1]), "r"((a)[2]), "r"((a)[3]), \
          "r"((b)[0]), "r"((b)[1]))

__device__ __forceinline__ float gelu_tanh(float v) {
    float u = 0.7978845608028654f * (v + 0.044715f * v * v * v);
    return 0.5f * v * (1.0f + tanhf(u));
}

// ===================== tf32 mma GEMM, cp.async double-buffered ===============
#define GSTAGE 4608
#define GEMM_SMEM (2 * 2 * GSTAGE * 4)   // 73728 bytes

template <bool GELU, bool RES>
__global__ void __launch_bounds__(256, 2)
gemm_mma(const float* __restrict__ A, const float* __restrict__ WT,
         const float* __restrict__ bias, const float* __restrict__ R,
         float* __restrict__ C, int N, int K)
{
    extern __shared__ float sm[];
    const uint32_t sm0 = smem_u32(sm);
    const int tid  = threadIdx.x;
    const int wid  = tid >> 5, lane = tid & 31;
    const int gID  = lane >> 2, tig = lane & 3;
    const int warpM = wid & 3, warpN = wid >> 2;
    const int rowBase = blockIdx.y << 7;
    const int colBase = blockIdx.x << 7;
    const int lr = tid >> 3;
    const int lc = (tid & 7) << 2;

    const float* Ab  = A  + (size_t)(rowBase + lr) * K + lc;
    const float* Wb  = WT + (size_t)(colBase + lr) * K + lc;
    const uint32_t dstA = sm0 + (uint32_t)(lr * 36 + lc) * 4;
    const uint32_t dstB = dstA + GSTAGE * 4;

    float d[2][8][4];
#pragma unroll
    for (int mi = 0; mi < 2; mi++)
#pragma unroll
        for (int ni = 0; ni < 8; ni++)
#pragma unroll
            for (int e = 0; e < 4; e++) d[mi][ni][e] = 0.f;

    const int nch = K >> 5;

#define ISSUE(c_, s_) do {                                                   \
        const int k0_ = (c_) << 5;                                          \
        const uint32_t so_ = (uint32_t)(s_) * (2 * GSTAGE * 4);             \
        _Pragma("unroll")                                                    \
        for (int i_ = 0; i_ < 4; i_++) {                                     \
            CP_ASYNC16(dstA + so_ + i_ * (32 * 36 * 4),                      \
                       Ab + (size_t)(i_ << 5) * K + k0_);                    \
            CP_ASYNC16(dstB + so_ + i_ * (32 * 36 * 4),                      \
                       Wb + (size_t)(i_ << 5) * K + k0_);                    \
        }                                                                    \
        CP_COMMIT();                                                         \
    } while (0)

    ISSUE(0, 0);
    ISSUE(1, 1);

    const int rA = warpM * 32 + gID;
    const int cB = warpN * 64 + gID;

    for (int c = 0; c < nch; c++) {
        const int s = c & 1;
        if (c == nch - 1) { CP_WAITG(0); } else { CP_WAITG(1); }
        __syncthreads();
        const float* As = sm + s * (2 * GSTAGE);
        const float* Bs = As + GSTAGE;
#pragma unroll
        for (int ks = 0; ks < 4; ks++) {
            const int kk = ks << 3;
            uint32_t af[2][4], bf[8][2];
#pragma unroll
            for (int mi = 0; mi < 2; mi++) {
                af[mi][0] = __float_as_uint(As[(rA + mi * 16) * 36 + kk + tig]);
                af[mi][1] = __float_as_uint(As[(rA + mi * 16 + 8) * 36 + kk + tig]);
                af[mi][2] = __float_as_uint(As[(rA + mi * 16) * 36 + kk + tig + 4]);
                af[mi][3] = __float_as_uint(As[(rA + mi * 16 + 8) * 36 + kk + tig + 4]);
            }
#pragma unroll
            for (int ni = 0; ni < 8; ni++) {
                bf[ni][0] = __float_as_uint(Bs[(cB + ni * 8) * 36 + kk + tig]);
                bf[ni][1] = __float_as_uint(Bs[(cB + ni * 8) * 36 + kk + tig + 4]);
            }
#pragma unroll
            for (int mi = 0; mi < 2; mi++)
#pragma unroll
                for (int ni = 0; ni < 8; ni++)
                    MMA_TF32(d[mi][ni], af[mi], bf[ni]);
        }
        __syncthreads();
        if (c + 2 < nch) ISSUE(c + 2, s);
    }
#undef ISSUE

    const int row0 = rowBase + warpM * 32 + gID;
    const int colW = colBase + warpN * 64 + (tig << 1);
#pragma unroll
    for (int ni = 0; ni < 8; ni++) {
        const int col = colW + ni * 8;
        float bx = 0.f, by = 0.f;
        if (bias) { bx = bias[col]; by = bias[col + 1]; }
#pragma unroll
        for (int mi = 0; mi < 2; mi++) {
#pragma unroll
            for (int half = 0; half < 2; half++) {
                int r = row0 + mi * 16 + half * 8;
                float vx = d[mi][ni][half * 2 + 0] + bx;
                float vy = d[mi][ni][half * 2 + 1] + by;
                if (GELU) { vx = rnd_tf32(gelu_tanh(vx)); vy = rnd_tf32(gelu_tanh(vy)); }
                size_t off = (size_t)r * N + col;
                if (RES) {
                    float2 rr = *(const float2*)(R + off);
                    vx += rr.x; vy += rr.y;
                }
                float2 o = { vx, vy };
                *(float2*)(C + off) = o;
            }
        }
    }
}

// ---------------- ONE transpose+round kernel for all weights -----------------
__global__ void transpose_all(const float* __restrict__ qkv_w,
                              const float* __restrict__ proj_w,
                              const float* __restrict__ mlp_w1,
                              const float* __restrict__ mlp_w2,
                              const float* __restrict__ ds_w,
                              float* __restrict__ out)
{
    int i = blockIdx.x * 256 + threadIdx.x;
    const float* in; int K, N, base;
    if (i < 98304)       { base = 0;      in = qkv_w;  K = 128; N = 384; }
    else if (i < 131072) { base = 98304;  in = proj_w; K = 128; N = 128; }
    else if (i < 262144) { base = 131072; in = mlp_w1; K = 128; N = 512; }
    else if (i < 393216) { base = 262144; in = mlp_w2; K = 512; N = 128; }
    else                 { base = 393216; in = ds_w;   K = 512; N = 256; }
    int r = i - base;
    int per = K * N;
    int l = r / per; r -= l * per;
    int n = r / K, k = r - n * K;
    out[i] = __uint_as_float(f2tf32(in[(size_t)l * per + k * N + n]));
}

// ------------------------------ LayerNorm (D=128), one warp per token -------
__global__ void __launch_bounds__(256)
ln128_kernel(const float* __restrict__ in, float* __restrict__ out,
             const float* __restrict__ g, const float* __restrict__ b)
{
    int warp = (blockIdx.x * blockDim.x + threadIdx.x) >> 5;
    int lane = threadIdx.x & 31;
    const float4 v = ((const float4*)(in + (size_t)warp * 128))[lane];
    float s = v.x + v.y + v.z + v.w;
#pragma unroll
    for (int o = 16; o; o >>= 1) s += __shfl_xor_sync(0xffffffffu, s, o);
    float mean = s * (1.0f / 128.0f);
    float dx = v.x - mean, dy = v.y - mean, dz = v.z - mean, dw = v.w - mean;
    float q = dx * dx + dy * dy + dz * dz + dw * dw;
#pragma unroll
    for (int o = 16; o; o >>= 1) q += __shfl_xor_sync(0xffffffffu, q, o);
    float rstd = rsqrtf(q * (1.0f / 128.0f) + 1e-5f);
    float4 gg = ((const float4*)g)[lane];
    float4 bb = ((const float4*)b)[lane];
    float4 r;
    r.x = rnd_tf32(dx * rstd * gg.x + bb.x);
    r.y = rnd_tf32(dy * rstd * gg.y + bb.y);
    r.z = rnd_tf32(dz * rstd * gg.z + bb.z);
    r.w = rnd_tf32(dw * rstd * gg.w + bb.w);
    ((float4*)(out + (size_t)warp * 128))[lane] = r;
}

// ------------------------------ Window attention (tensor-core) ---------------
// One block per (b, window, head); 4 warps. M=64 (49 valid), N_keys=56, K=32.
// qs[64][36], ks[56][36], vt[32][60] (V transposed), sc[64][60].
__global__ void __launch_bounds__(128)
attn_kernel(const float* __restrict__ qkv, float* __restrict__ o,
            int shift, int use_mask)
{
    __shared__ float qs[64 * 36];
    __shared__ float ks[56 * 36];
    __shared__ float vt[32 * 60];
    __shared__ float sc[64 * 60];
    __shared__ int   tok[64];
    __shared__ int   regn[64];

    const int tid  = threadIdx.x;
    const int wid  = tid >> 5, lane = tid & 31;
    const int gID  = lane >> 2, tig = lane & 3;
    const int head = blockIdx.y;
    const int bg   = blockIdx.x;
    const int b    = bg >> 6;
    const int g    = bg & 63;
    const int gy   = g >> 3, gx = g & 7;

    if (tid < 64) {
        regn[tid] = 0;
        if (tid < 49) {
            int wy = tid / 7, wx = tid - (tid / 7) * 7;
            int ph = gy * 7 + wy, pw = gx * 7 + wx;
            int hh = ph + shift; if (hh >= 56) hh -= 56;
            int ww = pw + shift; if (ww >= 56) ww -= 56;
            tok[tid] = b * 3136 + hh * 56 + ww;
            int rh = (ph < 49) ? 0 : ((ph < 53) ? 1 : 2);
            int rw = (pw < 49) ? 0 : ((pw < 53) ? 1 : 2);
            regn[tid] = rh * 3 + rw;
        }
    }
    // zero pads: qs rows 49..63 (540), ks rows 49..55 (252), vt cols 49..55 (224)
    for (int i = tid; i < 540; i += 128) qs[49 * 36 + i] = 0.f;
    for (int i = tid; i < 252; i += 128) ks[49 * 36 + i] = 0.f;
    for (int i = tid; i < 224; i += 128) {
        int c = i / 7, j = 49 + (i - c * 7);
        vt[c * 60 + j] = 0.f;
    }
    __syncthreads();

    // load q,k,v (q,k row-major; v transposed), tf32-rounded
    for (int i = tid; i < 49 * 8; i += 128) {
        int r = i >> 3, c4 = (i & 7) << 2;
        const float* base = qkv + (size_t)tok[r] * 384 + head * 32 + c4;
        float4 q4 = *(const float4*)(base);
        float4 k4 = *(const float4*)(base + 128);
        float4 v4 = *(const float4*)(base + 256);
        float4 qr = { rnd_tf32(q4.x), rnd_tf32(q4.y), rnd_tf32(q4.z), rnd_tf32(q4.w) };
        float4 kr = { rnd_tf32(k4.x), rnd_tf32(k4.y), rnd_tf32(k4.z), rnd_tf32(k4.w) };
        *(float4*)&qs[r * 36 + c4] = qr;
        *(float4*)&ks[r * 36 + c4] = kr;
        vt[(c4 + 0) * 60 + r] = rnd_tf32(v4.x);
        vt[(c4 + 1) * 60 + r] = rnd_tf32(v4.y);
        vt[(c4 + 2) * 60 + r] = rnd_tf32(v4.z);
        vt[(c4 + 3) * 60 + r] = rnd_tf32(v4.w);
    }
    __syncthreads();

    const int r0 = wid * 16 + gID;   // this thread's base row (and +8)

    // ---- QK^T: per warp 16 rows x 56 cols, K=32 (4 k-steps)
    float d[7][4];
#pragma unroll
    for (int ni = 0; ni < 7; ni++)
#pragma unroll
        for (int e = 0; e < 4; e++) d[ni][e] = 0.f;

#pragma unroll
    for (int kstep = 0; kstep < 4; kstep++) {
        const int klo = (kstep << 3) + tig, khi = klo + 4;
        uint32_t af[4];
        af[0] = __float_as_uint(qs[r0 * 36 + klo]);
        af[1] = __float_as_uint(qs[(r0 + 8) * 36 + klo]);
        af[2] = __float_as_uint(qs[r0 * 36 + khi]);
        af[3] = __float_as_uint(qs[(r0 + 8) * 36 + khi]);
#pragma unroll
        for (int ni = 0; ni < 7; ni++) {
            uint32_t bf[2];
            bf[0] = __float_as_uint(ks[(gID + ni * 8) * 36 + klo]);
            bf[1] = __float_as_uint(ks[(gID + ni * 8) * 36 + khi]);
            MMA_TF32(d[ni], af, bf);
        }
    }

    // ---- store scores with scale + window mask (+ column padding = -1e30)
    const float scale = 0.17677669529663689f;
    const int rgn0 = regn[r0], rgn1 = regn[r0 + 8];
#pragma unroll
    for (int ni = 0; ni < 7; ni++) {
#pragma unroll
        for (int e = 0; e < 4; e++) {
            int row = r0 + ((e >= 2) ? 8 : 0);
            int j   = ni * 8 + (tig << 1) + (e & 1);
            float val;
            if (j >= 49) val = -1e30f;
            else {
                val = d[ni][e] * scale;
                if (use_mask && (((e >= 2) ? rgn1 : rgn0) != regn[j])) val -= 100.f;
            }
            sc[row * 60 + j] = val;
        }
    }
    __syncthreads();

    // ---- softmax over rows 0..48 (4 warps), weights tf32-rounded
    for (int i = wid; i < 49; i += 4) {
        float v0 = sc[i * 60 + lane];
        float v1 = (lane + 32 < 56) ? sc[i * 60 + lane + 32] : -1e30f;
        float m = fmaxf(v0, v1);
#pragma unroll
        for (int o2 = 16; o2; o2 >>= 1) m = fmaxf(m, __shfl_xor_sync(0xffffffffu, m, o2));
        float e0 = __expf(v0 - m);
        float e1 = (lane + 32 < 56) ? __expf(v1 - m) : 0.f;
        float s = e0 + e1;
#pragma unroll
        for (int o2 = 16; o2; o2 >>= 1) s += __shfl_xor_sync(0xffffffffu, s, o2);
        float inv = 1.0f / s;
        sc[i * 60 + lane] = rnd_tf32(e0 * inv);
        if (lane + 32 < 56) sc[i * 60 + lane + 32] = rnd_tf32(e1 * inv);
    }
    __syncthreads();

    // ---- AV: attn[64x56] @ Vt^T -> [64x32], K=56 (7 k-steps)
    float d2[4][4];
#pragma unroll
    for (int ni = 0; ni < 4; ni++)
#pragma unroll
        for (int e = 0; e < 4; e++) d2[ni][e] = 0.f;

#pragma unroll
    for (int kstep = 0; kstep < 7; kstep++) {
        const int klo = (kstep << 3) + tig, khi = klo + 4;
        uint32_t af[4];
        af[0] = __float_as_uint(sc[r0 * 60 + klo]);
        af[1] = __float_as_uint(sc[(r0 + 8) * 60 + klo]);
        af[2] = __float_as_uint(sc[r0 * 60 + khi]);
        af[3] = __float_as_uint(sc[(r0 + 8) * 60 + khi]);
#pragma unroll
        for (int ni = 0; ni < 4; ni++) {
            uint32_t bf[2];
            bf[0] = __float_as_uint(vt[(gID + ni * 8) * 60 + klo]);
            bf[1] = __float_as_uint(vt[(gID + ni * 8) * 60 + khi]);
            MMA_TF32(d2[ni], af, bf);
        }
    }

    // ---- store output (rows < 49 only), tf32-rounded for proj GEMM
#pragma unroll
    for (int ni = 0; ni < 4; ni++) {
#pragma unroll
        for (int e = 0; e < 4; e++) {
            int row = r0 + ((e >= 2) ? 8 : 0);
            if (row < 49) {
                int c = ni * 8 + (tig << 1) + (e & 1);
                o[(size_t)tok[row] * 128 + head * 32 + c] = rnd_tf32(d2[ni][e]);
            }
        }
    }
}

// ------------------------------ 2x2 patch merge + LN(512) -------------------
__global__ void __launch_bounds__(256)
merge_ln_kernel(const float* __restrict__ x, float* __restrict__ y,
                const float* __restrict__ g, const float* __restrict__ b)
{
    int warp = (blockIdx.x * blockDim.x + threadIdx.x) >> 5;
    int lane = threadIdx.x & 31;
    int bI = warp / 784;
    int r  = warp - bI * 784;
    int i  = r / 28;
    int j  = r - i * 28;
    int grp = lane >> 3;
    int hh  = grp >> 1, ww = grp & 1;
    int d0  = (lane & 7) << 4;
    const float* src =
        x + (((size_t)(bI * 56 + 2 * i + hh)) * 56 + (2 * j + ww)) * 128 + d0;

    float v[16];
#pragma unroll
    for (int t = 0; t < 4; t++) {
        float4 f = ((const float4*)src)[t];
        v[t * 4 + 0] = f.x; v[t * 4 + 1] = f.y; v[t * 4 + 2] = f.z; v[t * 4 + 3] = f.w;
    }
    float s = 0.f;
#pragma unroll
    for (int t = 0; t < 16; t++) s += v[t];
#pragma unroll
    for (int o = 16; o; o >>= 1) s += __shfl_xor_sync(0xffffffffu, s, o);
    float mean = s * (1.0f / 512.0f);
    float q = 0.f;
#pragma unroll
    for (int t = 0; t < 16; t++) { float dd = v[t] - mean; q += dd * dd; }
#pragma unroll
    for (int o = 16; o; o >>= 1) q += __shfl_xor_sync(0xffffffffu, q, o);
    float rstd = rsqrtf(q * (1.0f / 512.0f) + 1e-5f);

    int c0 = lane << 4;
    float* dst = y + (size_t)warp * 512 + c0;
#pragma unroll
    for (int t = 0; t < 4; t++) {
        float4 gg = ((const float4*)(g + c0))[t];
        float4 bb = ((const float4*)(b + c0))[t];
        float4 out;
        out.x = rnd_tf32((v[t * 4 + 0] - mean) * rstd * gg.x + bb.x);
        out.y = rnd_tf32((v[t * 4 + 1] - mean) * rstd * gg.y + bb.y);
        out.z = rnd_tf32((v[t * 4 + 2] - mean) * rstd * gg.z + bb.z);
        out.w = rnd_tf32((v[t * 4 + 3] - mean) * rstd * gg.w + bb.w);
        ((float4*)dst)[t] = out;
    }
}

// ---------------------------------------------------------------------------
extern "C" void kernel_launch(void* const* d_in, const int* in_sizes, int n_in,
                              void* d_out, int out_size)
{
    const float* x       = (const float*)d_in[0];
    const float* ln1_g   = (const float*)d_in[1];
    const float* ln1_b   = (const float*)d_in[2];
    const float* qkv_w   = (const float*)d_in[3];
    const float* qkv_b   = (const float*)d_in[4];
    const float* proj_w  = (const float*)d_in[5];
    const float* proj_b  = (const float*)d_in[6];
    const float* ln2_g   = (const float*)d_in[7];
    const float* ln2_b   = (const float*)d_in[8];
    const float* mlp_w1  = (const float*)d_in[9];
    const float* mlp_b1  = (const float*)d_in[10];
    const float* mlp_w2  = (const float*)d_in[11];
    const float* mlp_b2  = (const float*)d_in[12];
    const float* dsn_g   = (const float*)d_in[13];
    const float* dsn_b   = (const float*)d_in[14];
    const float* ds_w    = (const float*)d_in[15];
    float* out           = (float*)d_out;

    float *gx, *gh, *gq, *go, *ghid, *gds, *gwt;
    cudaGetSymbolAddress((void**)&gx,   g_x);
    cudaGetSymbolAddress((void**)&gh,   g_h);
    cudaGetSymbolAddress((void**)&gq,   g_qkv);
    cudaGetSymbolAddress((void**)&go,   g_o);
    cudaGetSymbolAddress((void**)&ghid, g_hid);
    cudaGetSymbolAddress((void**)&gds,  g_ds);
    cudaGetSymbolAddress((void**)&gwt,  g_wt);

    cudaFuncSetAttribute(gemm_mma<false, false>, cudaFuncAttributeMaxDynamicSharedMemorySize, GEMM_SMEM);
    cudaFuncSetAttribute(gemm_mma<false, true>,  cudaFuncAttributeMaxDynamicSharedMemorySize, GEMM_SMEM);
    cudaFuncSetAttribute(gemm_mma<true, false>,  cudaFuncAttributeMaxDynamicSharedMemorySize, GEMM_SMEM);

    transpose_all<<<524288 / 256, 256>>>(qkv_w, proj_w, mlp_w1, mlp_w2, ds_w, gwt);

    const int lnBlocks = TOK / 8;
    const dim3 attnGrid(4096, 4);

    for (int layer = 0; layer < 2; layer++) {
        const float* res_in = (layer == 0) ? x : gx;
        int shift   = (layer == 1) ? 3 : 0;
        int useMask = (layer == 1) ? 1 : 0;

        ln128_kernel<<<lnBlocks, 256>>>(res_in, gh,
                                        ln1_g + layer * 128, ln1_b + layer * 128);
        gemm_mma<false, false><<<dim3(3, TOK / 128), 256, GEMM_SMEM>>>(
            gh, gwt + 0 + layer * 49152, qkv_b + layer * 384, nullptr, gq, 384, 128);
        attn_kernel<<<attnGrid, 128>>>(gq, go, shift, useMask);
        gemm_mma<false, true><<<dim3(1, TOK / 128), 256, GEMM_SMEM>>>(
            go, gwt + 98304 + layer * 16384, proj_b + layer * 128, res_in, gx, 128, 128);
        ln128_kernel<<<lnBlocks, 256>>>(gx, gh,
                                        ln2_g + layer * 128, ln2_b + layer * 128);
        gemm_mma<true, false><<<dim3(4, TOK / 128), 256, GEMM_SMEM>>>(
            gh, gwt + 131072 + layer * 65536, mlp_b1 + layer * 512, nullptr, ghid, 512, 128);
        gemm_mma<false, true><<<dim3(1, TOK / 128), 256, GEMM_SMEM>>>(
            ghid, gwt + 262144 + layer * 65536, mlp_b2 + layer * 128, gx, gx, 128, 512);
    }

    merge_ln_kernel<<<DSTOK / 8, 256>>>(gx, gds, dsn_g, dsn_b);
    gemm_mma<false, false><<<dim3(2, DSTOK / 128), 256, GEMM_SMEM>>>(
        gds, gwt + 393216, nullptr, nullptr, out, 256, 512);
}

// round 11
// speedup vs baseline: 1.6937x; 1.0752x over previous
#include <cuda_runtime.h>
#include <cstdint>
#include <math.h>

// ---------------------------------------------------------------------------
// Swin stage on GB300 (compute_103: mma.sync tf32 path).
// R11: attn smem aliasing (occupancy) + LN fused into N=128 GEMM epilogues.
// ---------------------------------------------------------------------------

#define TOK 200704          // 64*56*56
#define DSTOK 50176         // 64*28*28

__device__ float g_x  [(size_t)TOK * 128];
__device__ float g_h  [(size_t)TOK * 128];
__device__ float g_qkv[(size_t)TOK * 384];
__device__ float g_o  [(size_t)TOK * 128];
__device__ float g_hid[(size_t)TOK * 512];
__device__ float g_ds [(size_t)DSTOK * 512];
__device__ float g_wt [524288];   // transposed weights [N,K] K-major, tf32-rounded

__device__ __forceinline__ uint32_t f2tf32(float f) {
    uint32_t u; asm("cvt.rna.tf32.f32 %0, %1;" : "=r"(u) : "f"(f)); return u;
}
__device__ __forceinline__ float rnd_tf32(float f) {
    return __uint_as_float(f2tf32(f));
}
__device__ __forceinline__ uint32_t smem_u32(const void* p) {
    uint32_t a;
    asm("{ .reg .u64 t; cvta.to.shared.u64 t, %1; cvt.u32.u64 %0, t; }" : "=r"(a) : "l"(p));
    return a;
}

#define CP_ASYNC16(dst, src) \
    asm volatile("cp.async.cg.shared.global [%0], [%1], 16;" :: "r"(dst), "l"(src))
#define CP_COMMIT() asm volatile("cp.async.commit_group;" ::: "memory")
#define CP_WAITG(n) asm volatile("cp.async.wait_group %0;" :: "n"(n) : "memory")

#define MMA_TF32(d, a, b) \
    asm volatile("mma.sync.aligned.m16n8k8.row.col.f32.tf32.tf32.f32 " \
        "{%0,%1,%2,%3}, {%4,%5,%6,%7}, {%8,%9}, {%0,%1,%2,%3};" \
        : "+f"((d)[0]), "+f"((d)[1]), "+f"((d)[2]), "+f"((d)[3]) \
        : "r"((a)[0]), "r"((a)[1]), "r"((a)[2]), "r"((a)[3]), \
          "r"((b)[0]), "r"((b)[1]))

__device__ __forceinline__ float gelu_tanh(float v) {
    float u = 0.7978845608028654f * (v + 0.044715f * v * v * v);
    return 0.5f * v * (1.0f + tanhf(u));
}

// ===================== tf32 mma GEMM, cp.async double-buffered ===============
// LNOUT (requires N==128, RES=true, GELU=false): epilogue also emits
// C2 = tf32(LN(C)) using in-block row stats (full rows live in the block).
#define GSTAGE 4608
#define GEMM_SMEM    (2 * 2 * GSTAGE * 4)          // 73728 bytes
#define GEMM_SMEM_LN (GEMM_SMEM + 2 * 128 * 8)     // + float2 part[2][128]

template <bool GELU, bool RES, bool LNOUT>
__global__ void __launch_bounds__(256, 2)
gemm_mma(const float* __restrict__ A, const float* __restrict__ WT,
         const float* __restrict__ bias, const float* __restrict__ R,
         float* __restrict__ C, int N, int K,
         const float* __restrict__ lng, const float* __restrict__ lnb,
         float* __restrict__ C2)
{
    extern __shared__ float sm[];
    const uint32_t sm0 = smem_u32(sm);
    const int tid  = threadIdx.x;
    const int wid  = tid >> 5, lane = tid & 31;
    const int gID  = lane >> 2, tig = lane & 3;
    const int warpM = wid & 3, warpN = wid >> 2;
    const int rowBase = blockIdx.y << 7;
    const int colBase = blockIdx.x << 7;
    const int lr = tid >> 3;
    const int lc = (tid & 7) << 2;

    const float* Ab  = A  + (size_t)(rowBase + lr) * K + lc;
    const float* Wb  = WT + (size_t)(colBase + lr) * K + lc;
    const uint32_t dstA = sm0 + (uint32_t)(lr * 36 + lc) * 4;
    const uint32_t dstB = dstA + GSTAGE * 4;

    float d[2][8][4];
#pragma unroll
    for (int mi = 0; mi < 2; mi++)
#pragma unroll
        for (int ni = 0; ni < 8; ni++)
#pragma unroll
            for (int e = 0; e < 4; e++) d[mi][ni][e] = 0.f;

    const int nch = K >> 5;

#define ISSUE(c_, s_) do {                                                   \
        const int k0_ = (c_) << 5;                                          \
        const uint32_t so_ = (uint32_t)(s_) * (2 * GSTAGE * 4);             \
        _Pragma("unroll")                                                    \
        for (int i_ = 0; i_ < 4; i_++) {                                     \
            CP_ASYNC16(dstA + so_ + i_ * (32 * 36 * 4),                      \
                       Ab + (size_t)(i_ << 5) * K + k0_);                    \
            CP_ASYNC16(dstB + so_ + i_ * (32 * 36 * 4),                      \
                       Wb + (size_t)(i_ << 5) * K + k0_);                    \
        }                                                                    \
        CP_COMMIT();                                                         \
    } while (0)

    ISSUE(0, 0);
    ISSUE(1, 1);

    const int rA = warpM * 32 + gID;
    const int cB = warpN * 64 + gID;

    for (int c = 0; c < nch; c++) {
        const int s = c & 1;
        if (c == nch - 1) { CP_WAITG(0); } else { CP_WAITG(1); }
        __syncthreads();
        const float* As = sm + s * (2 * GSTAGE);
        const float* Bs = As + GSTAGE;
#pragma unroll
        for (int ks = 0; ks < 4; ks++) {
            const int kk = ks << 3;
            uint32_t af[2][4], bf[8][2];
#pragma unroll
            for (int mi = 0; mi < 2; mi++) {
                af[mi][0] = __float_as_uint(As[(rA + mi * 16) * 36 + kk + tig]);
                af[mi][1] = __float_as_uint(As[(rA + mi * 16 + 8) * 36 + kk + tig]);
                af[mi][2] = __float_as_uint(As[(rA + mi * 16) * 36 + kk + tig + 4]);
                af[mi][3] = __float_as_uint(As[(rA + mi * 16 + 8) * 36 + kk + tig + 4]);
            }
#pragma unroll
            for (int ni = 0; ni < 8; ni++) {
                bf[ni][0] = __float_as_uint(Bs[(cB + ni * 8) * 36 + kk + tig]);
                bf[ni][1] = __float_as_uint(Bs[(cB + ni * 8) * 36 + kk + tig + 4]);
            }
#pragma unroll
            for (int mi = 0; mi < 2; mi++)
#pragma unroll
                for (int ni = 0; ni < 8; ni++)
                    MMA_TF32(d[mi][ni], af[mi], bf[ni]);
        }
        __syncthreads();
        if (c + 2 < nch) ISSUE(c + 2, s);
    }
#undef ISSUE

    const int row0 = rowBase + warpM * 32 + gID;
    const int colW = colBase + warpN * 64 + (tig << 1);

    if (!LNOUT) {
#pragma unroll
        for (int ni = 0; ni < 8; ni++) {
            const int col = colW + ni * 8;
            float bx = 0.f, by = 0.f;
            if (bias) { bx = bias[col]; by = bias[col + 1]; }
#pragma unroll
            for (int mi = 0; mi < 2; mi++) {
#pragma unroll
                for (int half = 0; half < 2; half++) {
                    int r = row0 + mi * 16 + half * 8;
                    float vx = d[mi][ni][half * 2 + 0] + bx;
                    float vy = d[mi][ni][half * 2 + 1] + by;
                    if (GELU) { vx = rnd_tf32(gelu_tanh(vx)); vy = rnd_tf32(gelu_tanh(vy)); }
                    size_t off = (size_t)r * N + col;
                    if (RES) {
                        float2 rr = *(const float2*)(R + off);
                        vx += rr.x; vy += rr.y;
                    }
                    float2 o = { vx, vy };
                    *(float2*)(C + off) = o;
                }
            }
        }
    } else {
        // pass 1: finalize values (bias + residual) in d; accumulate row sums
        float rs[2][2] = {}, rq[2][2] = {};
#pragma unroll
        for (int ni = 0; ni < 8; ni++) {
            const int col = colW + ni * 8;
            float bx = bias[col], by = bias[col + 1];
#pragma unroll
            for (int mi = 0; mi < 2; mi++) {
#pragma unroll
                for (int half = 0; half < 2; half++) {
                    int r = row0 + mi * 16 + half * 8;
                    size_t off = (size_t)r * 128 + col;
                    float2 rr = *(const float2*)(R + off);
                    float vx = d[mi][ni][half * 2 + 0] + bx + rr.x;
                    float vy = d[mi][ni][half * 2 + 1] + by + rr.y;
                    d[mi][ni][half * 2 + 0] = vx;
                    d[mi][ni][half * 2 + 1] = vy;
                    rs[mi][half] += vx + vy;
                    rq[mi][half] += vx * vx + vy * vy;
                }
            }
        }
        // quad reduce across tig (lanes gID*4 + 0..3)
#pragma unroll
        for (int mi = 0; mi < 2; mi++)
#pragma unroll
            for (int half = 0; half < 2; half++) {
#pragma unroll
                for (int o2 = 1; o2 <= 2; o2 <<= 1) {
                    rs[mi][half] += __shfl_xor_sync(0xffffffffu, rs[mi][half], o2);
                    rq[mi][half] += __shfl_xor_sync(0xffffffffu, rq[mi][half], o2);
                }
            }
        // exchange across the two warpN warps sharing each row
        float2* part = (float2*)(sm + 2 * 2 * GSTAGE);   // [2][128]
        if (tig == 0) {
#pragma unroll
            for (int mi = 0; mi < 2; mi++)
#pragma unroll
                for (int half = 0; half < 2; half++) {
                    int rl = warpM * 32 + gID + mi * 16 + half * 8;
                    float2 p = { rs[mi][half], rq[mi][half] };
                    part[warpN * 128 + rl] = p;
                }
        }
        __syncthreads();
        float mean_r[2][2], rstd_r[2][2];
#pragma unroll
        for (int mi = 0; mi < 2; mi++)
#pragma unroll
            for (int half = 0; half < 2; half++) {
                int rl = warpM * 32 + gID + mi * 16 + half * 8;
                float2 p0 = part[rl], p1 = part[128 + rl];
                float s = p0.x + p1.x, q = p0.y + p1.y;
                float mean = s * (1.0f / 128.0f);
                float var  = q * (1.0f / 128.0f) - mean * mean;
                mean_r[mi][half] = mean;
                rstd_r[mi][half] = rsqrtf(var + 1e-5f);
            }
        // pass 2: store C (residual stream) and C2 = tf32(LN(C))
#pragma unroll
        for (int ni = 0; ni < 8; ni++) {
            const int col = colW + ni * 8;
            float2 ge = __ldg((const float2*)(lng + col));
            float2 be = __ldg((const float2*)(lnb + col));
#pragma unroll
            for (int mi = 0; mi < 2; mi++) {
#pragma unroll
                for (int half = 0; half < 2; half++) {
                    int r = row0 + mi * 16 + half * 8;
                    size_t off = (size_t)r * 128 + col;
                    float vx = d[mi][ni][half * 2 + 0];
                    float vy = d[mi][ni][half * 2 + 1];
                    float2 o = { vx, vy };
                    *(float2*)(C + off) = o;
                    float m = mean_r[mi][half], rstd = rstd_r[mi][half];
                    float2 h;
                    h.x = rnd_tf32((vx - m) * rstd * ge.x + be.x);
                    h.y = rnd_tf32((vy - m) * rstd * ge.y + be.y);
                    *(float2*)(C2 + off) = h;
                }
            }
        }
    }
}

// ---------------- ONE transpose+round kernel for all weights -----------------
__global__ void transpose_all(const float* __restrict__ qkv_w,
                              const float* __restrict__ proj_w,
                              const float* __restrict__ mlp_w1,
                              const float* __restrict__ mlp_w2,
                              const float* __restrict__ ds_w,
                              float* __restrict__ out)
{
    int i = blockIdx.x * 256 + threadIdx.x;
    const float* in; int K, N, base;
    if (i < 98304)       { base = 0;      in = qkv_w;  K = 128; N = 384; }
    else if (i < 131072) { base = 98304;  in = proj_w; K = 128; N = 128; }
    else if (i < 262144) { base = 131072; in = mlp_w1; K = 128; N = 512; }
    else if (i < 393216) { base = 262144; in = mlp_w2; K = 512; N = 128; }
    else                 { base = 393216; in = ds_w;   K = 512; N = 256; }
    int r = i - base;
    int per = K * N;
    int l = r / per; r -= l * per;
    int n = r / K, k = r - n * K;
    out[i] = __uint_as_float(f2tf32(in[(size_t)l * per + k * N + n]));
}

// ------------------------------ LayerNorm (D=128), one warp per token -------
__global__ void __launch_bounds__(256)
ln128_kernel(const float* __restrict__ in, float* __restrict__ out,
             const float* __restrict__ g, const float* __restrict__ b)
{
    int warp = (blockIdx.x * blockDim.x + threadIdx.x) >> 5;
    int lane = threadIdx.x & 31;
    const float4 v = ((const float4*)(in + (size_t)warp * 128))[lane];
    float s = v.x + v.y + v.z + v.w;
#pragma unroll
    for (int o = 16; o; o >>= 1) s += __shfl_xor_sync(0xffffffffu, s, o);
    float mean = s * (1.0f / 128.0f);
    float dx = v.x - mean, dy = v.y - mean, dz = v.z - mean, dw = v.w - mean;
    float q = dx * dx + dy * dy + dz * dz + dw * dw;
#pragma unroll
    for (int o = 16; o; o >>= 1) q += __shfl_xor_sync(0xffffffffu, q, o);
    float rstd = rsqrtf(q * (1.0f / 128.0f) + 1e-5f);
    float4 gg = ((const float4*)g)[lane];
    float4 bb = ((const float4*)b)[lane];
    float4 r;
    r.x = rnd_tf32(dx * rstd * gg.x + bb.x);
    r.y = rnd_tf32(dy * rstd * gg.y + bb.y);
    r.z = rnd_tf32(dz * rstd * gg.z + bb.z);
    r.w = rnd_tf32(dw * rstd * gg.w + bb.w);
    ((float4*)(out + (size_t)warp * 128))[lane] = r;
}

// ------------------------------ Window attention (tensor-core) ---------------
// One block per (b, window, head); 4 warps. M=64 (49 valid), N_keys=56, K=32.
// smem aliasing: sc[64*60] overlays qs[64*36]+ks[56*36] after QK MMA.
__global__ void __launch_bounds__(128)
attn_kernel(const float* __restrict__ qkv, float* __restrict__ o,
            int shift, int use_mask)
{
    __shared__ float buf[4320];        // qs @0 (2304), ks @2304 (2016); sc aliases @0 (3840)
    __shared__ float vt[32 * 60];
    __shared__ int   tok[64];
    __shared__ int   regn[64];
    float* qs = buf;
    float* ks = buf + 2304;
    float* sc = buf;

    const int tid  = threadIdx.x;
    const int wid  = tid >> 5, lane = tid & 31;
    const int gID  = lane >> 2, tig = lane & 3;
    const int head = blockIdx.y;
    const int bg   = blockIdx.x;
    const int b    = bg >> 6;
    const int g    = bg & 63;
    const int gy   = g >> 3, gx = g & 7;

    if (tid < 64) {
        regn[tid] = 0;
        if (tid < 49) {
            int wy = tid / 7, wx = tid - (tid / 7) * 7;
            int ph = gy * 7 + wy, pw = gx * 7 + wx;
            int hh = ph + shift; if (hh >= 56) hh -= 56;
            int ww = pw + shift; if (ww >= 56) ww -= 56;
            tok[tid] = b * 3136 + hh * 56 + ww;
            int rh = (ph < 49) ? 0 : ((ph < 53) ? 1 : 2);
            int rw = (pw < 49) ? 0 : ((pw < 53) ? 1 : 2);
            regn[tid] = rh * 3 + rw;
        }
    }
    // zero pads: qs rows 49..63 (540), ks rows 49..55 (252), vt cols 49..55 (224)
    for (int i = tid; i < 540; i += 128) qs[49 * 36 + i] = 0.f;
    for (int i = tid; i < 252; i += 128) ks[49 * 36 + i] = 0.f;
    for (int i = tid; i < 224; i += 128) {
        int c = i / 7, j = 49 + (i - c * 7);
        vt[c * 60 + j] = 0.f;
    }
    __syncthreads();

    for (int i = tid; i < 49 * 8; i += 128) {
        int r = i >> 3, c4 = (i & 7) << 2;
        const float* base = qkv + (size_t)tok[r] * 384 + head * 32 + c4;
        float4 q4 = *(const float4*)(base);
        float4 k4 = *(const float4*)(base + 128);
        float4 v4 = *(const float4*)(base + 256);
        float4 qr = { rnd_tf32(q4.x), rnd_tf32(q4.y), rnd_tf32(q4.z), rnd_tf32(q4.w) };
        float4 kr = { rnd_tf32(k4.x), rnd_tf32(k4.y), rnd_tf32(k4.z), rnd_tf32(k4.w) };
        *(float4*)&qs[r * 36 + c4] = qr;
        *(float4*)&ks[r * 36 + c4] = kr;
        vt[(c4 + 0) * 60 + r] = rnd_tf32(v4.x);
        vt[(c4 + 1) * 60 + r] = rnd_tf32(v4.y);
        vt[(c4 + 2) * 60 + r] = rnd_tf32(v4.z);
        vt[(c4 + 3) * 60 + r] = rnd_tf32(v4.w);
    }
    __syncthreads();

    const int r0 = wid * 16 + gID;

    // ---- QK^T: per warp 16 rows x 56 cols, K=32
    float d[7][4];
#pragma unroll
    for (int ni = 0; ni < 7; ni++)
#pragma unroll
        for (int e = 0; e < 4; e++) d[ni][e] = 0.f;

#pragma unroll
    for (int kstep = 0; kstep < 4; kstep++) {
        const int klo = (kstep << 3) + tig, khi = klo + 4;
        uint32_t af[4];
        af[0] = __float_as_uint(qs[r0 * 36 + klo]);
        af[1] = __float_as_uint(qs[(r0 + 8) * 36 + klo]);
        af[2] = __float_as_uint(qs[r0 * 36 + khi]);
        af[3] = __float_as_uint(qs[(r0 + 8) * 36 + khi]);
#pragma unroll
        for (int ni = 0; ni < 7; ni++) {
            uint32_t bf[2];
            bf[0] = __float_as_uint(ks[(gID + ni * 8) * 36 + klo]);
            bf[1] = __float_as_uint(ks[(gID + ni * 8) * 36 + khi]);
            MMA_TF32(d[ni], af, bf);
        }
    }
    __syncthreads();   // all warps done reading qs/ks before sc overlays them

    const float scale = 0.17677669529663689f;
    const int rgn0 = regn[r0], rgn1 = regn[r0 + 8];
#pragma unroll
    for (int ni = 0; ni < 7; ni++) {
#pragma unroll
        for (int e = 0; e < 4; e++) {
            int row = r0 + ((e >= 2) ? 8 : 0);
            int j   = ni * 8 + (tig << 1) + (e & 1);
            float val;
            if (j >= 49) val = -1e30f;
            else {
                val = d[ni][e] * scale;
                if (use_mask && (((e >= 2) ? rgn1 : rgn0) != regn[j])) val -= 100.f;
            }
            sc[row * 60 + j] = val;
        }
    }
    __syncthreads();

    for (int i = wid; i < 49; i += 4) {
        float v0 = sc[i * 60 + lane];
        float v1 = (lane + 32 < 56) ? sc[i * 60 + lane + 32] : -1e30f;
        float m = fmaxf(v0, v1);
#pragma unroll
        for (int o2 = 16; o2; o2 >>= 1) m = fmaxf(m, __shfl_xor_sync(0xffffffffu, m, o2));
        float e0 = __expf(v0 - m);
        float e1 = (lane + 32 < 56) ? __expf(v1 - m) : 0.f;
        float s = e0 + e1;
#pragma unroll
        for (int o2 = 16; o2; o2 >>= 1) s += __shfl_xor_sync(0xffffffffu, s, o2);
        float inv = 1.0f / s;
        sc[i * 60 + lane] = rnd_tf32(e0 * inv);
        if (lane + 32 < 56) sc[i * 60 + lane + 32] = rnd_tf32(e1 * inv);
    }
    __syncthreads();

    // ---- AV: attn[64x56] @ Vt^T -> [64x32], K=56
    float d2[4][4];
#pragma unroll
    for (int ni = 0; ni < 4; ni++)
#pragma unroll
        for (int e = 0; e < 4; e++) d2[ni][e] = 0.f;

#pragma unroll
    for (int kstep = 0; kstep < 7; kstep++) {
        const int klo = (kstep << 3) + tig, khi = klo + 4;
        uint32_t af[4];
        af[0] = __float_as_uint(sc[r0 * 60 + klo]);
        af[1] = __float_as_uint(sc[(r0 + 8) * 60 + klo]);
        af[2] = __float_as_uint(sc[r0 * 60 + khi]);
        af[3] = __float_as_uint(sc[(r0 + 8) * 60 + khi]);
#pragma unroll
        for (int ni = 0; ni < 4; ni++) {
            uint32_t bf[2];
            bf[0] = __float_as_uint(vt[(gID + ni * 8) * 60 + klo]);
            bf[1] = __float_as_uint(vt[(gID + ni * 8) * 60 + khi]);
            MMA_TF32(d2[ni], af, bf);
        }
    }

#pragma unroll
    for (int ni = 0; ni < 4; ni++) {
#pragma unroll
        for (int e = 0; e < 4; e++) {
            int row = r0 + ((e >= 2) ? 8 : 0);
            if (row < 49) {
                int c = ni * 8 + (tig << 1) + (e & 1);
                o[(size_t)tok[row] * 128 + head * 32 + c] = rnd_tf32(d2[ni][e]);
            }
        }
    }
}

// ------------------------------ 2x2 patch merge + LN(512) -------------------
__global__ void __launch_bounds__(256)
merge_ln_kernel(const float* __restrict__ x, float* __restrict__ y,
                const float* __restrict__ g, const float* __restrict__ b)
{
    int warp = (blockIdx.x * blockDim.x + threadIdx.x) >> 5;
    int lane = threadIdx.x & 31;
    int bI = warp / 784;
    int r  = warp - bI * 784;
    int i  = r / 28;
    int j  = r - i * 28;
    int grp = lane >> 3;
    int hh  = grp >> 1, ww = grp & 1;
    int d0  = (lane & 7) << 4;
    const float* src =
        x + (((size_t)(bI * 56 + 2 * i + hh)) * 56 + (2 * j + ww)) * 128 + d0;

    float v[16];
#pragma unroll
    for (int t = 0; t < 4; t++) {
        float4 f = ((const float4*)src)[t];
        v[t * 4 + 0] = f.x; v[t * 4 + 1] = f.y; v[t * 4 + 2] = f.z; v[t * 4 + 3] = f.w;
    }
    float s = 0.f;
#pragma unroll
    for (int t = 0; t < 16; t++) s += v[t];
#pragma unroll
    for (int o = 16; o; o >>= 1) s += __shfl_xor_sync(0xffffffffu, s, o);
    float mean = s * (1.0f / 512.0f);
    float q = 0.f;
#pragma unroll
    for (int t = 0; t < 16; t++) { float dd = v[t] - mean; q += dd * dd; }
#pragma unroll
    for (int o = 16; o; o >>= 1) q += __shfl_xor_sync(0xffffffffu, q, o);
    float rstd = rsqrtf(q * (1.0f / 512.0f) + 1e-5f);

    int c0 = lane << 4;
    float* dst = y + (size_t)warp * 512 + c0;
#pragma unroll
    for (int t = 0; t < 4; t++) {
        float4 gg = ((const float4*)(g + c0))[t];
        float4 bb = ((const float4*)(b + c0))[t];
        float4 out;
        out.x = rnd_tf32((v[t * 4 + 0] - mean) * rstd * gg.x + bb.x);
        out.y = rnd_tf32((v[t * 4 + 1] - mean) * rstd * gg.y + bb.y);
        out.z = rnd_tf32((v[t * 4 + 2] - mean) * rstd * gg.z + bb.z);
        out.w = rnd_tf32((v[t * 4 + 3] - mean) * rstd * gg.w + bb.w);
        ((float4*)dst)[t] = out;
    }
}

// ---------------------------------------------------------------------------
extern "C" void kernel_launch(void* const* d_in, const int* in_sizes, int n_in,
                              void* d_out, int out_size)
{
    const float* x       = (const float*)d_in[0];
    const float* ln1_g   = (const float*)d_in[1];
    const float* ln1_b   = (const float*)d_in[2];
    const float* qkv_w   = (const float*)d_in[3];
    const float* qkv_b   = (const float*)d_in[4];
    const float* proj_w  = (const float*)d_in[5];
    const float* proj_b  = (const float*)d_in[6];
    const float* ln2_g   = (const float*)d_in[7];
    const float* ln2_b   = (const float*)d_in[8];
    const float* mlp_w1  = (const float*)d_in[9];
    const float* mlp_b1  = (const float*)d_in[10];
    const float* mlp_w2  = (const float*)d_in[11];
    const float* mlp_b2  = (const float*)d_in[12];
    const float* dsn_g   = (const float*)d_in[13];
    const float* dsn_b   = (const float*)d_in[14];
    const float* ds_w    = (const float*)d_in[15];
    float* out           = (float*)d_out;

    float *gx, *gh, *gq, *go, *ghid, *gds, *gwt;
    cudaGetSymbolAddress((void**)&gx,   g_x);
    cudaGetSymbolAddress((void**)&gh,   g_h);
    cudaGetSymbolAddress((void**)&gq,   g_qkv);
    cudaGetSymbolAddress((void**)&go,   g_o);
    cudaGetSymbolAddress((void**)&ghid, g_hid);
    cudaGetSymbolAddress((void**)&gds,  g_ds);
    cudaGetSymbolAddress((void**)&gwt,  g_wt);

    cudaFuncSetAttribute(gemm_mma<false, false, false>, cudaFuncAttributeMaxDynamicSharedMemorySize, GEMM_SMEM);
    cudaFuncSetAttribute(gemm_mma<false, true, false>,  cudaFuncAttributeMaxDynamicSharedMemorySize, GEMM_SMEM);
    cudaFuncSetAttribute(gemm_mma<true, false, false>,  cudaFuncAttributeMaxDynamicSharedMemorySize, GEMM_SMEM);
    cudaFuncSetAttribute(gemm_mma<false, true, true>,   cudaFuncAttributeMaxDynamicSharedMemorySize, GEMM_SMEM_LN);

    transpose_all<<<524288 / 256, 256>>>(qkv_w, proj_w, mlp_w1, mlp_w2, ds_w, gwt);

    const dim3 attnGrid(4096, 4);

    // ---- layer 0
    ln128_kernel<<<TOK / 8, 256>>>(x, gh, ln1_g, ln1_b);
    gemm_mma<false, false, false><<<dim3(3, TOK / 128), 256, GEMM_SMEM>>>(
        gh, gwt + 0, qkv_b, nullptr, gq, 384, 128, nullptr, nullptr, nullptr);
    attn_kernel<<<attnGrid, 128>>>(gq, go, 0, 0);
    // proj + residual + fused LN2(layer0) -> gx, gh
    gemm_mma<false, true, true><<<dim3(1, TOK / 128), 256, GEMM_SMEM_LN>>>(
        go, gwt + 98304, proj_b, x, gx, 128, 128, ln2_g, ln2_b, gh);
    gemm_mma<true, false, false><<<dim3(4, TOK / 128), 256, GEMM_SMEM>>>(
        gh, gwt + 131072, mlp_b1, nullptr, ghid, 512, 128, nullptr, nullptr, nullptr);
    // MLP2 + residual + fused LN1(layer1) -> gx, gh
    gemm_mma<false, true, true><<<dim3(1, TOK / 128), 256, GEMM_SMEM_LN>>>(
        ghid, gwt + 262144, mlp_b2, gx, gx, 128, 512, ln1_g + 128, ln1_b + 128, gh);

    // ---- layer 1 (shifted)
    gemm_mma<false, false, false><<<dim3(3, TOK / 128), 256, GEMM_SMEM>>>(
        gh, gwt + 49152, qkv_b + 384, nullptr, gq, 384, 128, nullptr, nullptr, nullptr);
    attn_kernel<<<attnGrid, 128>>>(gq, go, 3, 1);
    // proj + residual + fused LN2(layer1) -> gx, gh
    gemm_mma<false, true, true><<<dim3(1, TOK / 128), 256, GEMM_SMEM_LN>>>(
        go, gwt + 98304 + 16384, proj_b + 128, gx, gx, 128, 128, ln2_g + 128, ln2_b + 128, gh);
    gemm_mma<true, false, false><<<dim3(4, TOK / 128), 256, GEMM_SMEM>>>(
        gh, gwt + 131072 + 65536, mlp_b1 + 512, nullptr, ghid, 512, 128, nullptr, nullptr, nullptr);
    // MLP2 + residual (no LN) -> gx
    gemm_mma<false, true, false><<<dim3(1, TOK / 128), 256, GEMM_SMEM>>>(
        ghid, gwt + 262144 + 65536, mlp_b2 + 128, gx, gx, 128, 512, nullptr, nullptr, nullptr);

    // ---- downsample
    merge_ln_kernel<<<DSTOK / 8, 256>>>(gx, gds, dsn_g, dsn_b);
    gemm_mma<false, false, false><<<dim3(2, DSTOK / 128), 256, GEMM_SMEM>>>(
        gds, gwt + 393216, nullptr, nullptr, out, 256, 512, nullptr, nullptr, nullptr);
}

// round 12
// speedup vs baseline: 1.7367x; 1.0254x over previous
#include <cuda_runtime.h>
#include <cstdint>
#include <math.h>

// ---------------------------------------------------------------------------
// Swin stage on GB300 (compute_103: mma.sync tf32 path).
// R12: ldmatrix fragment loads (GEMM + attention) + attn grid swap for L2 reuse.
// ---------------------------------------------------------------------------

#define TOK 200704          // 64*56*56
#define DSTOK 50176         // 64*28*28

__device__ float g_x  [(size_t)TOK * 128];
__device__ float g_h  [(size_t)TOK * 128];
__device__ float g_qkv[(size_t)TOK * 384];
__device__ float g_o  [(size_t)TOK * 128];
__device__ float g_hid[(size_t)TOK * 512];
__device__ float g_ds [(size_t)DSTOK * 512];
__device__ float g_wt [524288];   // transposed weights [N,K] K-major, tf32-rounded

__device__ __forceinline__ uint32_t f2tf32(float f) {
    uint32_t u; asm("cvt.rna.tf32.f32 %0, %1;" : "=r"(u) : "f"(f)); return u;
}
__device__ __forceinline__ float rnd_tf32(float f) {
    return __uint_as_float(f2tf32(f));
}
__device__ __forceinline__ uint32_t smem_u32(const void* p) {
    uint32_t a;
    asm("{ .reg .u64 t; cvta.to.shared.u64 t, %1; cvt.u32.u64 %0, t; }" : "=r"(a) : "l"(p));
    return a;
}

#define CP_ASYNC16(dst, src) \
    asm volatile("cp.async.cg.shared.global [%0], [%1], 16;" :: "r"(dst), "l"(src))
#define CP_COMMIT() asm volatile("cp.async.commit_group;" ::: "memory")
#define CP_WAITG(n) asm volatile("cp.async.wait_group %0;" :: "n"(n) : "memory")

#define MMA_TF32(d, a, b) \
    asm volatile("mma.sync.aligned.m16n8k8.row.col.f32.tf32.tf32.f32 " \
        "{%0,%1,%2,%3}, {%4,%5,%6,%7}, {%8,%9}, {%0,%1,%2,%3};" \
        : "+f"((d)[0]), "+f"((d)[1]), "+f"((d)[2]), "+f"((d)[3]) \
        : "r"((a)[0]), "r"((a)[1]), "r"((a)[2]), "r"((a)[3]), \
          "r"((b)[0]), "r"((b)[1]))

#define LDMX4(r0, r1, r2, r3, addr) \
    asm volatile("ldmatrix.sync.aligned.m8n8.x4.shared.b16 {%0,%1,%2,%3}, [%4];" \
        : "=r"(r0), "=r"(r1), "=r"(r2), "=r"(r3) : "r"(addr))
#define LDMX2(r0, r1, addr) \
    asm volatile("ldmatrix.sync.aligned.m8n8.x2.shared.b16 {%0,%1}, [%2];" \
        : "=r"(r0), "=r"(r1) : "r"(addr))

__device__ __forceinline__ float gelu_tanh(float v) {
    float u = 0.7978845608028654f * (v + 0.044715f * v * v * v);
    return 0.5f * v * (1.0f + tanhf(u));
}

// ===================== tf32 mma GEMM, cp.async double-buffered ===============
// Fragments loaded via ldmatrix (tf32 as b16-pair matrices).
// A-fragment x4 map: m0=rows+0/k+0, m1=rows+8/k+0, m2=rows+0/k+4, m3=rows+8/k+4
//   -> thread addr: row += (sel&1)*8, col += (sel>>1)*4   (sel = lane>>3)
// B-fragment x4 map (two n8 tiles): m0=n+0/k+0, m1=n+0/k+4, m2=n+8/k+0, m3=n+8/k+4
//   -> thread addr: row += (sel>>1)*8, col += (sel&1)*4
#define GSTAGE 4608
#define GEMM_SMEM    (2 * 2 * GSTAGE * 4)          // 73728 bytes
#define GEMM_SMEM_LN (GEMM_SMEM + 2 * 128 * 8)     // + float2 part[2][128]

template <bool GELU, bool RES, bool LNOUT>
__global__ void __launch_bounds__(256, 2)
gemm_mma(const float* __restrict__ A, const float* __restrict__ WT,
         const float* __restrict__ bias, const float* __restrict__ R,
         float* __restrict__ C, int N, int K,
         const float* __restrict__ lng, const float* __restrict__ lnb,
         float* __restrict__ C2)
{
    extern __shared__ float sm[];
    const uint32_t sm0 = smem_u32(sm);
    const int tid  = threadIdx.x;
    const int wid  = tid >> 5, lane = tid & 31;
    const int gID  = lane >> 2, tig = lane & 3;
    const int warpM = wid & 3, warpN = wid >> 2;
    const int rowBase = blockIdx.y << 7;
    const int colBase = blockIdx.x << 7;
    const int lr = tid >> 3;
    const int lc = (tid & 7) << 2;

    const float* Ab  = A  + (size_t)(rowBase + lr) * K + lc;
    const float* Wb  = WT + (size_t)(colBase + lr) * K + lc;
    const uint32_t dstA = sm0 + (uint32_t)(lr * 36 + lc) * 4;
    const uint32_t dstB = dstA + GSTAGE * 4;

    // ldmatrix per-thread address components
    const int lane8 = lane & 7, sel = lane >> 3;
    const int aRowF = warpM * 32 + lane8 + ((sel & 1) << 3);
    const int aColF = (sel >> 1) << 2;
    const int bRowF = warpN * 64 + lane8 + ((sel >> 1) << 3);
    const int bColF = (sel & 1) << 2;

    float d[2][8][4];
#pragma unroll
    for (int mi = 0; mi < 2; mi++)
#pragma unroll
        for (int ni = 0; ni < 8; ni++)
#pragma unroll
            for (int e = 0; e < 4; e++) d[mi][ni][e] = 0.f;

    const int nch = K >> 5;

#define ISSUE(c_, s_) do {                                                   \
        const int k0_ = (c_) << 5;                                          \
        const uint32_t so_ = (uint32_t)(s_) * (2 * GSTAGE * 4);             \
        _Pragma("unroll")                                                    \
        for (int i_ = 0; i_ < 4; i_++) {                                     \
            CP_ASYNC16(dstA + so_ + i_ * (32 * 36 * 4),                      \
                       Ab + (size_t)(i_ << 5) * K + k0_);                    \
            CP_ASYNC16(dstB + so_ + i_ * (32 * 36 * 4),                      \
                       Wb + (size_t)(i_ << 5) * K + k0_);                    \
        }                                                                    \
        CP_COMMIT();                                                         \
    } while (0)

    ISSUE(0, 0);
    ISSUE(1, 1);

    for (int c = 0; c < nch; c++) {
        const int s = c & 1;
        if (c == nch - 1) { CP_WAITG(0); } else { CP_WAITG(1); }
        __syncthreads();
        const uint32_t stA = sm0 + (uint32_t)s * (2 * GSTAGE * 4);
        const uint32_t stB = stA + GSTAGE * 4;
        const uint32_t aBase = stA + (uint32_t)(aRowF * 36 + aColF) * 4;
        const uint32_t bBase = stB + (uint32_t)(bRowF * 36 + bColF) * 4;
#pragma unroll
        for (int ks = 0; ks < 4; ks++) {
            const uint32_t kb = (uint32_t)(ks << 5);   // kk*4 bytes
            uint32_t af[2][4], bf[8][2];
#pragma unroll
            for (int mi = 0; mi < 2; mi++)
                LDMX4(af[mi][0], af[mi][1], af[mi][2], af[mi][3],
                      aBase + kb + (uint32_t)(mi * 16 * 36 * 4));
#pragma unroll
            for (int p = 0; p < 4; p++)
                LDMX4(bf[2 * p][0], bf[2 * p][1], bf[2 * p + 1][0], bf[2 * p + 1][1],
                      bBase + kb + (uint32_t)(p * 16 * 36 * 4));
#pragma unroll
            for (int mi = 0; mi < 2; mi++)
#pragma unroll
                for (int ni = 0; ni < 8; ni++)
                    MMA_TF32(d[mi][ni], af[mi], bf[ni]);
        }
        __syncthreads();
        if (c + 2 < nch) ISSUE(c + 2, s);
    }
#undef ISSUE

    const int row0 = rowBase + warpM * 32 + gID;
    const int colW = colBase + warpN * 64 + (tig << 1);

    if (!LNOUT) {
#pragma unroll
        for (int ni = 0; ni < 8; ni++) {
            const int col = colW + ni * 8;
            float bx = 0.f, by = 0.f;
            if (bias) { bx = bias[col]; by = bias[col + 1]; }
#pragma unroll
            for (int mi = 0; mi < 2; mi++) {
#pragma unroll
                for (int half = 0; half < 2; half++) {
                    int r = row0 + mi * 16 + half * 8;
                    float vx = d[mi][ni][half * 2 + 0] + bx;
                    float vy = d[mi][ni][half * 2 + 1] + by;
                    if (GELU) { vx = rnd_tf32(gelu_tanh(vx)); vy = rnd_tf32(gelu_tanh(vy)); }
                    size_t off = (size_t)r * N + col;
                    if (RES) {
                        float2 rr = *(const float2*)(R + off);
                        vx += rr.x; vy += rr.y;
                    }
                    float2 o = { vx, vy };
                    *(float2*)(C + off) = o;
                }
            }
        }
    } else {
        float rs[2][2] = {}, rq[2][2] = {};
#pragma unroll
        for (int ni = 0; ni < 8; ni++) {
            const int col = colW + ni * 8;
            float bx = bias[col], by = bias[col + 1];
#pragma unroll
            for (int mi = 0; mi < 2; mi++) {
#pragma unroll
                for (int half = 0; half < 2; half++) {
                    int r = row0 + mi * 16 + half * 8;
                    size_t off = (size_t)r * 128 + col;
                    float2 rr = *(const float2*)(R + off);
                    float vx = d[mi][ni][half * 2 + 0] + bx + rr.x;
                    float vy = d[mi][ni][half * 2 + 1] + by + rr.y;
                    d[mi][ni][half * 2 + 0] = vx;
                    d[mi][ni][half * 2 + 1] = vy;
                    rs[mi][half] += vx + vy;
                    rq[mi][half] += vx * vx + vy * vy;
                }
            }
        }
#pragma unroll
        for (int mi = 0; mi < 2; mi++)
#pragma unroll
            for (int half = 0; half < 2; half++) {
#pragma unroll
                for (int o2 = 1; o2 <= 2; o2 <<= 1) {
                    rs[mi][half] += __shfl_xor_sync(0xffffffffu, rs[mi][half], o2);
                    rq[mi][half] += __shfl_xor_sync(0xffffffffu, rq[mi][half], o2);
                }
            }
        float2* part = (float2*)(sm + 2 * 2 * GSTAGE);
        if (tig == 0) {
#pragma unroll
            for (int mi = 0; mi < 2; mi++)
#pragma unroll
                for (int half = 0; half < 2; half++) {
                    int rl = warpM * 32 + gID + mi * 16 + half * 8;
                    float2 p = { rs[mi][half], rq[mi][half] };
                    part[warpN * 128 + rl] = p;
                }
        }
        __syncthreads();
        float mean_r[2][2], rstd_r[2][2];
#pragma unroll
        for (int mi = 0; mi < 2; mi++)
#pragma unroll
            for (int half = 0; half < 2; half++) {
                int rl = warpM * 32 + gID + mi * 16 + half * 8;
                float2 p0 = part[rl], p1 = part[128 + rl];
                float s = p0.x + p1.x, q = p0.y + p1.y;
                float mean = s * (1.0f / 128.0f);
                float var  = q * (1.0f / 128.0f) - mean * mean;
                mean_r[mi][half] = mean;
                rstd_r[mi][half] = rsqrtf(var + 1e-5f);
            }
#pragma unroll
        for (int ni = 0; ni < 8; ni++) {
            const int col = colW + ni * 8;
            float2 ge = __ldg((const float2*)(lng + col));
            float2 be = __ldg((const float2*)(lnb + col));
#pragma unroll
            for (int mi = 0; mi < 2; mi++) {
#pragma unroll
                for (int half = 0; half < 2; half++) {
                    int r = row0 + mi * 16 + half * 8;
                    size_t off = (size_t)r * 128 + col;
                    float vx = d[mi][ni][half * 2 + 0];
                    float vy = d[mi][ni][half * 2 + 1];
                    float2 o = { vx, vy };
                    *(float2*)(C + off) = o;
                    float m = mean_r[mi][half], rstd = rstd_r[mi][half];
                    float2 h;
                    h.x = rnd_tf32((vx - m) * rstd * ge.x + be.x);
                    h.y = rnd_tf32((vy - m) * rstd * ge.y + be.y);
                    *(float2*)(C2 + off) = h;
                }
            }
        }
    }
}

// ---------------- ONE transpose+round kernel for all weights -----------------
__global__ void transpose_all(const float* __restrict__ qkv_w,
                              const float* __restrict__ proj_w,
                              const float* __restrict__ mlp_w1,
                              const float* __restrict__ mlp_w2,
                              const float* __restrict__ ds_w,
                              float* __restrict__ out)
{
    int i = blockIdx.x * 256 + threadIdx.x;
    const float* in; int K, N, base;
    if (i < 98304)       { base = 0;      in = qkv_w;  K = 128; N = 384; }
    else if (i < 131072) { base = 98304;  in = proj_w; K = 128; N = 128; }
    else if (i < 262144) { base = 131072; in = mlp_w1; K = 128; N = 512; }
    else if (i < 393216) { base = 262144; in = mlp_w2; K = 512; N = 128; }
    else                 { base = 393216; in = ds_w;   K = 512; N = 256; }
    int r = i - base;
    int per = K * N;
    int l = r / per; r -= l * per;
    int n = r / K, k = r - n * K;
    out[i] = __uint_as_float(f2tf32(in[(size_t)l * per + k * N + n]));
}

// ------------------------------ LayerNorm (D=128), one warp per token -------
__global__ void __launch_bounds__(256)
ln128_kernel(const float* __restrict__ in, float* __restrict__ out,
             const float* __restrict__ g, const float* __restrict__ b)
{
    int warp = (blockIdx.x * blockDim.x + threadIdx.x) >> 5;
    int lane = threadIdx.x & 31;
    const float4 v = ((const float4*)(in + (size_t)warp * 128))[lane];
    float s = v.x + v.y + v.z + v.w;
#pragma unroll
    for (int o = 16; o; o >>= 1) s += __shfl_xor_sync(0xffffffffu, s, o);
    float mean = s * (1.0f / 128.0f);
    float dx = v.x - mean, dy = v.y - mean, dz = v.z - mean, dw = v.w - mean;
    float q = dx * dx + dy * dy + dz * dz + dw * dw;
#pragma unroll
    for (int o = 16; o; o >>= 1) q += __shfl_xor_sync(0xffffffffu, q, o);
    float rstd = rsqrtf(q * (1.0f / 128.0f) + 1e-5f);
    float4 gg = ((const float4*)g)[lane];
    float4 bb = ((const float4*)b)[lane];
    float4 r;
    r.x = rnd_tf32(dx * rstd * gg.x + bb.x);
    r.y = rnd_tf32(dy * rstd * gg.y + bb.y);
    r.z = rnd_tf32(dz * rstd * gg.z + bb.z);
    r.w = rnd_tf32(dw * rstd * gg.w + bb.w);
    ((float4*)(out + (size_t)warp * 128))[lane] = r;
}

// ------------------------------ Window attention (tensor-core + ldmatrix) ----
// Grid (4, 4096): head = blockIdx.x (fast) so the 4 head-blocks of a window are
// launch-adjacent -> qkv rows hit L2. smem aliasing: sc overlays qs+ks.
__global__ void __launch_bounds__(128)
attn_kernel(const float* __restrict__ qkv, float* __restrict__ o,
            int shift, int use_mask)
{
    __shared__ float buf[4320];        // qs @0 (2304), ks @2304 (2016); sc aliases @0
    __shared__ float vt[32 * 60];
    __shared__ int   tok[64];
    __shared__ int   regn[64];
    float* qs = buf;
    float* ks = buf + 2304;
    float* sc = buf;

    const int tid  = threadIdx.x;
    const int wid  = tid >> 5, lane = tid & 31;
    const int gID  = lane >> 2, tig = lane & 3;
    const int head = blockIdx.x;
    const int bg   = blockIdx.y;
    const int b    = bg >> 6;
    const int g    = bg & 63;
    const int gy   = g >> 3, gx = g & 7;

    const uint32_t bufB = smem_u32(buf);
    const uint32_t ksB  = bufB + 2304 * 4;
    const uint32_t vtB  = smem_u32(vt);
    const int lane8 = lane & 7, sel = lane >> 3;
    // A map: row += (sel&1)*8, col += (sel>>1)*4 ; B map: row += (sel>>1)*8, col += (sel&1)*4
    const int aRow = wid * 16 + lane8 + ((sel & 1) << 3);
    const int aCol = (sel >> 1) << 2;
    const int bRow = lane8 + ((sel >> 1) << 3);
    const int bCol = (sel & 1) << 2;

    if (tid < 64) {
        regn[tid] = 0;
        if (tid < 49) {
            int wy = tid / 7, wx = tid - (tid / 7) * 7;
            int ph = gy * 7 + wy, pw = gx * 7 + wx;
            int hh = ph + shift; if (hh >= 56) hh -= 56;
            int ww = pw + shift; if (ww >= 56) ww -= 56;
            tok[tid] = b * 3136 + hh * 56 + ww;
            int rh = (ph < 49) ? 0 : ((ph < 53) ? 1 : 2);
            int rw = (pw < 49) ? 0 : ((pw < 53) ? 1 : 2);
            regn[tid] = rh * 3 + rw;
        }
    }
    for (int i = tid; i < 540; i += 128) qs[49 * 36 + i] = 0.f;
    for (int i = tid; i < 252; i += 128) ks[49 * 36 + i] = 0.f;
    for (int i = tid; i < 224; i += 128) {
        int c = i / 7, j = 49 + (i - c * 7);
        vt[c * 60 + j] = 0.f;
    }
    __syncthreads();

    for (int i = tid; i < 49 * 8; i += 128) {
        int r = i >> 3, c4 = (i & 7) << 2;
        const float* base = qkv + (size_t)tok[r] * 384 + head * 32 + c4;
        float4 q4 = *(const float4*)(base);
        float4 k4 = *(const float4*)(base + 128);
        float4 v4 = *(const float4*)(base + 256);
        float4 qr = { rnd_tf32(q4.x), rnd_tf32(q4.y), rnd_tf32(q4.z), rnd_tf32(q4.w) };
        float4 kr = { rnd_tf32(k4.x), rnd_tf32(k4.y), rnd_tf32(k4.z), rnd_tf32(k4.w) };
        *(float4*)&qs[r * 36 + c4] = qr;
        *(float4*)&ks[r * 36 + c4] = kr;
        vt[(c4 + 0) * 60 + r] = rnd_tf32(v4.x);
        vt[(c4 + 1) * 60 + r] = rnd_tf32(v4.y);
        vt[(c4 + 2) * 60 + r] = rnd_tf32(v4.z);
        vt[(c4 + 3) * 60 + r] = rnd_tf32(v4.w);
    }
    __syncthreads();

    const int r0 = wid * 16 + gID;

    // ---- QK^T via ldmatrix: A = qs (stride 36), B = ks (stride 36), K=32
    float d[7][4];
#pragma unroll
    for (int ni = 0; ni < 7; ni++)
#pragma unroll
        for (int e = 0; e < 4; e++) d[ni][e] = 0.f;

    {
        const uint32_t aB = bufB + (uint32_t)(aRow * 36 + aCol) * 4;
        const uint32_t bB = ksB + (uint32_t)(bRow * 36 + bCol) * 4;
#pragma unroll
        for (int kstep = 0; kstep < 4; kstep++) {
            const uint32_t kb = (uint32_t)(kstep << 5);
            uint32_t af[4], bf[7][2];
            LDMX4(af[0], af[1], af[2], af[3], aB + kb);
#pragma unroll
            for (int p = 0; p < 3; p++)
                LDMX4(bf[2 * p][0], bf[2 * p][1], bf[2 * p + 1][0], bf[2 * p + 1][1],
                      bB + kb + (uint32_t)(p * 16 * 36 * 4));
            LDMX2(bf[6][0], bf[6][1], bB + kb + (uint32_t)(48 * 36 * 4));
#pragma unroll
            for (int ni = 0; ni < 7; ni++)
                MMA_TF32(d[ni], af, bf[ni]);
        }
    }
    __syncthreads();   // all warps done reading qs/ks before sc overlays them

    const float scale = 0.17677669529663689f;
    const int rgn0 = regn[r0], rgn1 = regn[r0 + 8];
#pragma unroll
    for (int ni = 0; ni < 7; ni++) {
#pragma unroll
        for (int e = 0; e < 4; e++) {
            int row = r0 + ((e >= 2) ? 8 : 0);
            int j   = ni * 8 + (tig << 1) + (e & 1);
            float val;
            if (j >= 49) val = -1e30f;
            else {
                val = d[ni][e] * scale;
                if (use_mask && (((e >= 2) ? rgn1 : rgn0) != regn[j])) val -= 100.f;
            }
            sc[row * 60 + j] = val;
        }
    }
    __syncthreads();

    for (int i = wid; i < 49; i += 4) {
        float v0 = sc[i * 60 + lane];
        float v1 = (lane + 32 < 56) ? sc[i * 60 + lane + 32] : -1e30f;
        float m = fmaxf(v0, v1);
#pragma unroll
        for (int o2 = 16; o2; o2 >>= 1) m = fmaxf(m, __shfl_xor_sync(0xffffffffu, m, o2));
        float e0 = __expf(v0 - m);
        float e1 = (lane + 32 < 56) ? __expf(v1 - m) : 0.f;
        float s = e0 + e1;
#pragma unroll
        for (int o2 = 16; o2; o2 >>= 1) s += __shfl_xor_sync(0xffffffffu, s, o2);
        float inv = 1.0f / s;
        sc[i * 60 + lane] = rnd_tf32(e0 * inv);
        if (lane + 32 < 56) sc[i * 60 + lane + 32] = rnd_tf32(e1 * inv);
    }
    __syncthreads();

    // ---- AV via ldmatrix: A = sc (stride 60), B = vt (stride 60), K=56
    float d2[4][4];
#pragma unroll
    for (int ni = 0; ni < 4; ni++)
#pragma unroll
        for (int e = 0; e < 4; e++) d2[ni][e] = 0.f;

    {
        const uint32_t aB = bufB + (uint32_t)(aRow * 60 + aCol) * 4;
        const uint32_t bB = vtB + (uint32_t)(bRow * 60 + bCol) * 4;
#pragma unroll
        for (int kstep = 0; kstep < 7; kstep++) {
            const uint32_t kb = (uint32_t)(kstep << 5);
            uint32_t af[4], bf[4][2];
            LDMX4(af[0], af[1], af[2], af[3], aB + kb);
#pragma unroll
            for (int p = 0; p < 2; p++)
                LDMX4(bf[2 * p][0], bf[2 * p][1], bf[2 * p + 1][0], bf[2 * p + 1][1],
                      bB + kb + (uint32_t)(p * 16 * 60 * 4));
#pragma unroll
            for (int ni = 0; ni < 4; ni++)
                MMA_TF32(d2[ni], af, bf[ni]);
        }
    }

#pragma unroll
    for (int ni = 0; ni < 4; ni++) {
#pragma unroll
        for (int e = 0; e < 4; e++) {
            int row = r0 + ((e >= 2) ? 8 : 0);
            if (row < 49) {
                int c = ni * 8 + (tig << 1) + (e & 1);
                o[(size_t)tok[row] * 128 + head * 32 + c] = rnd_tf32(d2[ni][e]);
            }
        }
    }
}

// ------------------------------ 2x2 patch merge + LN(512) -------------------
__global__ void __launch_bounds__(256)
merge_ln_kernel(const float* __restrict__ x, float* __restrict__ y,
                const float* __restrict__ g, const float* __restrict__ b)
{
    int warp = (blockIdx.x * blockDim.x + threadIdx.x) >> 5;
    int lane = threadIdx.x & 31;
    int bI = warp / 784;
    int r  = warp - bI * 784;
    int i  = r / 28;
    int j  = r - i * 28;
    int grp = lane >> 3;
    int hh  = grp >> 1, ww = grp & 1;
    int d0  = (lane & 7) << 4;
    const float* src =
        x + (((size_t)(bI * 56 + 2 * i + hh)) * 56 + (2 * j + ww)) * 128 + d0;

    float v[16];
#pragma unroll
    for (int t = 0; t < 4; t++) {
        float4 f = ((const float4*)src)[t];
        v[t * 4 + 0] = f.x; v[t * 4 + 1] = f.y; v[t * 4 + 2] = f.z; v[t * 4 + 3] = f.w;
    }
    float s = 0.f;
#pragma unroll
    for (int t = 0; t < 16; t++) s += v[t];
#pragma unroll
    for (int o = 16; o; o >>= 1) s += __shfl_xor_sync(0xffffffffu, s, o);
    float mean = s * (1.0f / 512.0f);
    float q = 0.f;
#pragma unroll
    for (int t = 0; t < 16; t++) { float dd = v[t] - mean; q += dd * dd; }
#pragma unroll
    for (int o = 16; o; o >>= 1) q += __shfl_xor_sync(0xffffffffu, q, o);
    float rstd = rsqrtf(q * (1.0f / 512.0f) + 1e-5f);

    int c0 = lane << 4;
    float* dst = y + (size_t)warp * 512 + c0;
#pragma unroll
    for (int t = 0; t < 4; t++) {
        float4 gg = ((const float4*)(g + c0))[t];
        float4 bb = ((const float4*)(b + c0))[t];
        float4 out;
        out.x = rnd_tf32((v[t * 4 + 0] - mean) * rstd * gg.x + bb.x);
        out.y = rnd_tf32((v[t * 4 + 1] - mean) * rstd * gg.y + bb.y);
        out.z = rnd_tf32((v[t * 4 + 2] - mean) * rstd * gg.z + bb.z);
        out.w = rnd_tf32((v[t * 4 + 3] - mean) * rstd * gg.w + bb.w);
        ((float4*)dst)[t] = out;
    }
}

// ---------------------------------------------------------------------------
extern "C" void kernel_launch(void* const* d_in, const int* in_sizes, int n_in,
                              void* d_out, int out_size)
{
    const float* x       = (const float*)d_in[0];
    const float* ln1_g   = (const float*)d_in[1];
    const float* ln1_b   = (const float*)d_in[2];
    const float* qkv_w   = (const float*)d_in[3];
    const float* qkv_b   = (const float*)d_in[4];
    const float* proj_w  = (const float*)d_in[5];
    const float* proj_b  = (const float*)d_in[6];
    const float* ln2_g   = (const float*)d_in[7];
    const float* ln2_b   = (const float*)d_in[8];
    const float* mlp_w1  = (const float*)d_in[9];
    const float* mlp_b1  = (const float*)d_in[10];
    const float* mlp_w2  = (const float*)d_in[11];
    const float* mlp_b2  = (const float*)d_in[12];
    const float* dsn_g   = (const float*)d_in[13];
    const float* dsn_b   = (const float*)d_in[14];
    const float* ds_w    = (const float*)d_in[15];
    float* out           = (float*)d_out;

    float *gx, *gh, *gq, *go, *ghid, *gds, *gwt;
    cudaGetSymbolAddress((void**)&gx,   g_x);
    cudaGetSymbolAddress((void**)&gh,   g_h);
    cudaGetSymbolAddress((void**)&gq,   g_qkv);
    cudaGetSymbolAddress((void**)&go,   g_o);
    cudaGetSymbolAddress((void**)&ghid, g_hid);
    cudaGetSymbolAddress((void**)&gds,  g_ds);
    cudaGetSymbolAddress((void**)&gwt,  g_wt);

    cudaFuncSetAttribute(gemm_mma<false, false, false>, cudaFuncAttributeMaxDynamicSharedMemorySize, GEMM_SMEM);
    cudaFuncSetAttribute(gemm_mma<false, true, false>,  cudaFuncAttributeMaxDynamicSharedMemorySize, GEMM_SMEM);
    cudaFuncSetAttribute(gemm_mma<true, false, false>,  cudaFuncAttributeMaxDynamicSharedMemorySize, GEMM_SMEM);
    cudaFuncSetAttribute(gemm_mma<false, true, true>,   cudaFuncAttributeMaxDynamicSharedMemorySize, GEMM_SMEM_LN);

    transpose_all<<<524288 / 256, 256>>>(qkv_w, proj_w, mlp_w1, mlp_w2, ds_w, gwt);

    const dim3 attnGrid(4, 4096);   // head fast-moving for L2 reuse

    // ---- layer 0
    ln128_kernel<<<TOK / 8, 256>>>(x, gh, ln1_g, ln1_b);
    gemm_mma<false, false, false><<<dim3(3, TOK / 128), 256, GEMM_SMEM>>>(
        gh, gwt + 0, qkv_b, nullptr, gq, 384, 128, nullptr, nullptr, nullptr);
    attn_kernel<<<attnGrid, 128>>>(gq, go, 0, 0);
    gemm_mma<false, true, true><<<dim3(1, TOK / 128), 256, GEMM_SMEM_LN>>>(
        go, gwt + 98304, proj_b, x, gx, 128, 128, ln2_g, ln2_b, gh);
    gemm_mma<true, false, false><<<dim3(4, TOK / 128), 256, GEMM_SMEM>>>(
        gh, gwt + 131072, mlp_b1, nullptr, ghid, 512, 128, nullptr, nullptr, nullptr);
    gemm_mma<false, true, true><<<dim3(1, TOK / 128), 256, GEMM_SMEM_LN>>>(
        ghid, gwt + 262144, mlp_b2, gx, gx, 128, 512, ln1_g + 128, ln1_b + 128, gh);

    // ---- layer 1 (shifted)
    gemm_mma<false, false, false><<<dim3(3, TOK / 128), 256, GEMM_SMEM>>>(
        gh, gwt + 49152, qkv_b + 384, nullptr, gq, 384, 128, nullptr, nullptr, nullptr);
    attn_kernel<<<attnGrid, 128>>>(gq, go, 3, 1);
    gemm_mma<false, true, true><<<dim3(1, TOK / 128), 256, GEMM_SMEM_LN>>>(
        go, gwt + 98304 + 16384, proj_b + 128, gx, gx, 128, 128, ln2_g + 128, ln2_b + 128, gh);
    gemm_mma<true, false, false><<<dim3(4, TOK / 128), 256, GEMM_SMEM>>>(
        gh, gwt + 131072 + 65536, mlp_b1 + 512, nullptr, ghid, 512, 128, nullptr, nullptr, nullptr);
    gemm_mma<false, true, false><<<dim3(1, TOK / 128), 256, GEMM_SMEM>>>(
        ghid, gwt + 262144 + 65536, mlp_b2 + 128, gx, gx, 128, 512, nullptr, nullptr, nullptr);

    // ---- downsample
    merge_ln_kernel<<<DSTOK / 8, 256>>>(gx, gds, dsn_g, dsn_b);
    gemm_mma<false, false, false><<<dim3(2, DSTOK / 128), 256, GEMM_SMEM>>>(
        gds, gwt + 393216, nullptr, nullptr, out, 256, 512, nullptr, nullptr, nullptr);
}

// round 13
// speedup vs baseline: 1.8268x; 1.0519x over previous
#include <cuda_runtime.h>
#include <cstdint>
#include <math.h>

// ---------------------------------------------------------------------------
// Swin stage on GB300 (compute_103: mma.sync tf32 path).
// R13: in-register softmax in attention (1 barrier, 1 sc pass); R12 GEMMs.
// ---------------------------------------------------------------------------

#define TOK 200704          // 64*56*56
#define DSTOK 50176         // 64*28*28

__device__ float g_x  [(size_t)TOK * 128];
__device__ float g_h  [(size_t)TOK * 128];
__device__ float g_qkv[(size_t)TOK * 384];
__device__ float g_o  [(size_t)TOK * 128];
__device__ float g_hid[(size_t)TOK * 512];
__device__ float g_ds [(size_t)DSTOK * 512];
__device__ float g_wt [524288];   // transposed weights [N,K] K-major, tf32-rounded

__device__ __forceinline__ uint32_t f2tf32(float f) {
    uint32_t u; asm("cvt.rna.tf32.f32 %0, %1;" : "=r"(u) : "f"(f)); return u;
}
__device__ __forceinline__ float rnd_tf32(float f) {
    return __uint_as_float(f2tf32(f));
}
__device__ __forceinline__ uint32_t smem_u32(const void* p) {
    uint32_t a;
    asm("{ .reg .u64 t; cvta.to.shared.u64 t, %1; cvt.u32.u64 %0, t; }" : "=r"(a) : "l"(p));
    return a;
}

#define CP_ASYNC16(dst, src) \
    asm volatile("cp.async.cg.shared.global [%0], [%1], 16;" :: "r"(dst), "l"(src))
#define CP_COMMIT() asm volatile("cp.async.commit_group;" ::: "memory")
#define CP_WAITG(n) asm volatile("cp.async.wait_group %0;" :: "n"(n) : "memory")

#define MMA_TF32(d, a, b) \
    asm volatile("mma.sync.aligned.m16n8k8.row.col.f32.tf32.tf32.f32 " \
        "{%0,%1,%2,%3}, {%4,%5,%6,%7}, {%8,%9}, {%0,%1,%2,%3};" \
        : "+f"((d)[0]), "+f"((d)[1]), "+f"((d)[2]), "+f"((d)[3]) \
        : "r"((a)[0]), "r"((a)[1]), "r"((a)[2]), "r"((a)[3]), \
          "r"((b)[0]), "r"((b)[1]))

#define LDMX4(r0, r1, r2, r3, addr) \
    asm volatile("ldmatrix.sync.aligned.m8n8.x4.shared.b16 {%0,%1,%2,%3}, [%4];" \
        : "=r"(r0), "=r"(r1), "=r"(r2), "=r"(r3) : "r"(addr))
#define LDMX2(r0, r1, addr) \
    asm volatile("ldmatrix.sync.aligned.m8n8.x2.shared.b16 {%0,%1}, [%2];" \
        : "=r"(r0), "=r"(r1) : "r"(addr))

__device__ __forceinline__ float gelu_tanh(float v) {
    float u = 0.7978845608028654f * (v + 0.044715f * v * v * v);
    return 0.5f * v * (1.0f + tanhf(u));
}

// ===================== tf32 mma GEMM, cp.async double-buffered ===============
#define GSTAGE 4608
#define GEMM_SMEM    (2 * 2 * GSTAGE * 4)          // 73728 bytes
#define GEMM_SMEM_LN (GEMM_SMEM + 2 * 128 * 8)     // + float2 part[2][128]

template <bool GELU, bool RES, bool LNOUT>
__global__ void __launch_bounds__(256, 2)
gemm_mma(const float* __restrict__ A, const float* __restrict__ WT,
         const float* __restrict__ bias, const float* __restrict__ R,
         float* __restrict__ C, int N, int K,
         const float* __restrict__ lng, const float* __restrict__ lnb,
         float* __restrict__ C2)
{
    extern __shared__ float sm[];
    const uint32_t sm0 = smem_u32(sm);
    const int tid  = threadIdx.x;
    const int wid  = tid >> 5, lane = tid & 31;
    const int gID  = lane >> 2, tig = lane & 3;
    const int warpM = wid & 3, warpN = wid >> 2;
    const int rowBase = blockIdx.y << 7;
    const int colBase = blockIdx.x << 7;
    const int lr = tid >> 3;
    const int lc = (tid & 7) << 2;

    const float* Ab  = A  + (size_t)(rowBase + lr) * K + lc;
    const float* Wb  = WT + (size_t)(colBase + lr) * K + lc;
    const uint32_t dstA = sm0 + (uint32_t)(lr * 36 + lc) * 4;
    const uint32_t dstB = dstA + GSTAGE * 4;

    const int lane8 = lane & 7, sel = lane >> 3;
    const int aRowF = warpM * 32 + lane8 + ((sel & 1) << 3);
    const int aColF = (sel >> 1) << 2;
    const int bRowF = warpN * 64 + lane8 + ((sel >> 1) << 3);
    const int bColF = (sel & 1) << 2;

    float d[2][8][4];
#pragma unroll
    for (int mi = 0; mi < 2; mi++)
#pragma unroll
        for (int ni = 0; ni < 8; ni++)
#pragma unroll
            for (int e = 0; e < 4; e++) d[mi][ni][e] = 0.f;

    const int nch = K >> 5;

#define ISSUE(c_, s_) do {                                                   \
        const int k0_ = (c_) << 5;                                          \
        const uint32_t so_ = (uint32_t)(s_) * (2 * GSTAGE * 4);             \
        _Pragma("unroll")                                                    \
        for (int i_ = 0; i_ < 4; i_++) {                                     \
            CP_ASYNC16(dstA + so_ + i_ * (32 * 36 * 4),                      \
                       Ab + (size_t)(i_ << 5) * K + k0_);                    \
            CP_ASYNC16(dstB + so_ + i_ * (32 * 36 * 4),                      \
                       Wb + (size_t)(i_ << 5) * K + k0_);                    \
        }                                                                    \
        CP_COMMIT();                                                         \
    } while (0)

    ISSUE(0, 0);
    ISSUE(1, 1);

    for (int c = 0; c < nch; c++) {
        const int s = c & 1;
        if (c == nch - 1) { CP_WAITG(0); } else { CP_WAITG(1); }
        __syncthreads();
        const uint32_t stA = sm0 + (uint32_t)s * (2 * GSTAGE * 4);
        const uint32_t stB = stA + GSTAGE * 4;
        const uint32_t aBase = stA + (uint32_t)(aRowF * 36 + aColF) * 4;
        const uint32_t bBase = stB + (uint32_t)(bRowF * 36 + bColF) * 4;
#pragma unroll
        for (int ks = 0; ks < 4; ks++) {
            const uint32_t kb = (uint32_t)(ks << 5);
            uint32_t af[2][4], bf[8][2];
#pragma unroll
            for (int mi = 0; mi < 2; mi++)
                LDMX4(af[mi][0], af[mi][1], af[mi][2], af[mi][3],
                      aBase + kb + (uint32_t)(mi * 16 * 36 * 4));
#pragma unroll
            for (int p = 0; p < 4; p++)
                LDMX4(bf[2 * p][0], bf[2 * p][1], bf[2 * p + 1][0], bf[2 * p + 1][1],
                      bBase + kb + (uint32_t)(p * 16 * 36 * 4));
#pragma unroll
            for (int mi = 0; mi < 2; mi++)
#pragma unroll
                for (int ni = 0; ni < 8; ni++)
                    MMA_TF32(d[mi][ni], af[mi], bf[ni]);
        }
        __syncthreads();
        if (c + 2 < nch) ISSUE(c + 2, s);
    }
#undef ISSUE

    const int row0 = rowBase + warpM * 32 + gID;
    const int colW = colBase + warpN * 64 + (tig << 1);

    if (!LNOUT) {
#pragma unroll
        for (int ni = 0; ni < 8; ni++) {
            const int col = colW + ni * 8;
            float bx = 0.f, by = 0.f;
            if (bias) { bx = bias[col]; by = bias[col + 1]; }
#pragma unroll
            for (int mi = 0; mi < 2; mi++) {
#pragma unroll
                for (int half = 0; half < 2; half++) {
                    int r = row0 + mi * 16 + half * 8;
                    float vx = d[mi][ni][half * 2 + 0] + bx;
                    float vy = d[mi][ni][half * 2 + 1] + by;
                    if (GELU) { vx = rnd_tf32(gelu_tanh(vx)); vy = rnd_tf32(gelu_tanh(vy)); }
                    size_t off = (size_t)r * N + col;
                    if (RES) {
                        float2 rr = *(const float2*)(R + off);
                        vx += rr.x; vy += rr.y;
                    }
                    float2 o = { vx, vy };
                    *(float2*)(C + off) = o;
                }
            }
        }
    } else {
        float rs[2][2] = {}, rq[2][2] = {};
#pragma unroll
        for (int ni = 0; ni < 8; ni++) {
            const int col = colW + ni * 8;
            float bx = bias[col], by = bias[col + 1];
#pragma unroll
            for (int mi = 0; mi < 2; mi++) {
#pragma unroll
                for (int half = 0; half < 2; half++) {
                    int r = row0 + mi * 16 + half * 8;
                    size_t off = (size_t)r * 128 + col;
                    float2 rr = *(const float2*)(R + off);
                    float vx = d[mi][ni][half * 2 + 0] + bx + rr.x;
                    float vy = d[mi][ni][half * 2 + 1] + by + rr.y;
                    d[mi][ni][half * 2 + 0] = vx;
                    d[mi][ni][half * 2 + 1] = vy;
                    rs[mi][half] += vx + vy;
                    rq[mi][half] += vx * vx + vy * vy;
                }
            }
        }
#pragma unroll
        for (int mi = 0; mi < 2; mi++)
#pragma unroll
            for (int half = 0; half < 2; half++) {
#pragma unroll
                for (int o2 = 1; o2 <= 2; o2 <<= 1) {
                    rs[mi][half] += __shfl_xor_sync(0xffffffffu, rs[mi][half], o2);
                    rq[mi][half] += __shfl_xor_sync(0xffffffffu, rq[mi][half], o2);
                }
            }
        float2* part = (float2*)(sm + 2 * 2 * GSTAGE);
        if (tig == 0) {
#pragma unroll
            for (int mi = 0; mi < 2; mi++)
#pragma unroll
                for (int half = 0; half < 2; half++) {
                    int rl = warpM * 32 + gID + mi * 16 + half * 8;
                    float2 p = { rs[mi][half], rq[mi][half] };
                    part[warpN * 128 + rl] = p;
                }
        }
        __syncthreads();
        float mean_r[2][2], rstd_r[2][2];
#pragma unroll
        for (int mi = 0; mi < 2; mi++)
#pragma unroll
            for (int half = 0; half < 2; half++) {
                int rl = warpM * 32 + gID + mi * 16 + half * 8;
                float2 p0 = part[rl], p1 = part[128 + rl];
                float s = p0.x + p1.x, q = p0.y + p1.y;
                float mean = s * (1.0f / 128.0f);
                float var  = q * (1.0f / 128.0f) - mean * mean;
                mean_r[mi][half] = mean;
                rstd_r[mi][half] = rsqrtf(var + 1e-5f);
            }
#pragma unroll
        for (int ni = 0; ni < 8; ni++) {
            const int col = colW + ni * 8;
            float2 ge = __ldg((const float2*)(lng + col));
            float2 be = __ldg((const float2*)(lnb + col));
#pragma unroll
            for (int mi = 0; mi < 2; mi++) {
#pragma unroll
                for (int half = 0; half < 2; half++) {
                    int r = row0 + mi * 16 + half * 8;
                    size_t off = (size_t)r * 128 + col;
                    float vx = d[mi][ni][half * 2 + 0];
                    float vy = d[mi][ni][half * 2 + 1];
                    float2 o = { vx, vy };
                    *(float2*)(C + off) = o;
                    float m = mean_r[mi][half], rstd = rstd_r[mi][half];
                    float2 h;
                    h.x = rnd_tf32((vx - m) * rstd * ge.x + be.x);
                    h.y = rnd_tf32((vy - m) * rstd * ge.y + be.y);
                    *(float2*)(C2 + off) = h;
                }
            }
        }
    }
}

// ---------------- ONE transpose+round kernel for all weights -----------------
__global__ void transpose_all(const float* __restrict__ qkv_w,
                              const float* __restrict__ proj_w,
                              const float* __restrict__ mlp_w1,
                              const float* __restrict__ mlp_w2,
                              const float* __restrict__ ds_w,
                              float* __restrict__ out)
{
    int i = blockIdx.x * 256 + threadIdx.x;
    const float* in; int K, N, base;
    if (i < 98304)       { base = 0;      in = qkv_w;  K = 128; N = 384; }
    else if (i < 131072) { base = 98304;  in = proj_w; K = 128; N = 128; }
    else if (i < 262144) { base = 131072; in = mlp_w1; K = 128; N = 512; }
    else if (i < 393216) { base = 262144; in = mlp_w2; K = 512; N = 128; }
    else                 { base = 393216; in = ds_w;   K = 512; N = 256; }
    int r = i - base;
    int per = K * N;
    int l = r / per; r -= l * per;
    int n = r / K, k = r - n * K;
    out[i] = __uint_as_float(f2tf32(in[(size_t)l * per + k * N + n]));
}

// ------------------------------ LayerNorm (D=128), one warp per token -------
__global__ void __launch_bounds__(256)
ln128_kernel(const float* __restrict__ in, float* __restrict__ out,
             const float* __restrict__ g, const float* __restrict__ b)
{
    int warp = (blockIdx.x * blockDim.x + threadIdx.x) >> 5;
    int lane = threadIdx.x & 31;
    const float4 v = ((const float4*)(in + (size_t)warp * 128))[lane];
    float s = v.x + v.y + v.z + v.w;
#pragma unroll
    for (int o = 16; o; o >>= 1) s += __shfl_xor_sync(0xffffffffu, s, o);
    float mean = s * (1.0f / 128.0f);
    float dx = v.x - mean, dy = v.y - mean, dz = v.z - mean, dw = v.w - mean;
    float q = dx * dx + dy * dy + dz * dz + dw * dw;
#pragma unroll
    for (int o = 16; o; o >>= 1) q += __shfl_xor_sync(0xffffffffu, q, o);
    float rstd = rsqrtf(q * (1.0f / 128.0f) + 1e-5f);
    float4 gg = ((const float4*)g)[lane];
    float4 bb = ((const float4*)b)[lane];
    float4 r;
    r.x = rnd_tf32(dx * rstd * gg.x + bb.x);
    r.y = rnd_tf32(dy * rstd * gg.y + bb.y);
    r.z = rnd_tf32(dz * rstd * gg.z + bb.z);
    r.w = rnd_tf32(dw * rstd * gg.w + bb.w);
    ((float4*)(out + (size_t)warp * 128))[lane] = r;
}

// ------------------------------ Window attention (tensor-core, reg softmax) --
// Grid (4, 4096). After QK MMA each warp owns its 16 score rows in registers;
// softmax is computed with quad shuffles; one weight store; AV reads only the
// warp's own sc rows -> single block barrier after QK.
__global__ void __launch_bounds__(128)
attn_kernel(const float* __restrict__ qkv, float* __restrict__ o,
            int shift, int use_mask)
{
    __shared__ float buf[4320];        // qs @0 (2304), ks @2304 (2016); sc aliases @0
    __shared__ float vt[32 * 60];
    __shared__ int   tok[64];
    __shared__ int   regn[64];
    float* qs = buf;
    float* ks = buf + 2304;
    float* sc = buf;

    const int tid  = threadIdx.x;
    const int wid  = tid >> 5, lane = tid & 31;
    const int gID  = lane >> 2, tig = lane & 3;
    const int head = blockIdx.x;
    const int bg   = blockIdx.y;
    const int b    = bg >> 6;
    const int g    = bg & 63;
    const int gy   = g >> 3, gx = g & 7;

    const uint32_t bufB = smem_u32(buf);
    const uint32_t ksB  = bufB + 2304 * 4;
    const uint32_t vtB  = smem_u32(vt);
    const int lane8 = lane & 7, sel = lane >> 3;
    const int aRow = wid * 16 + lane8 + ((sel & 1) << 3);
    const int aCol = (sel >> 1) << 2;
    const int bRow = lane8 + ((sel >> 1) << 3);
    const int bCol = (sel & 1) << 2;

    if (tid < 64) {
        regn[tid] = 0;
        if (tid < 49) {
            int wy = tid / 7, wx = tid - (tid / 7) * 7;
            int ph = gy * 7 + wy, pw = gx * 7 + wx;
            int hh = ph + shift; if (hh >= 56) hh -= 56;
            int ww = pw + shift; if (ww >= 56) ww -= 56;
            tok[tid] = b * 3136 + hh * 56 + ww;
            int rh = (ph < 49) ? 0 : ((ph < 53) ? 1 : 2);
            int rw = (pw < 49) ? 0 : ((pw < 53) ? 1 : 2);
            regn[tid] = rh * 3 + rw;
        }
    }
    for (int i = tid; i < 540; i += 128) qs[49 * 36 + i] = 0.f;
    for (int i = tid; i < 252; i += 128) ks[49 * 36 + i] = 0.f;
    for (int i = tid; i < 224; i += 128) {
        int c = i / 7, j = 49 + (i - c * 7);
        vt[c * 60 + j] = 0.f;
    }
    __syncthreads();

    for (int i = tid; i < 49 * 8; i += 128) {
        int r = i >> 3, c4 = (i & 7) << 2;
        const float* base = qkv + (size_t)tok[r] * 384 + head * 32 + c4;
        float4 q4 = *(const float4*)(base);
        float4 k4 = *(const float4*)(base + 128);
        float4 v4 = *(const float4*)(base + 256);
        float4 qr = { rnd_tf32(q4.x), rnd_tf32(q4.y), rnd_tf32(q4.z), rnd_tf32(q4.w) };
        float4 kr = { rnd_tf32(k4.x), rnd_tf32(k4.y), rnd_tf32(k4.z), rnd_tf32(k4.w) };
        *(float4*)&qs[r * 36 + c4] = qr;
        *(float4*)&ks[r * 36 + c4] = kr;
        vt[(c4 + 0) * 60 + r] = rnd_tf32(v4.x);
        vt[(c4 + 1) * 60 + r] = rnd_tf32(v4.y);
        vt[(c4 + 2) * 60 + r] = rnd_tf32(v4.z);
        vt[(c4 + 3) * 60 + r] = rnd_tf32(v4.w);
    }
    __syncthreads();

    const int r0 = wid * 16 + gID;

    // ---- QK^T via ldmatrix (K=32)
    float d[7][4];
#pragma unroll
    for (int ni = 0; ni < 7; ni++)
#pragma unroll
        for (int e = 0; e < 4; e++) d[ni][e] = 0.f;

    {
        const uint32_t aB = bufB + (uint32_t)(aRow * 36 + aCol) * 4;
        const uint32_t bB = ksB + (uint32_t)(bRow * 36 + bCol) * 4;
#pragma unroll
        for (int kstep = 0; kstep < 4; kstep++) {
            const uint32_t kb = (uint32_t)(kstep << 5);
            uint32_t af[4], bf[7][2];
            LDMX4(af[0], af[1], af[2], af[3], aB + kb);
#pragma unroll
            for (int p = 0; p < 3; p++)
                LDMX4(bf[2 * p][0], bf[2 * p][1], bf[2 * p + 1][0], bf[2 * p + 1][1],
                      bB + kb + (uint32_t)(p * 16 * 36 * 4));
            LDMX2(bf[6][0], bf[6][1], bB + kb + (uint32_t)(48 * 36 * 4));
#pragma unroll
            for (int ni = 0; ni < 7; ni++)
                MMA_TF32(d[ni], af, bf[ni]);
        }
    }
    __syncthreads();   // all QK reads of qs/ks complete before sc overlays them

    // ---- in-register softmax: thread owns rows r0, r0+8; cols ni*8+2*tig+{0,1}
    const float scale = 0.17677669529663689f;
    {
        // mask regn for this thread's 14 columns (shared by both rows)
        int rj[7][2];
        if (use_mask) {
#pragma unroll
            for (int ni = 0; ni < 7; ni++) {
                int j0 = ni * 8 + (tig << 1);
                rj[ni][0] = (j0 < 49) ? regn[j0] : -1;
                rj[ni][1] = (j0 + 1 < 49) ? regn[j0 + 1] : -1;
            }
        }
#pragma unroll
        for (int rr = 0; rr < 2; rr++) {
            const int row = r0 + rr * 8;
            const int rgn = use_mask ? regn[row] : 0;
            float m = -1e30f;
#pragma unroll
            for (int ni = 0; ni < 7; ni++) {
#pragma unroll
                for (int e2 = 0; e2 < 2; e2++) {
                    int j = ni * 8 + (tig << 1) + e2;
                    float val;
                    if (j < 49) {
                        val = d[ni][rr * 2 + e2] * scale;
                        if (use_mask && rgn != rj[ni][e2]) val -= 100.f;
                    } else val = -1e30f;
                    d[ni][rr * 2 + e2] = val;
                    m = fmaxf(m, val);
                }
            }
            m = fmaxf(m, __shfl_xor_sync(0xffffffffu, m, 1));
            m = fmaxf(m, __shfl_xor_sync(0xffffffffu, m, 2));
            float sum = 0.f;
#pragma unroll
            for (int ni = 0; ni < 7; ni++) {
#pragma unroll
                for (int e2 = 0; e2 < 2; e2++) {
                    float e = __expf(d[ni][rr * 2 + e2] - m);
                    d[ni][rr * 2 + e2] = e;
                    sum += e;
                }
            }
            sum += __shfl_xor_sync(0xffffffffu, sum, 1);
            sum += __shfl_xor_sync(0xffffffffu, sum, 2);
            float inv = 1.0f / sum;
#pragma unroll
            for (int ni = 0; ni < 7; ni++) {
#pragma unroll
                for (int e2 = 0; e2 < 2; e2++) {
                    int j = ni * 8 + (tig << 1) + e2;
                    sc[row * 60 + j] = rnd_tf32(d[ni][rr * 2 + e2] * inv);
                }
            }
        }
    }
    __syncwarp();   // warp-local: AV A-fragment reads only this warp's sc rows

    // ---- AV via ldmatrix (K=56)
    float d2[4][4];
#pragma unroll
    for (int ni = 0; ni < 4; ni++)
#pragma unroll
        for (int e = 0; e < 4; e++) d2[ni][e] = 0.f;

    {
        const uint32_t aB = bufB + (uint32_t)(aRow * 60 + aCol) * 4;
        const uint32_t bB = vtB + (uint32_t)(bRow * 60 + bCol) * 4;
#pragma unroll
        for (int kstep = 0; kstep < 7; kstep++) {
            const uint32_t kb = (uint32_t)(kstep << 5);
            uint32_t af[4], bf[4][2];
            LDMX4(af[0], af[1], af[2], af[3], aB + kb);
#pragma unroll
            for (int p = 0; p < 2; p++)
                LDMX4(bf[2 * p][0], bf[2 * p][1], bf[2 * p + 1][0], bf[2 * p + 1][1],
                      bB + kb + (uint32_t)(p * 16 * 60 * 4));
#pragma unroll
            for (int ni = 0; ni < 4; ni++)
                MMA_TF32(d2[ni], af, bf[ni]);
        }
    }

#pragma unroll
    for (int ni = 0; ni < 4; ni++) {
#pragma unroll
        for (int e = 0; e < 4; e++) {
            int row = r0 + ((e >= 2) ? 8 : 0);
            if (row < 49) {
                int c = ni * 8 + (tig << 1) + (e & 1);
                o[(size_t)tok[row] * 128 + head * 32 + c] = rnd_tf32(d2[ni][e]);
            }
        }
    }
}

// ------------------------------ 2x2 patch merge + LN(512) -------------------
__global__ void __launch_bounds__(256)
merge_ln_kernel(const float* __restrict__ x, float* __restrict__ y,
                const float* __restrict__ g, const float* __restrict__ b)
{
    int warp = (blockIdx.x * blockDim.x + threadIdx.x) >> 5;
    int lane = threadIdx.x & 31;
    int bI = warp / 784;
    int r  = warp - bI * 784;
    int i  = r / 28;
    int j  = r - i * 28;
    int grp = lane >> 3;
    int hh  = grp >> 1, ww = grp & 1;
    int d0  = (lane & 7) << 4;
    const float* src =
        x + (((size_t)(bI * 56 + 2 * i + hh)) * 56 + (2 * j + ww)) * 128 + d0;

    float v[16];
#pragma unroll
    for (int t = 0; t < 4; t++) {
        float4 f = ((const float4*)src)[t];
        v[t * 4 + 0] = f.x; v[t * 4 + 1] = f.y; v[t * 4 + 2] = f.z; v[t * 4 + 3] = f.w;
    }
    float s = 0.f;
#pragma unroll
    for (int t = 0; t < 16; t++) s += v[t];
#pragma unroll
    for (int o = 16; o; o >>= 1) s += __shfl_xor_sync(0xffffffffu, s, o);
    float mean = s * (1.0f / 512.0f);
    float q = 0.f;
#pragma unroll
    for (int t = 0; t < 16; t++) { float dd = v[t] - mean; q += dd * dd; }
#pragma unroll
    for (int o = 16; o; o >>= 1) q += __shfl_xor_sync(0xffffffffu, q, o);
    float rstd = rsqrtf(q * (1.0f / 512.0f) + 1e-5f);

    int c0 = lane << 4;
    float* dst = y + (size_t)warp * 512 + c0;
#pragma unroll
    for (int t = 0; t < 4; t++) {
        float4 gg = ((const float4*)(g + c0))[t];
        float4 bb = ((const float4*)(b + c0))[t];
        float4 out;
        out.x = rnd_tf32((v[t * 4 + 0] - mean) * rstd * gg.x + bb.x);
        out.y = rnd_tf32((v[t * 4 + 1] - mean) * rstd * gg.y + bb.y);
        out.z = rnd_tf32((v[t * 4 + 2] - mean) * rstd * gg.z + bb.z);
        out.w = rnd_tf32((v[t * 4 + 3] - mean) * rstd * gg.w + bb.w);
        ((float4*)dst)[t] = out;
    }
}

// ---------------------------------------------------------------------------
extern "C" void kernel_launch(void* const* d_in, const int* in_sizes, int n_in,
                              void* d_out, int out_size)
{
    const float* x       = (const float*)d_in[0];
    const float* ln1_g   = (const float*)d_in[1];
    const float* ln1_b   = (const float*)d_in[2];
    const float* qkv_w   = (const float*)d_in[3];
    const float* qkv_b   = (const float*)d_in[4];
    const float* proj_w  = (const float*)d_in[5];
    const float* proj_b  = (const float*)d_in[6];
    const float* ln2_g   = (const float*)d_in[7];
    const float* ln2_b   = (const float*)d_in[8];
    const float* mlp_w1  = (const float*)d_in[9];
    const float* mlp_b1  = (const float*)d_in[10];
    const float* mlp_w2  = (const float*)d_in[11];
    const float* mlp_b2  = (const float*)d_in[12];
    const float* dsn_g   = (const float*)d_in[13];
    const float* dsn_b   = (const float*)d_in[14];
    const float* ds_w    = (const float*)d_in[15];
    float* out           = (float*)d_out;

    float *gx, *gh, *gq, *go, *ghid, *gds, *gwt;
    cudaGetSymbolAddress((void**)&gx,   g_x);
    cudaGetSymbolAddress((void**)&gh,   g_h);
    cudaGetSymbolAddress((void**)&gq,   g_qkv);
    cudaGetSymbolAddress((void**)&go,   g_o);
    cudaGetSymbolAddress((void**)&ghid, g_hid);
    cudaGetSymbolAddress((void**)&gds,  g_ds);
    cudaGetSymbolAddress((void**)&gwt,  g_wt);

    cudaFuncSetAttribute(gemm_mma<false, false, false>, cudaFuncAttributeMaxDynamicSharedMemorySize, GEMM_SMEM);
    cudaFuncSetAttribute(gemm_mma<false, true, false>,  cudaFuncAttributeMaxDynamicSharedMemorySize, GEMM_SMEM);
    cudaFuncSetAttribute(gemm_mma<true, false, false>,  cudaFuncAttributeMaxDynamicSharedMemorySize, GEMM_SMEM);
    cudaFuncSetAttribute(gemm_mma<false, true, true>,   cudaFuncAttributeMaxDynamicSharedMemorySize, GEMM_SMEM_LN);

    transpose_all<<<524288 / 256, 256>>>(qkv_w, proj_w, mlp_w1, mlp_w2, ds_w, gwt);

    const dim3 attnGrid(4, 4096);

    // ---- layer 0
    ln128_kernel<<<TOK / 8, 256>>>(x, gh, ln1_g, ln1_b);
    gemm_mma<false, false, false><<<dim3(3, TOK / 128), 256, GEMM_SMEM>>>(
        gh, gwt + 0, qkv_b, nullptr, gq, 384, 128, nullptr, nullptr, nullptr);
    attn_kernel<<<attnGrid, 128>>>(gq, go, 0, 0);
    gemm_mma<false, true, true><<<dim3(1, TOK / 128), 256, GEMM_SMEM_LN>>>(
        go, gwt + 98304, proj_b, x, gx, 128, 128, ln2_g, ln2_b, gh);
    gemm_mma<true, false, false><<<dim3(4, TOK / 128), 256, GEMM_SMEM>>>(
        gh, gwt + 131072, mlp_b1, nullptr, ghid, 512, 128, nullptr, nullptr, nullptr);
    gemm_mma<false, true, true><<<dim3(1, TOK / 128), 256, GEMM_SMEM_LN>>>(
        ghid, gwt + 262144, mlp_b2, gx, gx, 128, 512, ln1_g + 128, ln1_b + 128, gh);

    // ---- layer 1 (shifted)
    gemm_mma<false, false, false><<<dim3(3, TOK / 128), 256, GEMM_SMEM>>>(
        gh, gwt + 49152, qkv_b + 384, nullptr, gq, 384, 128, nullptr, nullptr, nullptr);
    attn_kernel<<<attnGrid, 128>>>(gq, go, 3, 1);
    gemm_mma<false, true, true><<<dim3(1, TOK / 128), 256, GEMM_SMEM_LN>>>(
        go, gwt + 98304 + 16384, proj_b + 128, gx, gx, 128, 128, ln2_g + 128, ln2_b + 128, gh);
    gemm_mma<true, false, false><<<dim3(4, TOK / 128), 256, GEMM_SMEM>>>(
        gh, gwt + 131072 + 65536, mlp_b1 + 512, nullptr, ghid, 512, 128, nullptr, nullptr, nullptr);
    gemm_mma<false, true, false><<<dim3(1, TOK / 128), 256, GEMM_SMEM>>>(
        ghid, gwt + 262144 + 65536, mlp_b2 + 128, gx, gx, 128, 512, nullptr, nullptr, nullptr);

    // ---- downsample
    merge_ln_kernel<<<DSTOK / 8, 256>>>(gx, gds, dsn_g, dsn_b);
    gemm_mma<false, false, false><<<dim3(2, DSTOK / 128), 256, GEMM_SMEM>>>(
        gds, gwt + 393216, nullptr, nullptr, out, 256, 512, nullptr, nullptr, nullptr);
}

// round 14
// speedup vs baseline: 1.9517x; 1.0684x over previous
#include <cuda_runtime.h>
#include <cstdint>
#include <math.h>

// ---------------------------------------------------------------------------
// Swin stage on GB300 (compute_103: mma.sync tf32 path).
// R14: GEMM smem XOR-swizzle (no padding) + 3-stage cp.async pipeline.
// ---------------------------------------------------------------------------

#define TOK 200704          // 64*56*56
#define DSTOK 50176         // 64*28*28

__device__ float g_x  [(size_t)TOK * 128];
__device__ float g_h  [(size_t)TOK * 128];
__device__ float g_qkv[(size_t)TOK * 384];
__device__ float g_o  [(size_t)TOK * 128];
__device__ float g_hid[(size_t)TOK * 512];
__device__ float g_ds [(size_t)DSTOK * 512];
__device__ float g_wt [524288];   // transposed weights [N,K] K-major, tf32-rounded

__device__ __forceinline__ uint32_t f2tf32(float f) {
    uint32_t u; asm("cvt.rna.tf32.f32 %0, %1;" : "=r"(u) : "f"(f)); return u;
}
__device__ __forceinline__ float rnd_tf32(float f) {
    return __uint_as_float(f2tf32(f));
}
__device__ __forceinline__ uint32_t smem_u32(const void* p) {
    uint32_t a;
    asm("{ .reg .u64 t; cvta.to.shared.u64 t, %1; cvt.u32.u64 %0, t; }" : "=r"(a) : "l"(p));
    return a;
}

#define CP_ASYNC16(dst, src) \
    asm volatile("cp.async.cg.shared.global [%0], [%1], 16;" :: "r"(dst), "l"(src))
#define CP_COMMIT() asm volatile("cp.async.commit_group;" ::: "memory")
#define CP_WAITG(n) asm volatile("cp.async.wait_group %0;" :: "n"(n) : "memory")

#define MMA_TF32(d, a, b) \
    asm volatile("mma.sync.aligned.m16n8k8.row.col.f32.tf32.tf32.f32 " \
        "{%0,%1,%2,%3}, {%4,%5,%6,%7}, {%8,%9}, {%0,%1,%2,%3};" \
        : "+f"((d)[0]), "+f"((d)[1]), "+f"((d)[2]), "+f"((d)[3]) \
        : "r"((a)[0]), "r"((a)[1]), "r"((a)[2]), "r"((a)[3]), \
          "r"((b)[0]), "r"((b)[1]))

#define LDMX4(r0, r1, r2, r3, addr) \
    asm volatile("ldmatrix.sync.aligned.m8n8.x4.shared.b16 {%0,%1,%2,%3}, [%4];" \
        : "=r"(r0), "=r"(r1), "=r"(r2), "=r"(r3) : "r"(addr))
#define LDMX2(r0, r1, addr) \
    asm volatile("ldmatrix.sync.aligned.m8n8.x2.shared.b16 {%0,%1}, [%2];" \
        : "=r"(r0), "=r"(r1) : "r"(addr))

__device__ __forceinline__ float gelu_tanh(float v) {
    float u = 0.7978845608028654f * (v + 0.044715f * v * v * v);
    return 0.5f * v * (1.0f + tanhf(u));
}

// ===================== tf32 mma GEMM, 3-stage cp.async, swizzled smem ========
// Tile rows are 128B (32 floats = 8 x 16B units); unit' = unit ^ (row & 7).
// Conflict-free for cp.async row writes and all ldmatrix 8-row phases.
#define GSTAGE 4096                                   // floats per matrix stage
#define NSTAGE 3
#define GEMM_SMEM    (NSTAGE * 2 * GSTAGE * 4)        // 98304 bytes
#define GEMM_SMEM_LN (GEMM_SMEM + 2 * 128 * 8)        // + float2 part[2][128]

template <bool GELU, bool RES, bool LNOUT>
__global__ void __launch_bounds__(256, 2)
gemm_mma(const float* __restrict__ A, const float* __restrict__ WT,
         const float* __restrict__ bias, const float* __restrict__ R,
         float* __restrict__ C, int N, int K,
         const float* __restrict__ lng, const float* __restrict__ lnb,
         float* __restrict__ C2)
{
    extern __shared__ float sm[];
    const uint32_t sm0 = smem_u32(sm);
    const int tid  = threadIdx.x;
    const int wid  = tid >> 5, lane = tid & 31;
    const int gID  = lane >> 2, tig = lane & 3;
    const int warpM = wid & 3, warpN = wid >> 2;
    const int rowBase = blockIdx.y << 7;
    const int colBase = blockIdx.x << 7;
    const int lr = tid >> 3;            // store row base (0..31)
    const int lu = tid & 7;             // store 16B-unit (0..7)

    const float* Ab  = A  + (size_t)(rowBase + lr) * K + (lu << 2);
    const float* Wb  = WT + (size_t)(colBase + lr) * K + (lu << 2);
    const uint32_t dstA = sm0 + (uint32_t)(lr * 128) + ((uint32_t)(lu ^ (lr & 7)) << 4);
    const uint32_t dstB = dstA + GSTAGE * 4;

    // ldmatrix per-thread components
    const int lane8 = lane & 7, sel = lane >> 3;
    const int aRowF = warpM * 32 + lane8 + ((sel & 1) << 3);
    const int ac2   = sel >> 1;                 // A col unit offset (0/1)
    const int bRowF = warpN * 64 + lane8 + ((sel >> 1) << 3);
    const int bc2   = sel & 1;                  // B col unit offset (0/1)
    const int aSw   = aRowF & 7, bSw = bRowF & 7;

    float d[2][8][4];
#pragma unroll
    for (int mi = 0; mi < 2; mi++)
#pragma unroll
        for (int ni = 0; ni < 8; ni++)
#pragma unroll
            for (int e = 0; e < 4; e++) d[mi][ni][e] = 0.f;

    const int nch = K >> 5;

#define ISSUE(c_, s_) do {                                                   \
        const int k0_ = (c_) << 5;                                          \
        const uint32_t so_ = (uint32_t)(s_) * (2 * GSTAGE * 4);             \
        _Pragma("unroll")                                                    \
        for (int i_ = 0; i_ < 4; i_++) {                                     \
            CP_ASYNC16(dstA + so_ + i_ * 4096,                               \
                       Ab + (size_t)(i_ << 5) * K + k0_);                    \
            CP_ASYNC16(dstB + so_ + i_ * 4096,                               \
                       Wb + (size_t)(i_ << 5) * K + k0_);                    \
        }                                                                    \
        CP_COMMIT();                                                         \
    } while (0)

    ISSUE(0, 0);
    if (nch > 1) ISSUE(1, 1);
    if (nch > 2) ISSUE(2, 2);

    int s = 0;
    for (int c = 0; c < nch; c++) {
        if (c + 3 <= nch)      { CP_WAITG(2); }
        else if (c + 2 == nch) { CP_WAITG(1); }
        else                   { CP_WAITG(0); }
        __syncthreads();
        const uint32_t stA = sm0 + (uint32_t)s * (2 * GSTAGE * 4);
        const uint32_t aBase = stA + (uint32_t)(aRowF * 128);
        const uint32_t bBase = stA + GSTAGE * 4 + (uint32_t)(bRowF * 128);
#pragma unroll
        for (int ks = 0; ks < 4; ks++) {
            const uint32_t uA = (uint32_t)(((ks << 1) + ac2) ^ aSw) << 4;
            const uint32_t uB = (uint32_t)(((ks << 1) + bc2) ^ bSw) << 4;
            uint32_t af[2][4], bf[8][2];
#pragma unroll
            for (int mi = 0; mi < 2; mi++)
                LDMX4(af[mi][0], af[mi][1], af[mi][2], af[mi][3],
                      aBase + uA + (uint32_t)(mi * 2048));
#pragma unroll
            for (int p = 0; p < 4; p++)
                LDMX4(bf[2 * p][0], bf[2 * p][1], bf[2 * p + 1][0], bf[2 * p + 1][1],
                      bBase + uB + (uint32_t)(p * 2048));
#pragma unroll
            for (int mi = 0; mi < 2; mi++)
#pragma unroll
                for (int ni = 0; ni < 8; ni++)
                    MMA_TF32(d[mi][ni], af[mi], bf[ni]);
        }
        __syncthreads();
        if (c + 3 < nch) ISSUE(c + 3, s);
        s = (s == NSTAGE - 1) ? 0 : s + 1;
    }
#undef ISSUE

    const int row0 = rowBase + warpM * 32 + gID;
    const int colW = colBase + warpN * 64 + (tig << 1);

    if (!LNOUT) {
#pragma unroll
        for (int ni = 0; ni < 8; ni++) {
            const int col = colW + ni * 8;
            float bx = 0.f, by = 0.f;
            if (bias) { bx = bias[col]; by = bias[col + 1]; }
#pragma unroll
            for (int mi = 0; mi < 2; mi++) {
#pragma unroll
                for (int half = 0; half < 2; half++) {
                    int r = row0 + mi * 16 + half * 8;
                    float vx = d[mi][ni][half * 2 + 0] + bx;
                    float vy = d[mi][ni][half * 2 + 1] + by;
                    if (GELU) { vx = rnd_tf32(gelu_tanh(vx)); vy = rnd_tf32(gelu_tanh(vy)); }
                    size_t off = (size_t)r * N + col;
                    if (RES) {
                        float2 rr = *(const float2*)(R + off);
                        vx += rr.x; vy += rr.y;
                    }
                    float2 o = { vx, vy };
                    *(float2*)(C + off) = o;
                }
            }
        }
    } else {
        float rs[2][2] = {}, rq[2][2] = {};
#pragma unroll
        for (int ni = 0; ni < 8; ni++) {
            const int col = colW + ni * 8;
            float bx = bias[col], by = bias[col + 1];
#pragma unroll
            for (int mi = 0; mi < 2; mi++) {
#pragma unroll
                for (int half = 0; half < 2; half++) {
                    int r = row0 + mi * 16 + half * 8;
                    size_t off = (size_t)r * 128 + col;
                    float2 rr = *(const float2*)(R + off);
                    float vx = d[mi][ni][half * 2 + 0] + bx + rr.x;
                    float vy = d[mi][ni][half * 2 + 1] + by + rr.y;
                    d[mi][ni][half * 2 + 0] = vx;
                    d[mi][ni][half * 2 + 1] = vy;
                    rs[mi][half] += vx + vy;
                    rq[mi][half] += vx * vx + vy * vy;
                }
            }
        }
#pragma unroll
        for (int mi = 0; mi < 2; mi++)
#pragma unroll
            for (int half = 0; half < 2; half++) {
#pragma unroll
                for (int o2 = 1; o2 <= 2; o2 <<= 1) {
                    rs[mi][half] += __shfl_xor_sync(0xffffffffu, rs[mi][half], o2);
                    rq[mi][half] += __shfl_xor_sync(0xffffffffu, rq[mi][half], o2);
                }
            }
        float2* part = (float2*)(sm + NSTAGE * 2 * GSTAGE);
        if (tig == 0) {
#pragma unroll
            for (int mi = 0; mi < 2; mi++)
#pragma unroll
                for (int half = 0; half < 2; half++) {
                    int rl = warpM * 32 + gID + mi * 16 + half * 8;
                    float2 p = { rs[mi][half], rq[mi][half] };
                    part[warpN * 128 + rl] = p;
                }
        }
        __syncthreads();
        float mean_r[2][2], rstd_r[2][2];
#pragma unroll
        for (int mi = 0; mi < 2; mi++)
#pragma unroll
            for (int half = 0; half < 2; half++) {
                int rl = warpM * 32 + gID + mi * 16 + half * 8;
                float2 p0 = part[rl], p1 = part[128 + rl];
                float s2 = p0.x + p1.x, q = p0.y + p1.y;
                float mean = s2 * (1.0f / 128.0f);
                float var  = q * (1.0f / 128.0f) - mean * mean;
                mean_r[mi][half] = mean;
                rstd_r[mi][half] = rsqrtf(var + 1e-5f);
            }
#pragma unroll
        for (int ni = 0; ni < 8; ni++) {
            const int col = colW + ni * 8;
            float2 ge = __ldg((const float2*)(lng + col));
            float2 be = __ldg((const float2*)(lnb + col));
#pragma unroll
            for (int mi = 0; mi < 2; mi++) {
#pragma unroll
                for (int half = 0; half < 2; half++) {
                    int r = row0 + mi * 16 + half * 8;
                    size_t off = (size_t)r * 128 + col;
                    float vx = d[mi][ni][half * 2 + 0];
                    float vy = d[mi][ni][half * 2 + 1];
                    float2 o = { vx, vy };
                    *(float2*)(C + off) = o;
                    float m = mean_r[mi][half], rstd = rstd_r[mi][half];
                    float2 h;
                    h.x = rnd_tf32((vx - m) * rstd * ge.x + be.x);
                    h.y = rnd_tf32((vy - m) * rstd * ge.y + be.y);
                    *(float2*)(C2 + off) = h;
                }
            }
        }
    }
}

// ---------------- ONE transpose+round kernel for all weights -----------------
__global__ void transpose_all(const float* __restrict__ qkv_w,
                              const float* __restrict__ proj_w,
                              const float* __restrict__ mlp_w1,
                              const float* __restrict__ mlp_w2,
                              const float* __restrict__ ds_w,
                              float* __restrict__ out)
{
    int i = blockIdx.x * 256 + threadIdx.x;
    const float* in; int K, N, base;
    if (i < 98304)       { base = 0;      in = qkv_w;  K = 128; N = 384; }
    else if (i < 131072) { base = 98304;  in = proj_w; K = 128; N = 128; }
    else if (i < 262144) { base = 131072; in = mlp_w1; K = 128; N = 512; }
    else if (i < 393216) { base = 262144; in = mlp_w2; K = 512; N = 128; }
    else                 { base = 393216; in = ds_w;   K = 512; N = 256; }
    int r = i - base;
    int per = K * N;
    int l = r / per; r -= l * per;
    int n = r / K, k = r - n * K;
    out[i] = __uint_as_float(f2tf32(in[(size_t)l * per + k * N + n]));
}

// ------------------------------ LayerNorm (D=128), one warp per token -------
__global__ void __launch_bounds__(256)
ln128_kernel(const float* __restrict__ in, float* __restrict__ out,
             const float* __restrict__ g, const float* __restrict__ b)
{
    int warp = (blockIdx.x * blockDim.x + threadIdx.x) >> 5;
    int lane = threadIdx.x & 31;
    const float4 v = ((const float4*)(in + (size_t)warp * 128))[lane];
    float s = v.x + v.y + v.z + v.w;
#pragma unroll
    for (int o = 16; o; o >>= 1) s += __shfl_xor_sync(0xffffffffu, s, o);
    float mean = s * (1.0f / 128.0f);
    float dx = v.x - mean, dy = v.y - mean, dz = v.z - mean, dw = v.w - mean;
    float q = dx * dx + dy * dy + dz * dz + dw * dw;
#pragma unroll
    for (int o = 16; o; o >>= 1) q += __shfl_xor_sync(0xffffffffu, q, o);
    float rstd = rsqrtf(q * (1.0f / 128.0f) + 1e-5f);
    float4 gg = ((const float4*)g)[lane];
    float4 bb = ((const float4*)b)[lane];
    float4 r;
    r.x = rnd_tf32(dx * rstd * gg.x + bb.x);
    r.y = rnd_tf32(dy * rstd * gg.y + bb.y);
    r.z = rnd_tf32(dz * rstd * gg.z + bb.z);
    r.w = rnd_tf32(dw * rstd * gg.w + bb.w);
    ((float4*)(out + (size_t)warp * 128))[lane] = r;
}

// ------------------------------ Window attention (tensor-core, reg softmax) --
__global__ void __launch_bounds__(128)
attn_kernel(const float* __restrict__ qkv, float* __restrict__ o,
            int shift, int use_mask)
{
    __shared__ float buf[4320];        // qs @0 (2304), ks @2304 (2016); sc aliases @0
    __shared__ float vt[32 * 60];
    __shared__ int   tok[64];
    __shared__ int   regn[64];
    float* qs = buf;
    float* ks = buf + 2304;
    float* sc = buf;

    const int tid  = threadIdx.x;
    const int wid  = tid >> 5, lane = tid & 31;
    const int gID  = lane >> 2, tig = lane & 3;
    const int head = blockIdx.x;
    const int bg   = blockIdx.y;
    const int b    = bg >> 6;
    const int g    = bg & 63;
    const int gy   = g >> 3, gx = g & 7;

    const uint32_t bufB = smem_u32(buf);
    const uint32_t ksB  = bufB + 2304 * 4;
    const uint32_t vtB  = smem_u32(vt);
    const int lane8 = lane & 7, sel = lane >> 3;
    const int aRow = wid * 16 + lane8 + ((sel & 1) << 3);
    const int aCol = (sel >> 1) << 2;
    const int bRow = lane8 + ((sel >> 1) << 3);
    const int bCol = (sel & 1) << 2;

    if (tid < 64) {
        regn[tid] = 0;
        if (tid < 49) {
            int wy = tid / 7, wx = tid - (tid / 7) * 7;
            int ph = gy * 7 + wy, pw = gx * 7 + wx;
            int hh = ph + shift; if (hh >= 56) hh -= 56;
            int ww = pw + shift; if (ww >= 56) ww -= 56;
            tok[tid] = b * 3136 + hh * 56 + ww;
            int rh = (ph < 49) ? 0 : ((ph < 53) ? 1 : 2);
            int rw = (pw < 49) ? 0 : ((pw < 53) ? 1 : 2);
            regn[tid] = rh * 3 + rw;
        }
    }
    for (int i = tid; i < 540; i += 128) qs[49 * 36 + i] = 0.f;
    for (int i = tid; i < 252; i += 128) ks[49 * 36 + i] = 0.f;
    for (int i = tid; i < 224; i += 128) {
        int c = i / 7, j = 49 + (i - c * 7);
        vt[c * 60 + j] = 0.f;
    }
    __syncthreads();

    for (int i = tid; i < 49 * 8; i += 128) {
        int r = i >> 3, c4 = (i & 7) << 2;
        const float* base = qkv + (size_t)tok[r] * 384 + head * 32 + c4;
        float4 q4 = *(const float4*)(base);
        float4 k4 = *(const float4*)(base + 128);
        float4 v4 = *(const float4*)(base + 256);
        float4 qr = { rnd_tf32(q4.x), rnd_tf32(q4.y), rnd_tf32(q4.z), rnd_tf32(q4.w) };
        float4 kr = { rnd_tf32(k4.x), rnd_tf32(k4.y), rnd_tf32(k4.z), rnd_tf32(k4.w) };
        *(float4*)&qs[r * 36 + c4] = qr;
        *(float4*)&ks[r * 36 + c4] = kr;
        vt[(c4 + 0) * 60 + r] = rnd_tf32(v4.x);
        vt[(c4 + 1) * 60 + r] = rnd_tf32(v4.y);
        vt[(c4 + 2) * 60 + r] = rnd_tf32(v4.z);
        vt[(c4 + 3) * 60 + r] = rnd_tf32(v4.w);
    }
    __syncthreads();

    const int r0 = wid * 16 + gID;

    // ---- QK^T via ldmatrix (K=32)
    float d[7][4];
#pragma unroll
    for (int ni = 0; ni < 7; ni++)
#pragma unroll
        for (int e = 0; e < 4; e++) d[ni][e] = 0.f;

    {
        const uint32_t aB = bufB + (uint32_t)(aRow * 36 + aCol) * 4;
        const uint32_t bB = ksB + (uint32_t)(bRow * 36 + bCol) * 4;
#pragma unroll
        for (int kstep = 0; kstep < 4; kstep++) {
            const uint32_t kb = (uint32_t)(kstep << 5);
            uint32_t af[4], bf[7][2];
            LDMX4(af[0], af[1], af[2], af[3], aB + kb);
#pragma unroll
            for (int p = 0; p < 3; p++)
                LDMX4(bf[2 * p][0], bf[2 * p][1], bf[2 * p + 1][0], bf[2 * p + 1][1],
                      bB + kb + (uint32_t)(p * 16 * 36 * 4));
            LDMX2(bf[6][0], bf[6][1], bB + kb + (uint32_t)(48 * 36 * 4));
#pragma unroll
            for (int ni = 0; ni < 7; ni++)
                MMA_TF32(d[ni], af, bf[ni]);
        }
    }
    __syncthreads();   // all QK reads of qs/ks complete before sc overlays them

    // ---- in-register softmax
    const float scale = 0.17677669529663689f;
    {
        int rj[7][2];
        if (use_mask) {
#pragma unroll
            for (int ni = 0; ni < 7; ni++) {
                int j0 = ni * 8 + (tig << 1);
                rj[ni][0] = (j0 < 49) ? regn[j0] : -1;
                rj[ni][1] = (j0 + 1 < 49) ? regn[j0 + 1] : -1;
            }
        }
#pragma unroll
        for (int rr = 0; rr < 2; rr++) {
            const int row = r0 + rr * 8;
            const int rgn = use_mask ? regn[row] : 0;
            float m = -1e30f;
#pragma unroll
            for (int ni = 0; ni < 7; ni++) {
#pragma unroll
                for (int e2 = 0; e2 < 2; e2++) {
                    int j = ni * 8 + (tig << 1) + e2;
                    float val;
                    if (j < 49) {
                        val = d[ni][rr * 2 + e2] * scale;
                        if (use_mask && rgn != rj[ni][e2]) val -= 100.f;
                    } else val = -1e30f;
                    d[ni][rr * 2 + e2] = val;
                    m = fmaxf(m, val);
                }
            }
            m = fmaxf(m, __shfl_xor_sync(0xffffffffu, m, 1));
            m = fmaxf(m, __shfl_xor_sync(0xffffffffu, m, 2));
            float sum = 0.f;
#pragma unroll
            for (int ni = 0; ni < 7; ni++) {
#pragma unroll
                for (int e2 = 0; e2 < 2; e2++) {
                    float e = __expf(d[ni][rr * 2 + e2] - m);
                    d[ni][rr * 2 + e2] = e;
                    sum += e;
                }
            }
            sum += __shfl_xor_sync(0xffffffffu, sum, 1);
            sum += __shfl_xor_sync(0xffffffffu, sum, 2);
            float inv = 1.0f / sum;
#pragma unroll
            for (int ni = 0; ni < 7; ni++) {
#pragma unroll
                for (int e2 = 0; e2 < 2; e2++) {
                    int j = ni * 8 + (tig << 1) + e2;
                    sc[row * 60 + j] = rnd_tf32(d[ni][rr * 2 + e2] * inv);
                }
            }
        }
    }
    __syncwarp();

    // ---- AV via ldmatrix (K=56)
    float d2[4][4];
#pragma unroll
    for (int ni = 0; ni < 4; ni++)
#pragma unroll
        for (int e = 0; e < 4; e++) d2[ni][e] = 0.f;

    {
        const uint32_t aB = bufB + (uint32_t)(aRow * 60 + aCol) * 4;
        const uint32_t bB = vtB + (uint32_t)(bRow * 60 + bCol) * 4;
#pragma unroll
        for (int kstep = 0; kstep < 7; kstep++) {
            const uint32_t kb = (uint32_t)(kstep << 5);
            uint32_t af[4], bf[4][2];
            LDMX4(af[0], af[1], af[2], af[3], aB + kb);
#pragma unroll
            for (int p = 0; p < 2; p++)
                LDMX4(bf[2 * p][0], bf[2 * p][1], bf[2 * p + 1][0], bf[2 * p + 1][1],
                      bB + kb + (uint32_t)(p * 16 * 60 * 4));
#pragma unroll
            for (int ni = 0; ni < 4; ni++)
                MMA_TF32(d2[ni], af, bf[ni]);
        }
    }

#pragma unroll
    for (int ni = 0; ni < 4; ni++) {
#pragma unroll
        for (int e = 0; e < 4; e++) {
            int row = r0 + ((e >= 2) ? 8 : 0);
            if (row < 49) {
                int c = ni * 8 + (tig << 1) + (e & 1);
                o[(size_t)tok[row] * 128 + head * 32 + c] = rnd_tf32(d2[ni][e]);
            }
        }
    }
}

// ------------------------------ 2x2 patch merge + LN(512) -------------------
__global__ void __launch_bounds__(256)
merge_ln_kernel(const float* __restrict__ x, float* __restrict__ y,
                const float* __restrict__ g, const float* __restrict__ b)
{
    int warp = (blockIdx.x * blockDim.x + threadIdx.x) >> 5;
    int lane = threadIdx.x & 31;
    int bI = warp / 784;
    int r  = warp - bI * 784;
    int i  = r / 28;
    int j  = r - i * 28;
    int grp = lane >> 3;
    int hh  = grp >> 1, ww = grp & 1;
    int d0  = (lane & 7) << 4;
    const float* src =
        x + (((size_t)(bI * 56 + 2 * i + hh)) * 56 + (2 * j + ww)) * 128 + d0;

    float v[16];
#pragma unroll
    for (int t = 0; t < 4; t++) {
        float4 f = ((const float4*)src)[t];
        v[t * 4 + 0] = f.x; v[t * 4 + 1] = f.y; v[t * 4 + 2] = f.z; v[t * 4 + 3] = f.w;
    }
    float s = 0.f;
#pragma unroll
    for (int t = 0; t < 16; t++) s += v[t];
#pragma unroll
    for (int o = 16; o; o >>= 1) s += __shfl_xor_sync(0xffffffffu, s, o);
    float mean = s * (1.0f / 512.0f);
    float q = 0.f;
#pragma unroll
    for (int t = 0; t < 16; t++) { float dd = v[t] - mean; q += dd * dd; }
#pragma unroll
    for (int o = 16; o; o >>= 1) q += __shfl_xor_sync(0xffffffffu, q, o);
    float rstd = rsqrtf(q * (1.0f / 512.0f) + 1e-5f);

    int c0 = lane << 4;
    float* dst = y + (size_t)warp * 512 + c0;
#pragma unroll
    for (int t = 0; t < 4; t++) {
        float4 gg = ((const float4*)(g + c0))[t];
        float4 bb = ((const float4*)(b + c0))[t];
        float4 out;
        out.x = rnd_tf32((v[t * 4 + 0] - mean) * rstd * gg.x + bb.x);
        out.y = rnd_tf32((v[t * 4 + 1] - mean) * rstd * gg.y + bb.y);
        out.z = rnd_tf32((v[t * 4 + 2] - mean) * rstd * gg.z + bb.z);
        out.w = rnd_tf32((v[t * 4 + 3] - mean) * rstd * gg.w + bb.w);
        ((float4*)dst)[t] = out;
    }
}

// ---------------------------------------------------------------------------
extern "C" void kernel_launch(void* const* d_in, const int* in_sizes, int n_in,
                              void* d_out, int out_size)
{
    const float* x       = (const float*)d_in[0];
    const float* ln1_g   = (const float*)d_in[1];
    const float* ln1_b   = (const float*)d_in[2];
    const float* qkv_w   = (const float*)d_in[3];
    const float* qkv_b   = (const float*)d_in[4];
    const float* proj_w  = (const float*)d_in[5];
    const float* proj_b  = (const float*)d_in[6];
    const float* ln2_g   = (const float*)d_in[7];
    const float* ln2_b   = (const float*)d_in[8];
    const float* mlp_w1  = (const float*)d_in[9];
    const float* mlp_b1  = (const float*)d_in[10];
    const float* mlp_w2  = (const float*)d_in[11];
    const float* mlp_b2  = (const float*)d_in[12];
    const float* dsn_g   = (const float*)d_in[13];
    const float* dsn_b   = (const float*)d_in[14];
    const float* ds_w    = (const float*)d_in[15];
    float* out           = (float*)d_out;

    float *gx, *gh, *gq, *go, *ghid, *gds, *gwt;
    cudaGetSymbolAddress((void**)&gx,   g_x);
    cudaGetSymbolAddress((void**)&gh,   g_h);
    cudaGetSymbolAddress((void**)&gq,   g_qkv);
    cudaGetSymbolAddress((void**)&go,   g_o);
    cudaGetSymbolAddress((void**)&ghid, g_hid);
    cudaGetSymbolAddress((void**)&gds,  g_ds);
    cudaGetSymbolAddress((void**)&gwt,  g_wt);

    cudaFuncSetAttribute(gemm_mma<false, false, false>, cudaFuncAttributeMaxDynamicSharedMemorySize, GEMM_SMEM);
    cudaFuncSetAttribute(gemm_mma<false, true, false>,  cudaFuncAttributeMaxDynamicSharedMemorySize, GEMM_SMEM);
    cudaFuncSetAttribute(gemm_mma<true, false, false>,  cudaFuncAttributeMaxDynamicSharedMemorySize, GEMM_SMEM);
    cudaFuncSetAttribute(gemm_mma<false, true, true>,   cudaFuncAttributeMaxDynamicSharedMemorySize, GEMM_SMEM_LN);

    transpose_all<<<524288 / 256, 256>>>(qkv_w, proj_w, mlp_w1, mlp_w2, ds_w, gwt);

    const dim3 attnGrid(4, 4096);

    // ---- layer 0
    ln128_kernel<<<TOK / 8, 256>>>(x, gh, ln1_g, ln1_b);
    gemm_mma<false, false, false><<<dim3(3, TOK / 128), 256, GEMM_SMEM>>>(
        gh, gwt + 0, qkv_b, nullptr, gq, 384, 128, nullptr, nullptr, nullptr);
    attn_kernel<<<attnGrid, 128>>>(gq, go, 0, 0);
    gemm_mma<false, true, true><<<dim3(1, TOK / 128), 256, GEMM_SMEM_LN>>>(
        go, gwt + 98304, proj_b, x, gx, 128, 128, ln2_g, ln2_b, gh);
    gemm_mma<true, false, false><<<dim3(4, TOK / 128), 256, GEMM_SMEM>>>(
        gh, gwt + 131072, mlp_b1, nullptr, ghid, 512, 128, nullptr, nullptr, nullptr);
    gemm_mma<false, true, true><<<dim3(1, TOK / 128), 256, GEMM_SMEM_LN>>>(
        ghid, gwt + 262144, mlp_b2, gx, gx, 128, 512, ln1_g + 128, ln1_b + 128, gh);

    // ---- layer 1 (shifted)
    gemm_mma<false, false, false><<<dim3(3, TOK / 128), 256, GEMM_SMEM>>>(
        gh, gwt + 49152, qkv_b + 384, nullptr, gq, 384, 128, nullptr, nullptr, nullptr);
    attn_kernel<<<attnGrid, 128>>>(gq, go, 3, 1);
    gemm_mma<false, true, true><<<dim3(1, TOK / 128), 256, GEMM_SMEM_LN>>>(
        go, gwt + 98304 + 16384, proj_b + 128, gx, gx, 128, 128, ln2_g + 128, ln2_b + 128, gh);
    gemm_mma<true, false, false><<<dim3(4, TOK / 128), 256, GEMM_SMEM>>>(
        gh, gwt + 131072 + 65536, mlp_b1 + 512, nullptr, ghid, 512, 128, nullptr, nullptr, nullptr);
    gemm_mma<false, true, false><<<dim3(1, TOK / 128), 256, GEMM_SMEM>>>(
        ghid, gwt + 262144 + 65536, mlp_b2 + 128, gx, gx, 128, 512, nullptr, nullptr, nullptr);

    // ---- downsample
    merge_ln_kernel<<<DSTOK / 8, 256>>>(gx, gds, dsn_g, dsn_b);
    gemm_mma<false, false, false><<<dim3(2, DSTOK / 128), 256, GEMM_SMEM>>>(
        gds, gwt + 393216, nullptr, nullptr, out, 256, 512, nullptr, nullptr, nullptr);
}

// round 15
// speedup vs baseline: 1.9854x; 1.0173x over previous
#include <cuda_runtime.h>
#include <cstdint>
#include <math.h>

// ---------------------------------------------------------------------------
// Swin stage on GB300 (compute_103: mma.sync tf32 path).
// R15: single-barrier GEMM mainloop (issue into just-freed stage after the
//      pre-compute barrier); R14 swizzled 3-stage pipeline otherwise.
// ---------------------------------------------------------------------------

#define TOK 200704          // 64*56*56
#define DSTOK 50176         // 64*28*28

__device__ float g_x  [(size_t)TOK * 128];
__device__ float g_h  [(size_t)TOK * 128];
__device__ float g_qkv[(size_t)TOK * 384];
__device__ float g_o  [(size_t)TOK * 128];
__device__ float g_hid[(size_t)TOK * 512];
__device__ float g_ds [(size_t)DSTOK * 512];
__device__ float g_wt [524288];   // transposed weights [N,K] K-major, tf32-rounded

__device__ __forceinline__ uint32_t f2tf32(float f) {
    uint32_t u; asm("cvt.rna.tf32.f32 %0, %1;" : "=r"(u) : "f"(f)); return u;
}
__device__ __forceinline__ float rnd_tf32(float f) {
    return __uint_as_float(f2tf32(f));
}
__device__ __forceinline__ uint32_t smem_u32(const void* p) {
    uint32_t a;
    asm("{ .reg .u64 t; cvta.to.shared.u64 t, %1; cvt.u32.u64 %0, t; }" : "=r"(a) : "l"(p));
    return a;
}

#define CP_ASYNC16(dst, src) \
    asm volatile("cp.async.cg.shared.global [%0], [%1], 16;" :: "r"(dst), "l"(src))
#define CP_COMMIT() asm volatile("cp.async.commit_group;" ::: "memory")
#define CP_WAITG(n) asm volatile("cp.async.wait_group %0;" :: "n"(n) : "memory")

#define MMA_TF32(d, a, b) \
    asm volatile("mma.sync.aligned.m16n8k8.row.col.f32.tf32.tf32.f32 " \
        "{%0,%1,%2,%3}, {%4,%5,%6,%7}, {%8,%9}, {%0,%1,%2,%3};" \
        : "+f"((d)[0]), "+f"((d)[1]), "+f"((d)[2]), "+f"((d)[3]) \
        : "r"((a)[0]), "r"((a)[1]), "r"((a)[2]), "r"((a)[3]), \
          "r"((b)[0]), "r"((b)[1]))

#define LDMX4(r0, r1, r2, r3, addr) \
    asm volatile("ldmatrix.sync.aligned.m8n8.x4.shared.b16 {%0,%1,%2,%3}, [%4];" \
        : "=r"(r0), "=r"(r1), "=r"(r2), "=r"(r3) : "r"(addr))
#define LDMX2(r0, r1, addr) \
    asm volatile("ldmatrix.sync.aligned.m8n8.x2.shared.b16 {%0,%1}, [%2];" \
        : "=r"(r0), "=r"(r1) : "r"(addr))

__device__ __forceinline__ float gelu_tanh(float v) {
    float u = 0.7978845608028654f * (v + 0.044715f * v * v * v);
    return 0.5f * v * (1.0f + tanhf(u));
}

// ===================== tf32 mma GEMM, 3-stage cp.async, swizzled smem ========
// unit' = unit ^ (row & 7); one block barrier per K-chunk.
#define GSTAGE 4096                                   // floats per matrix stage
#define NSTAGE 3
#define GEMM_SMEM    (NSTAGE * 2 * GSTAGE * 4)        // 98304 bytes
#define GEMM_SMEM_LN (GEMM_SMEM + 2 * 128 * 8)        // + float2 part[2][128]

template <bool GELU, bool RES, bool LNOUT>
__global__ void __launch_bounds__(256, 2)
gemm_mma(const float* __restrict__ A, const float* __restrict__ WT,
         const float* __restrict__ bias, const float* __restrict__ R,
         float* __restrict__ C, int N, int K,
         const float* __restrict__ lng, const float* __restrict__ lnb,
         float* __restrict__ C2)
{
    extern __shared__ float sm[];
    const uint32_t sm0 = smem_u32(sm);
    const int tid  = threadIdx.x;
    const int wid  = tid >> 5, lane = tid & 31;
    const int gID  = lane >> 2, tig = lane & 3;
    const int warpM = wid & 3, warpN = wid >> 2;
    const int rowBase = blockIdx.y << 7;
    const int colBase = blockIdx.x << 7;
    const int lr = tid >> 3;            // store row base (0..31)
    const int lu = tid & 7;             // store 16B-unit (0..7)

    const float* Ab  = A  + (size_t)(rowBase + lr) * K + (lu << 2);
    const float* Wb  = WT + (size_t)(colBase + lr) * K + (lu << 2);
    const uint32_t dstA = sm0 + (uint32_t)(lr * 128) + ((uint32_t)(lu ^ (lr & 7)) << 4);
    const uint32_t dstB = dstA + GSTAGE * 4;

    const int lane8 = lane & 7, sel = lane >> 3;
    const int aRowF = warpM * 32 + lane8 + ((sel & 1) << 3);
    const int ac2   = sel >> 1;
    const int bRowF = warpN * 64 + lane8 + ((sel >> 1) << 3);
    const int bc2   = sel & 1;
    const int aSw   = aRowF & 7, bSw = bRowF & 7;

    float d[2][8][4];
#pragma unroll
    for (int mi = 0; mi < 2; mi++)
#pragma unroll
        for (int ni = 0; ni < 8; ni++)
#pragma unroll
            for (int e = 0; e < 4; e++) d[mi][ni][e] = 0.f;

    const int nch = K >> 5;

#define ISSUE(c_, s_) do {                                                   \
        const int k0_ = (c_) << 5;                                          \
        const uint32_t so_ = (uint32_t)(s_) * (2 * GSTAGE * 4);             \
        _Pragma("unroll")                                                    \
        for (int i_ = 0; i_ < 4; i_++) {                                     \
            CP_ASYNC16(dstA + so_ + i_ * 4096,                               \
                       Ab + (size_t)(i_ << 5) * K + k0_);                    \
            CP_ASYNC16(dstB + so_ + i_ * 4096,                               \
                       Wb + (size_t)(i_ << 5) * K + k0_);                    \
        }                                                                    \
        CP_COMMIT();                                                         \
    } while (0)

    ISSUE(0, 0);
    ISSUE(1, 1);       // nch >= 4 always (K multiple of 128)

    int s = 0, sNext = 2;   // stage for the next in-loop issue (chunk c+2)
    for (int c = 0; c < nch; c++) {
        if (c == nch - 1) { CP_WAITG(0); } else { CP_WAITG(1); }
        __syncthreads();   // all warps done with stage (c-1)%3 -> safe to refill
        if (c + 2 < nch) {
            ISSUE(c + 2, sNext);
            sNext = (sNext == NSTAGE - 1) ? 0 : sNext + 1;
        }
        const uint32_t stA = sm0 + (uint32_t)s * (2 * GSTAGE * 4);
        const uint32_t aBase = stA + (uint32_t)(aRowF * 128);
        const uint32_t bBase = stA + GSTAGE * 4 + (uint32_t)(bRowF * 128);
#pragma unroll
        for (int ks = 0; ks < 4; ks++) {
            const uint32_t uA = (uint32_t)(((ks << 1) + ac2) ^ aSw) << 4;
            const uint32_t uB = (uint32_t)(((ks << 1) + bc2) ^ bSw) << 4;
            uint32_t af[2][4], bf[8][2];
#pragma unroll
            for (int mi = 0; mi < 2; mi++)
                LDMX4(af[mi][0], af[mi][1], af[mi][2], af[mi][3],
                      aBase + uA + (uint32_t)(mi * 2048));
#pragma unroll
            for (int p = 0; p < 4; p++)
                LDMX4(bf[2 * p][0], bf[2 * p][1], bf[2 * p + 1][0], bf[2 * p + 1][1],
                      bBase + uB + (uint32_t)(p * 2048));
#pragma unroll
            for (int mi = 0; mi < 2; mi++)
#pragma unroll
                for (int ni = 0; ni < 8; ni++)
                    MMA_TF32(d[mi][ni], af[mi], bf[ni]);
        }
        s = (s == NSTAGE - 1) ? 0 : s + 1;
    }
#undef ISSUE

    const int row0 = rowBase + warpM * 32 + gID;
    const int colW = colBase + warpN * 64 + (tig << 1);

    if (!LNOUT) {
#pragma unroll
        for (int ni = 0; ni < 8; ni++) {
            const int col = colW + ni * 8;
            float bx = 0.f, by = 0.f;
            if (bias) { bx = bias[col]; by = bias[col + 1]; }
#pragma unroll
            for (int mi = 0; mi < 2; mi++) {
#pragma unroll
                for (int half = 0; half < 2; half++) {
                    int r = row0 + mi * 16 + half * 8;
                    float vx = d[mi][ni][half * 2 + 0] + bx;
                    float vy = d[mi][ni][half * 2 + 1] + by;
                    if (GELU) { vx = rnd_tf32(gelu_tanh(vx)); vy = rnd_tf32(gelu_tanh(vy)); }
                    size_t off = (size_t)r * N + col;
                    if (RES) {
                        float2 rr = *(const float2*)(R + off);
                        vx += rr.x; vy += rr.y;
                    }
                    float2 o = { vx, vy };
                    *(float2*)(C + off) = o;
                }
            }
        }
    } else {
        float rs[2][2] = {}, rq[2][2] = {};
#pragma unroll
        for (int ni = 0; ni < 8; ni++) {
            const int col = colW + ni * 8;
            float bx = bias[col], by = bias[col + 1];
#pragma unroll
            for (int mi = 0; mi < 2; mi++) {
#pragma unroll
                for (int half = 0; half < 2; half++) {
                    int r = row0 + mi * 16 + half * 8;
                    size_t off = (size_t)r * 128 + col;
                    float2 rr = *(const float2*)(R + off);
                    float vx = d[mi][ni][half * 2 + 0] + bx + rr.x;
                    float vy = d[mi][ni][half * 2 + 1] + by + rr.y;
                    d[mi][ni][half * 2 + 0] = vx;
                    d[mi][ni][half * 2 + 1] = vy;
                    rs[mi][half] += vx + vy;
                    rq[mi][half] += vx * vx + vy * vy;
                }
            }
        }
#pragma unroll
        for (int mi = 0; mi < 2; mi++)
#pragma unroll
            for (int half = 0; half < 2; half++) {
#pragma unroll
                for (int o2 = 1; o2 <= 2; o2 <<= 1) {
                    rs[mi][half] += __shfl_xor_sync(0xffffffffu, rs[mi][half], o2);
                    rq[mi][half] += __shfl_xor_sync(0xffffffffu, rq[mi][half], o2);
                }
            }
        float2* part = (float2*)(sm + NSTAGE * 2 * GSTAGE);
        __syncthreads();   // mainloop stage reads done before part overlays nothing; orders warps
        if (tig == 0) {
#pragma unroll
            for (int mi = 0; mi < 2; mi++)
#pragma unroll
                for (int half = 0; half < 2; half++) {
                    int rl = warpM * 32 + gID + mi * 16 + half * 8;
                    float2 p = { rs[mi][half], rq[mi][half] };
                    part[warpN * 128 + rl] = p;
                }
        }
        __syncthreads();
        float mean_r[2][2], rstd_r[2][2];
#pragma unroll
        for (int mi = 0; mi < 2; mi++)
#pragma unroll
            for (int half = 0; half < 2; half++) {
                int rl = warpM * 32 + gID + mi * 16 + half * 8;
                float2 p0 = part[rl], p1 = part[128 + rl];
                float s2 = p0.x + p1.x, q = p0.y + p1.y;
                float mean = s2 * (1.0f / 128.0f);
                float var  = q * (1.0f / 128.0f) - mean * mean;
                mean_r[mi][half] = mean;
                rstd_r[mi][half] = rsqrtf(var + 1e-5f);
            }
#pragma unroll
        for (int ni = 0; ni < 8; ni++) {
            const int col = colW + ni * 8;
            float2 ge = __ldg((const float2*)(lng + col));
            float2 be = __ldg((const float2*)(lnb + col));
#pragma unroll
            for (int mi = 0; mi < 2; mi++) {
#pragma unroll
                for (int half = 0; half < 2; half++) {
                    int r = row0 + mi * 16 + half * 8;
                    size_t off = (size_t)r * 128 + col;
                    float vx = d[mi][ni][half * 2 + 0];
                    float vy = d[mi][ni][half * 2 + 1];
                    float2 o = { vx, vy };
                    *(float2*)(C + off) = o;
                    float m = mean_r[mi][half], rstd = rstd_r[mi][half];
                    float2 h;
                    h.x = rnd_tf32((vx - m) * rstd * ge.x + be.x);
                    h.y = rnd_tf32((vy - m) * rstd * ge.y + be.y);
                    *(float2*)(C2 + off) = h;
                }
            }
        }
    }
}

// ---------------- ONE transpose+round kernel for all weights -----------------
__global__ void transpose_all(const float* __restrict__ qkv_w,
                              const float* __restrict__ proj_w,
                              const float* __restrict__ mlp_w1,
                              const float* __restrict__ mlp_w2,
                              const float* __restrict__ ds_w,
                              float* __restrict__ out)
{
    int i = blockIdx.x * 256 + threadIdx.x;
    const float* in; int K, N, base;
    if (i < 98304)       { base = 0;      in = qkv_w;  K = 128; N = 384; }
    else if (i < 131072) { base = 98304;  in = proj_w; K = 128; N = 128; }
    else if (i < 262144) { base = 131072; in = mlp_w1; K = 128; N = 512; }
    else if (i < 393216) { base = 262144; in = mlp_w2; K = 512; N = 128; }
    else                 { base = 393216; in = ds_w;   K = 512; N = 256; }
    int r = i - base;
    int per = K * N;
    int l = r / per; r -= l * per;
    int n = r / K, k = r - n * K;
    out[i] = __uint_as_float(f2tf32(in[(size_t)l * per + k * N + n]));
}

// ------------------------------ LayerNorm (D=128), one warp per token -------
__global__ void __launch_bounds__(256)
ln128_kernel(const float* __restrict__ in, float* __restrict__ out,
             const float* __restrict__ g, const float* __restrict__ b)
{
    int warp = (blockIdx.x * blockDim.x + threadIdx.x) >> 5;
    int lane = threadIdx.x & 31;
    const float4 v = ((const float4*)(in + (size_t)warp * 128))[lane];
    float s = v.x + v.y + v.z + v.w;
#pragma unroll
    for (int o = 16; o; o >>= 1) s += __shfl_xor_sync(0xffffffffu, s, o);
    float mean = s * (1.0f / 128.0f);
    float dx = v.x - mean, dy = v.y - mean, dz = v.z - mean, dw = v.w - mean;
    float q = dx * dx + dy * dy + dz * dz + dw * dw;
#pragma unroll
    for (int o = 16; o; o >>= 1) q += __shfl_xor_sync(0xffffffffu, q, o);
    float rstd = rsqrtf(q * (1.0f / 128.0f) + 1e-5f);
    float4 gg = ((const float4*)g)[lane];
    float4 bb = ((const float4*)b)[lane];
    float4 r;
    r.x = rnd_tf32(dx * rstd * gg.x + bb.x);
    r.y = rnd_tf32(dy * rstd * gg.y + bb.y);
    r.z = rnd_tf32(dz * rstd * gg.z + bb.z);
    r.w = rnd_tf32(dw * rstd * gg.w + bb.w);
    ((float4*)(out + (size_t)warp * 128))[lane] = r;
}

// ------------------------------ Window attention (tensor-core, reg softmax) --
__global__ void __launch_bounds__(128)
attn_kernel(const float* __restrict__ qkv, float* __restrict__ o,
            int shift, int use_mask)
{
    __shared__ float buf[4320];        // qs @0 (2304), ks @2304 (2016); sc aliases @0
    __shared__ float vt[32 * 60];
    __shared__ int   tok[64];
    __shared__ int   regn[64];
    float* qs = buf;
    float* ks = buf + 2304;
    float* sc = buf;

    const int tid  = threadIdx.x;
    const int wid  = tid >> 5, lane = tid & 31;
    const int gID  = lane >> 2, tig = lane & 3;
    const int head = blockIdx.x;
    const int bg   = blockIdx.y;
    const int b    = bg >> 6;
    const int g    = bg & 63;
    const int gy   = g >> 3, gx = g & 7;

    const uint32_t bufB = smem_u32(buf);
    const uint32_t ksB  = bufB + 2304 * 4;
    const uint32_t vtB  = smem_u32(vt);
    const int lane8 = lane & 7, sel = lane >> 3;
    const int aRow = wid * 16 + lane8 + ((sel & 1) << 3);
    const int aCol = (sel >> 1) << 2;
    const int bRow = lane8 + ((sel >> 1) << 3);
    const int bCol = (sel & 1) << 2;

    if (tid < 64) {
        regn[tid] = 0;
        if (tid < 49) {
            int wy = tid / 7, wx = tid - (tid / 7) * 7;
            int ph = gy * 7 + wy, pw = gx * 7 + wx;
            int hh = ph + shift; if (hh >= 56) hh -= 56;
            int ww = pw + shift; if (ww >= 56) ww -= 56;
            tok[tid] = b * 3136 + hh * 56 + ww;
            int rh = (ph < 49) ? 0 : ((ph < 53) ? 1 : 2);
            int rw = (pw < 49) ? 0 : ((pw < 53) ? 1 : 2);
            regn[tid] = rh * 3 + rw;
        }
    }
    for (int i = tid; i < 540; i += 128) qs[49 * 36 + i] = 0.f;
    for (int i = tid; i < 252; i += 128) ks[49 * 36 + i] = 0.f;
    for (int i = tid; i < 224; i += 128) {
        int c = i / 7, j = 49 + (i - c * 7);
        vt[c * 60 + j] = 0.f;
    }
    __syncthreads();

    for (int i = tid; i < 49 * 8; i += 128) {
        int r = i >> 3, c4 = (i & 7) << 2;
        const float* base = qkv + (size_t)tok[r] * 384 + head * 32 + c4;
        float4 q4 = *(const float4*)(base);
        float4 k4 = *(const float4*)(base + 128);
        float4 v4 = *(const float4*)(base + 256);
        float4 qr = { rnd_tf32(q4.x), rnd_tf32(q4.y), rnd_tf32(q4.z), rnd_tf32(q4.w) };
        float4 kr = { rnd_tf32(k4.x), rnd_tf32(k4.y), rnd_tf32(k4.z), rnd_tf32(k4.w) };
        *(float4*)&qs[r * 36 + c4] = qr;
        *(float4*)&ks[r * 36 + c4] = kr;
        vt[(c4 + 0) * 60 + r] = rnd_tf32(v4.x);
        vt[(c4 + 1) * 60 + r] = rnd_tf32(v4.y);
        vt[(c4 + 2) * 60 + r] = rnd_tf32(v4.z);
        vt[(c4 + 3) * 60 + r] = rnd_tf32(v4.w);
    }
    __syncthreads();

    const int r0 = wid * 16 + gID;

    // ---- QK^T via ldmatrix (K=32)
    float d[7][4];
#pragma unroll
    for (int ni = 0; ni < 7; ni++)
#pragma unroll
        for (int e = 0; e < 4; e++) d[ni][e] = 0.f;

    {
        const uint32_t aB = bufB + (uint32_t)(aRow * 36 + aCol) * 4;
        const uint32_t bB = ksB + (uint32_t)(bRow * 36 + bCol) * 4;
#pragma unroll
        for (int kstep = 0; kstep < 4; kstep++) {
            const uint32_t kb = (uint32_t)(kstep << 5);
            uint32_t af[4], bf[7][2];
            LDMX4(af[0], af[1], af[2], af[3], aB + kb);
#pragma unroll
            for (int p = 0; p < 3; p++)
                LDMX4(bf[2 * p][0], bf[2 * p][1], bf[2 * p + 1][0], bf[2 * p + 1][1],
                      bB + kb + (uint32_t)(p * 16 * 36 * 4));
            LDMX2(bf[6][0], bf[6][1], bB + kb + (uint32_t)(48 * 36 * 4));
#pragma unroll
            for (int ni = 0; ni < 7; ni++)
                MMA_TF32(d[ni], af, bf[ni]);
        }
    }
    __syncthreads();

    // ---- in-register softmax
    const float scale = 0.17677669529663689f;
    {
        int rj[7][2];
        if (use_mask) {
#pragma unroll
            for (int ni = 0; ni < 7; ni++) {
                int j0 = ni * 8 + (tig << 1);
                rj[ni][0] = (j0 < 49) ? regn[j0] : -1;
                rj[ni][1] = (j0 + 1 < 49) ? regn[j0 + 1] : -1;
            }
        }
#pragma unroll
        for (int rr = 0; rr < 2; rr++) {
            const int row = r0 + rr * 8;
            const int rgn = use_mask ? regn[row] : 0;
            float m = -1e30f;
#pragma unroll
            for (int ni = 0; ni < 7; ni++) {
#pragma unroll
                for (int e2 = 0; e2 < 2; e2++) {
                    int j = ni * 8 + (tig << 1) + e2;
                    float val;
                    if (j < 49) {
                        val = d[ni][rr * 2 + e2] * scale;
                        if (use_mask && rgn != rj[ni][e2]) val -= 100.f;
                    } else val = -1e30f;
                    d[ni][rr * 2 + e2] = val;
                    m = fmaxf(m, val);
                }
            }
            m = fmaxf(m, __shfl_xor_sync(0xffffffffu, m, 1));
            m = fmaxf(m, __shfl_xor_sync(0xffffffffu, m, 2));
            float sum = 0.f;
#pragma unroll
            for (int ni = 0; ni < 7; ni++) {
#pragma unroll
                for (int e2 = 0; e2 < 2; e2++) {
                    float e = __expf(d[ni][rr * 2 + e2] - m);
                    d[ni][rr * 2 + e2] = e;
                    sum += e;
                }
            }
            sum += __shfl_xor_sync(0xffffffffu, sum, 1);
            sum += __shfl_xor_sync(0xffffffffu, sum, 2);
            float inv = 1.0f / sum;
#pragma unroll
            for (int ni = 0; ni < 7; ni++) {
#pragma unroll
                for (int e2 = 0; e2 < 2; e2++) {
                    int j = ni * 8 + (tig << 1) + e2;
                    sc[row * 60 + j] = rnd_tf32(d[ni][rr * 2 + e2] * inv);
                }
            }
        }
    }
    __syncwarp();

    // ---- AV via ldmatrix (K=56)
    float d2[4][4];
#pragma unroll
    for (int ni = 0; ni < 4; ni++)
#pragma unroll
        for (int e = 0; e < 4; e++) d2[ni][e] = 0.f;

    {
        const uint32_t aB = bufB + (uint32_t)(aRow * 60 + aCol) * 4;
        const uint32_t bB = vtB + (uint32_t)(bRow * 60 + bCol) * 4;
#pragma unroll
        for (int kstep = 0; kstep < 7; kstep++) {
            const uint32_t kb = (uint32_t)(kstep << 5);
            uint32_t af[4], bf[4][2];
            LDMX4(af[0], af[1], af[2], af[3], aB + kb);
#pragma unroll
            for (int p = 0; p < 2; p++)
                LDMX4(bf[2 * p][0], bf[2 * p][1], bf[2 * p + 1][0], bf[2 * p + 1][1],
                      bB + kb + (uint32_t)(p * 16 * 60 * 4));
#pragma unroll
            for (int ni = 0; ni < 4; ni++)
                MMA_TF32(d2[ni], af, bf[ni]);
        }
    }

#pragma unroll
    for (int ni = 0; ni < 4; ni++) {
#pragma unroll
        for (int e = 0; e < 4; e++) {
            int row = r0 + ((e >= 2) ? 8 : 0);
            if (row < 49) {
                int c = ni * 8 + (tig << 1) + (e & 1);
                o[(size_t)tok[row] * 128 + head * 32 + c] = rnd_tf32(d2[ni][e]);
            }
        }
    }
}

// ------------------------------ 2x2 patch merge + LN(512) -------------------
__global__ void __launch_bounds__(256)
merge_ln_kernel(const float* __restrict__ x, float* __restrict__ y,
                const float* __restrict__ g, const float* __restrict__ b)
{
    int warp = (blockIdx.x * blockDim.x + threadIdx.x) >> 5;
    int lane = threadIdx.x & 31;
    int bI = warp / 784;
    int r  = warp - bI * 784;
    int i  = r / 28;
    int j  = r - i * 28;
    int grp = lane >> 3;
    int hh  = grp >> 1, ww = grp & 1;
    int d0  = (lane & 7) << 4;
    const float* src =
        x + (((size_t)(bI * 56 + 2 * i + hh)) * 56 + (2 * j + ww)) * 128 + d0;

    float v[16];
#pragma unroll
    for (int t = 0; t < 4; t++) {
        float4 f = ((const float4*)src)[t];
        v[t * 4 + 0] = f.x; v[t * 4 + 1] = f.y; v[t * 4 + 2] = f.z; v[t * 4 + 3] = f.w;
    }
    float s = 0.f;
#pragma unroll
    for (int t = 0; t < 16; t++) s += v[t];
#pragma unroll
    for (int o = 16; o; o >>= 1) s += __shfl_xor_sync(0xffffffffu, s, o);
    float mean = s * (1.0f / 512.0f);
    float q = 0.f;
#pragma unroll
    for (int t = 0; t < 16; t++) { float dd = v[t] - mean; q += dd * dd; }
#pragma unroll
    for (int o = 16; o; o >>= 1) q += __shfl_xor_sync(0xffffffffu, q, o);
    float rstd = rsqrtf(q * (1.0f / 512.0f) + 1e-5f);

    int c0 = lane << 4;
    float* dst = y + (size_t)warp * 512 + c0;
#pragma unroll
    for (int t = 0; t < 4; t++) {
        float4 gg = ((const float4*)(g + c0))[t];
        float4 bb = ((const float4*)(b + c0))[t];
        float4 out;
        out.x = rnd_tf32((v[t * 4 + 0] - mean) * rstd * gg.x + bb.x);
        out.y = rnd_tf32((v[t * 4 + 1] - mean) * rstd * gg.y + bb.y);
        out.z = rnd_tf32((v[t * 4 + 2] - mean) * rstd * gg.z + bb.z);
        out.w = rnd_tf32((v[t * 4 + 3] - mean) * rstd * gg.w + bb.w);
        ((float4*)dst)[t] = out;
    }
}

// ---------------------------------------------------------------------------
extern "C" void kernel_launch(void* const* d_in, const int* in_sizes, int n_in,
                              void* d_out, int out_size)
{
    const float* x       = (const float*)d_in[0];
    const float* ln1_g   = (const float*)d_in[1];
    const float* ln1_b   = (const float*)d_in[2];
    const float* qkv_w   = (const float*)d_in[3];
    const float* qkv_b   = (const float*)d_in[4];
    const float* proj_w  = (const float*)d_in[5];
    const float* proj_b  = (const float*)d_in[6];
    const float* ln2_g   = (const float*)d_in[7];
    const float* ln2_b   = (const float*)d_in[8];
    const float* mlp_w1  = (const float*)d_in[9];
    const float* mlp_b1  = (const float*)d_in[10];
    const float* mlp_w2  = (const float*)d_in[11];
    const float* mlp_b2  = (const float*)d_in[12];
    const float* dsn_g   = (const float*)d_in[13];
    const float* dsn_b   = (const float*)d_in[14];
    const float* ds_w    = (const float*)d_in[15];
    float* out           = (float*)d_out;

    float *gx, *gh, *gq, *go, *ghid, *gds, *gwt;
    cudaGetSymbolAddress((void**)&gx,   g_x);
    cudaGetSymbolAddress((void**)&gh,   g_h);
    cudaGetSymbolAddress((void**)&gq,   g_qkv);
    cudaGetSymbolAddress((void**)&go,   g_o);
    cudaGetSymbolAddress((void**)&ghid, g_hid);
    cudaGetSymbolAddress((void**)&gds,  g_ds);
    cudaGetSymbolAddress((void**)&gwt,  g_wt);

    cudaFuncSetAttribute(gemm_mma<false, false, false>, cudaFuncAttributeMaxDynamicSharedMemorySize, GEMM_SMEM);
    cudaFuncSetAttribute(gemm_mma<false, true, false>,  cudaFuncAttributeMaxDynamicSharedMemorySize, GEMM_SMEM);
    cudaFuncSetAttribute(gemm_mma<true, false, false>,  cudaFuncAttributeMaxDynamicSharedMemorySize, GEMM_SMEM);
    cudaFuncSetAttribute(gemm_mma<false, true, true>,   cudaFuncAttributeMaxDynamicSharedMemorySize, GEMM_SMEM_LN);

    transpose_all<<<524288 / 256, 256>>>(qkv_w, proj_w, mlp_w1, mlp_w2, ds_w, gwt);

    const dim3 attnGrid(4, 4096);

    // ---- layer 0
    ln128_kernel<<<TOK / 8, 256>>>(x, gh, ln1_g, ln1_b);
    gemm_mma<false, false, false><<<dim3(3, TOK / 128), 256, GEMM_SMEM>>>(
        gh, gwt + 0, qkv_b, nullptr, gq, 384, 128, nullptr, nullptr, nullptr);
    attn_kernel<<<attnGrid, 128>>>(gq, go, 0, 0);
    gemm_mma<false, true, true><<<dim3(1, TOK / 128), 256, GEMM_SMEM_LN>>>(
        go, gwt + 98304, proj_b, x, gx, 128, 128, ln2_g, ln2_b, gh);
    gemm_mma<true, false, false><<<dim3(4, TOK / 128), 256, GEMM_SMEM>>>(
        gh, gwt + 131072, mlp_b1, nullptr, ghid, 512, 128, nullptr, nullptr, nullptr);
    gemm_mma<false, true, true><<<dim3(1, TOK / 128), 256, GEMM_SMEM_LN>>>(
        ghid, gwt + 262144, mlp_b2, gx, gx, 128, 512, ln1_g + 128, ln1_b + 128, gh);

    // ---- layer 1 (shifted)
    gemm_mma<false, false, false><<<dim3(3, TOK / 128), 256, GEMM_SMEM>>>(
        gh, gwt + 49152, qkv_b + 384, nullptr, gq, 384, 128, nullptr, nullptr, nullptr);
    attn_kernel<<<attnGrid, 128>>>(gq, go, 3, 1);
    gemm_mma<false, true, true><<<dim3(1, TOK / 128), 256, GEMM_SMEM_LN>>>(
        go, gwt + 98304 + 16384, proj_b + 128, gx, gx, 128, 128, ln2_g + 128, ln2_b + 128, gh);
    gemm_mma<true, false, false><<<dim3(4, TOK / 128), 256, GEMM_SMEM>>>(
        gh, gwt + 131072 + 65536, mlp_b1 + 512, nullptr, ghid, 512, 128, nullptr, nullptr, nullptr);
    gemm_mma<false, true, false><<<dim3(1, TOK / 128), 256, GEMM_SMEM>>>(
        ghid, gwt + 262144 + 65536, mlp_b2 + 128, gx, gx, 128, 512, nullptr, nullptr, nullptr);

    // ---- downsample
    merge_ln_kernel<<<DSTOK / 8, 256>>>(gx, gds, dsn_g, dsn_b);
    gemm_mma<false, false, false><<<dim3(2, DSTOK / 128), 256, GEMM_SMEM>>>(
        gds, gwt + 393216, nullptr, nullptr, out, 256, 512, nullptr, nullptr, nullptr);
}

// round 16
// speedup vs baseline: 2.1161x; 1.0658x over previous
#include <cuda_runtime.h>
#include <cuda_bf16.h>
#include <cstdint>
#include <math.h>

// ---------------------------------------------------------------------------
// Swin stage on GB300 (compute_103: mma.sync path).
// R16: MLP2 in bf16 (hidden stored bf16, W2 bf16) — cuts 824MB of DRAM traffic.
//      Downsample GEMM stays tf32 (output-facing precision).
// ---------------------------------------------------------------------------

#define TOK 200704          // 64*56*56
#define DSTOK 50176         // 64*28*28

__device__ float g_x  [(size_t)TOK * 128];
__device__ float g_h  [(size_t)TOK * 128];
__device__ float g_qkv[(size_t)TOK * 384];
__device__ float g_o  [(size_t)TOK * 128];
__device__ __nv_bfloat16 g_hidb[(size_t)TOK * 512];
__device__ float g_ds [(size_t)DSTOK * 512];
__device__ float g_wt [524288];   // transposed weights [N,K] K-major, tf32-rounded
__device__ __nv_bfloat16 g_wtb[131072];  // mlp2T bf16 [l][N=128,K=512]

__device__ __forceinline__ uint32_t f2tf32(float f) {
    uint32_t u; asm("cvt.rna.tf32.f32 %0, %1;" : "=r"(u) : "f"(f)); return u;
}
__device__ __forceinline__ float rnd_tf32(float f) {
    return __uint_as_float(f2tf32(f));
}
__device__ __forceinline__ uint32_t smem_u32(const void* p) {
    uint32_t a;
    asm("{ .reg .u64 t; cvta.to.shared.u64 t, %1; cvt.u32.u64 %0, t; }" : "=r"(a) : "l"(p));
    return a;
}
__device__ __forceinline__ uint32_t pack_bf16x2(float x, float y) {
    return ((uint32_t)__bfloat16_as_ushort(__float2bfloat16_rn(y)) << 16) |
           (uint32_t)__bfloat16_as_ushort(__float2bfloat16_rn(x));
}

#define CP_ASYNC16(dst, src) \
    asm volatile("cp.async.cg.shared.global [%0], [%1], 16;" :: "r"(dst), "l"(src))
#define CP_COMMIT() asm volatile("cp.async.commit_group;" ::: "memory")
#define CP_WAITG(n) asm volatile("cp.async.wait_group %0;" :: "n"(n) : "memory")

#define MMA_TF32(d, a, b) \
    asm volatile("mma.sync.aligned.m16n8k8.row.col.f32.tf32.tf32.f32 " \
        "{%0,%1,%2,%3}, {%4,%5,%6,%7}, {%8,%9}, {%0,%1,%2,%3};" \
        : "+f"((d)[0]), "+f"((d)[1]), "+f"((d)[2]), "+f"((d)[3]) \
        : "r"((a)[0]), "r"((a)[1]), "r"((a)[2]), "r"((a)[3]), \
          "r"((b)[0]), "r"((b)[1]))

#define MMA_BF16(d, a, b) \
    asm volatile("mma.sync.aligned.m16n8k16.row.col.f32.bf16.bf16.f32 " \
        "{%0,%1,%2,%3}, {%4,%5,%6,%7}, {%8,%9}, {%0,%1,%2,%3};" \
        : "+f"((d)[0]), "+f"((d)[1]), "+f"((d)[2]), "+f"((d)[3]) \
        : "r"((a)[0]), "r"((a)[1]), "r"((a)[2]), "r"((a)[3]), \
          "r"((b)[0]), "r"((b)[1]))

#define LDMX4(r0, r1, r2, r3, addr) \
    asm volatile("ldmatrix.sync.aligned.m8n8.x4.shared.b16 {%0,%1,%2,%3}, [%4];" \
        : "=r"(r0), "=r"(r1), "=r"(r2), "=r"(r3) : "r"(addr))
#define LDMX2(r0, r1, addr) \
    asm volatile("ldmatrix.sync.aligned.m8n8.x2.shared.b16 {%0,%1}, [%2];" \
        : "=r"(r0), "=r"(r1) : "r"(addr))

__device__ __forceinline__ float gelu_tanh(float v) {
    float u = 0.7978845608028654f * (v + 0.044715f * v * v * v);
    return 0.5f * v * (1.0f + tanhf(u));
}

// ===================== tf32 mma GEMM, 3-stage cp.async, swizzled smem ========
// unit' = unit ^ (row & 7); one block barrier per K-chunk (chunk = 32 fp32).
// GELU=true stores C as bf16 (feeds the bf16 MLP2 GEMM).
#define GSTAGE 4096                                   // floats per matrix stage
#define NSTAGE 3
#define GEMM_SMEM    (NSTAGE * 2 * GSTAGE * 4)        // 98304 bytes
#define GEMM_SMEM_LN (GEMM_SMEM + 2 * 128 * 8)        // + float2 part[2][128]

template <bool GELU, bool RES, bool LNOUT>
__global__ void __launch_bounds__(256, 2)
gemm_mma(const float* __restrict__ A, const float* __restrict__ WT,
         const float* __restrict__ bias, const float* __restrict__ R,
         float* __restrict__ C, int N, int K,
         const float* __restrict__ lng, const float* __restrict__ lnb,
         float* __restrict__ C2)
{
    extern __shared__ float sm[];
    const uint32_t sm0 = smem_u32(sm);
    const int tid  = threadIdx.x;
    const int wid  = tid >> 5, lane = tid & 31;
    const int gID  = lane >> 2, tig = lane & 3;
    const int warpM = wid & 3, warpN = wid >> 2;
    const int rowBase = blockIdx.y << 7;
    const int colBase = blockIdx.x << 7;
    const int lr = tid >> 3;            // store row base (0..31)
    const int lu = tid & 7;             // store 16B-unit (0..7)

    const float* Ab  = A  + (size_t)(rowBase + lr) * K + (lu << 2);
    const float* Wb  = WT + (size_t)(colBase + lr) * K + (lu << 2);
    const uint32_t dstA = sm0 + (uint32_t)(lr * 128) + ((uint32_t)(lu ^ (lr & 7)) << 4);
    const uint32_t dstB = dstA + GSTAGE * 4;

    const int lane8 = lane & 7, sel = lane >> 3;
    const int aRowF = warpM * 32 + lane8 + ((sel & 1) << 3);
    const int ac2   = sel >> 1;
    const int bRowF = warpN * 64 + lane8 + ((sel >> 1) << 3);
    const int bc2   = sel & 1;
    const int aSw   = aRowF & 7, bSw = bRowF & 7;

    float d[2][8][4];
#pragma unroll
    for (int mi = 0; mi < 2; mi++)
#pragma unroll
        for (int ni = 0; ni < 8; ni++)
#pragma unroll
            for (int e = 0; e < 4; e++) d[mi][ni][e] = 0.f;

    const int nch = K >> 5;

#define ISSUE(c_, s_) do {                                                   \
        const int k0_ = (c_) << 5;                                          \
        const uint32_t so_ = (uint32_t)(s_) * (2 * GSTAGE * 4);             \
        _Pragma("unroll")                                                    \
        for (int i_ = 0; i_ < 4; i_++) {                                     \
            CP_ASYNC16(dstA + so_ + i_ * 4096,                               \
                       Ab + (size_t)(i_ << 5) * K + k0_);                    \
            CP_ASYNC16(dstB + so_ + i_ * 4096,                               \
                       Wb + (size_t)(i_ << 5) * K + k0_);                    \
        }                                                                    \
        CP_COMMIT();                                                         \
    } while (0)

    ISSUE(0, 0);
    ISSUE(1, 1);

    int s = 0, sNext = 2;
    for (int c = 0; c < nch; c++) {
        if (c == nch - 1) { CP_WAITG(0); } else { CP_WAITG(1); }
        __syncthreads();
        if (c + 2 < nch) {
            ISSUE(c + 2, sNext);
            sNext = (sNext == NSTAGE - 1) ? 0 : sNext + 1;
        }
        const uint32_t stA = sm0 + (uint32_t)s * (2 * GSTAGE * 4);
        const uint32_t aBase = stA + (uint32_t)(aRowF * 128);
        const uint32_t bBase = stA + GSTAGE * 4 + (uint32_t)(bRowF * 128);
#pragma unroll
        for (int ks = 0; ks < 4; ks++) {
            const uint32_t uA = (uint32_t)(((ks << 1) + ac2) ^ aSw) << 4;
            const uint32_t uB = (uint32_t)(((ks << 1) + bc2) ^ bSw) << 4;
            uint32_t af[2][4], bf[8][2];
#pragma unroll
            for (int mi = 0; mi < 2; mi++)
                LDMX4(af[mi][0], af[mi][1], af[mi][2], af[mi][3],
                      aBase + uA + (uint32_t)(mi * 2048));
#pragma unroll
            for (int p = 0; p < 4; p++)
                LDMX4(bf[2 * p][0], bf[2 * p][1], bf[2 * p + 1][0], bf[2 * p + 1][1],
                      bBase + uB + (uint32_t)(p * 2048));
#pragma unroll
            for (int mi = 0; mi < 2; mi++)
#pragma unroll
                for (int ni = 0; ni < 8; ni++)
                    MMA_TF32(d[mi][ni], af[mi], bf[ni]);
        }
        s = (s == NSTAGE - 1) ? 0 : s + 1;
    }
#undef ISSUE

    const int row0 = rowBase + warpM * 32 + gID;
    const int colW = colBase + warpN * 64 + (tig << 1);

    if (!LNOUT) {
#pragma unroll
        for (int ni = 0; ni < 8; ni++) {
            const int col = colW + ni * 8;
            float bx = 0.f, by = 0.f;
            if (bias) { bx = bias[col]; by = bias[col + 1]; }
#pragma unroll
            for (int mi = 0; mi < 2; mi++) {
#pragma unroll
                for (int half = 0; half < 2; half++) {
                    int r = row0 + mi * 16 + half * 8;
                    float vx = d[mi][ni][half * 2 + 0] + bx;
                    float vy = d[mi][ni][half * 2 + 1] + by;
                    size_t off = (size_t)r * N + col;
                    if (GELU) {
                        // store bf16 (hidden for bf16 MLP2)
                        uint32_t pk = pack_bf16x2(gelu_tanh(vx), gelu_tanh(vy));
                        *(uint32_t*)((__nv_bfloat16*)C + off) = pk;
                    } else {
                        if (RES) {
                            float2 rr = *(const float2*)(R + off);
                            vx += rr.x; vy += rr.y;
                        }
                        float2 o = { vx, vy };
                        *(float2*)(C + off) = o;
                    }
                }
            }
        }
    } else {
        float rs[2][2] = {}, rq[2][2] = {};
#pragma unroll
        for (int ni = 0; ni < 8; ni++) {
            const int col = colW + ni * 8;
            float bx = bias[col], by = bias[col + 1];
#pragma unroll
            for (int mi = 0; mi < 2; mi++) {
#pragma unroll
                for (int half = 0; half < 2; half++) {
                    int r = row0 + mi * 16 + half * 8;
                    size_t off = (size_t)r * 128 + col;
                    float2 rr = *(const float2*)(R + off);
                    float vx = d[mi][ni][half * 2 + 0] + bx + rr.x;
                    float vy = d[mi][ni][half * 2 + 1] + by + rr.y;
                    d[mi][ni][half * 2 + 0] = vx;
                    d[mi][ni][half * 2 + 1] = vy;
                    rs[mi][half] += vx + vy;
                    rq[mi][half] += vx * vx + vy * vy;
                }
            }
        }
#pragma unroll
        for (int mi = 0; mi < 2; mi++)
#pragma unroll
            for (int half = 0; half < 2; half++) {
#pragma unroll
                for (int o2 = 1; o2 <= 2; o2 <<= 1) {
                    rs[mi][half] += __shfl_xor_sync(0xffffffffu, rs[mi][half], o2);
                    rq[mi][half] += __shfl_xor_sync(0xffffffffu, rq[mi][half], o2);
                }
            }
        float2* part = (float2*)(sm + NSTAGE * 2 * GSTAGE);
        __syncthreads();
        if (tig == 0) {
#pragma unroll
            for (int mi = 0; mi < 2; mi++)
#pragma unroll
                for (int half = 0; half < 2; half++) {
                    int rl = warpM * 32 + gID + mi * 16 + half * 8;
                    float2 p = { rs[mi][half], rq[mi][half] };
                    part[warpN * 128 + rl] = p;
                }
        }
        __syncthreads();
        float mean_r[2][2], rstd_r[2][2];
#pragma unroll
        for (int mi = 0; mi < 2; mi++)
#pragma unroll
            for (int half = 0; half < 2; half++) {
                int rl = warpM * 32 + gID + mi * 16 + half * 8;
                float2 p0 = part[rl], p1 = part[128 + rl];
                float s2 = p0.x + p1.x, q = p0.y + p1.y;
                float mean = s2 * (1.0f / 128.0f);
                float var  = q * (1.0f / 128.0f) - mean * mean;
                mean_r[mi][half] = mean;
                rstd_r[mi][half] = rsqrtf(var + 1e-5f);
            }
#pragma unroll
        for (int ni = 0; ni < 8; ni++) {
            const int col = colW + ni * 8;
            float2 ge = __ldg((const float2*)(lng + col));
            float2 be = __ldg((const float2*)(lnb + col));
#pragma unroll
            for (int mi = 0; mi < 2; mi++) {
#pragma unroll
                for (int half = 0; half < 2; half++) {
                    int r = row0 + mi * 16 + half * 8;
                    size_t off = (size_t)r * 128 + col;
                    float vx = d[mi][ni][half * 2 + 0];
                    float vy = d[mi][ni][half * 2 + 1];
                    float2 o = { vx, vy };
                    *(float2*)(C + off) = o;
                    float m = mean_r[mi][half], rstd = rstd_r[mi][half];
                    float2 h;
                    h.x = rnd_tf32((vx - m) * rstd * ge.x + be.x);
                    h.y = rnd_tf32((vy - m) * rstd * ge.y + be.y);
                    *(float2*)(C2 + off) = h;
                }
            }
        }
    }
}

// ===================== bf16 mma GEMM (MLP2), K-chunks of 64 ==================
// A [M,K] bf16, WT [N,K] bf16; 128B rows (64 bf16), same swizzle/pipeline.
// RES always on; LNOUT optionally emits C2 = tf32(LN(C)).
template <bool LNOUT>
__global__ void __launch_bounds__(256, 2)
gemm_bf16(const __nv_bfloat16* __restrict__ A, const __nv_bfloat16* __restrict__ WT,
          const float* __restrict__ bias, const float* __restrict__ R,
          float* __restrict__ C, int N, int K,
          const float* __restrict__ lng, const float* __restrict__ lnb,
          float* __restrict__ C2)
{
    extern __shared__ float sm[];
    const uint32_t sm0 = smem_u32(sm);
    const int tid  = threadIdx.x;
    const int wid  = tid >> 5, lane = tid & 31;
    const int gID  = lane >> 2, tig = lane & 3;
    const int warpM = wid & 3, warpN = wid >> 2;
    const int rowBase = blockIdx.y << 7;
    const int colBase = blockIdx.x << 7;
    const int lr = tid >> 3;
    const int lu = tid & 7;

    const __nv_bfloat16* Ab = A  + (size_t)(rowBase + lr) * K + (lu << 3);
    const __nv_bfloat16* Wb = WT + (size_t)(colBase + lr) * K + (lu << 3);
    const uint32_t dstA = sm0 + (uint32_t)(lr * 128) + ((uint32_t)(lu ^ (lr & 7)) << 4);
    const uint32_t dstB = dstA + GSTAGE * 4;

    const int lane8 = lane & 7, sel = lane >> 3;
    const int aRowF = warpM * 32 + lane8 + ((sel & 1) << 3);
    const int ac2   = sel >> 1;
    const int bRowF = warpN * 64 + lane8 + ((sel >> 1) << 3);
    const int bc2   = sel & 1;
    const int aSw   = aRowF & 7, bSw = bRowF & 7;

    float d[2][8][4];
#pragma unroll
    for (int mi = 0; mi < 2; mi++)
#pragma unroll
        for (int ni = 0; ni < 8; ni++)
#pragma unroll
            for (int e = 0; e < 4; e++) d[mi][ni][e] = 0.f;

    const int nch = K >> 6;    // chunks of 64 bf16

#define ISSUEB(c_, s_) do {                                                  \
        const int k0_ = (c_) << 6;                                          \
        const uint32_t so_ = (uint32_t)(s_) * (2 * GSTAGE * 4);             \
        _Pragma("unroll")                                                    \
        for (int i_ = 0; i_ < 4; i_++) {                                     \
            CP_ASYNC16(dstA + so_ + i_ * 4096,                               \
                       Ab + (size_t)(i_ << 5) * K + k0_);                    \
            CP_ASYNC16(dstB + so_ + i_ * 4096,                               \
                       Wb + (size_t)(i_ << 5) * K + k0_);                    \
        }                                                                    \
        CP_COMMIT();                                                         \
    } while (0)

    ISSUEB(0, 0);
    ISSUEB(1, 1);

    int s = 0, sNext = 2;
    for (int c = 0; c < nch; c++) {
        if (c == nch - 1) { CP_WAITG(0); } else { CP_WAITG(1); }
        __syncthreads();
        if (c + 2 < nch) {
            ISSUEB(c + 2, sNext);
            sNext = (sNext == NSTAGE - 1) ? 0 : sNext + 1;
        }
        const uint32_t stA = sm0 + (uint32_t)s * (2 * GSTAGE * 4);
        const uint32_t aBase = stA + (uint32_t)(aRowF * 128);
        const uint32_t bBase = stA + GSTAGE * 4 + (uint32_t)(bRowF * 128);
#pragma unroll
        for (int ks = 0; ks < 4; ks++) {   // 4 k16 steps per 64-wide chunk
            const uint32_t uA = (uint32_t)(((ks << 1) + ac2) ^ aSw) << 4;
            const uint32_t uB = (uint32_t)(((ks << 1) + bc2) ^ bSw) << 4;
            uint32_t af[2][4], bf[8][2];
#pragma unroll
            for (int mi = 0; mi < 2; mi++)
                LDMX4(af[mi][0], af[mi][1], af[mi][2], af[mi][3],
                      aBase + uA + (uint32_t)(mi * 2048));
#pragma unroll
            for (int p = 0; p < 4; p++)
                LDMX4(bf[2 * p][0], bf[2 * p][1], bf[2 * p + 1][0], bf[2 * p + 1][1],
                      bBase + uB + (uint32_t)(p * 2048));
#pragma unroll
            for (int mi = 0; mi < 2; mi++)
#pragma unroll
                for (int ni = 0; ni < 8; ni++)
                    MMA_BF16(d[mi][ni], af[mi], bf[ni]);
        }
        s = (s == NSTAGE - 1) ? 0 : s + 1;
    }
#undef ISSUEB

    const int row0 = rowBase + warpM * 32 + gID;
    const int colW = colBase + warpN * 64 + (tig << 1);

    if (!LNOUT) {
#pragma unroll
        for (int ni = 0; ni < 8; ni++) {
            const int col = colW + ni * 8;
            float bx = bias[col], by = bias[col + 1];
#pragma unroll
            for (int mi = 0; mi < 2; mi++) {
#pragma unroll
                for (int half = 0; half < 2; half++) {
                    int r = row0 + mi * 16 + half * 8;
                    size_t off = (size_t)r * N + col;
                    float2 rr = *(const float2*)(R + off);
                    float2 o = { d[mi][ni][half * 2 + 0] + bx + rr.x,
                                 d[mi][ni][half * 2 + 1] + by + rr.y };
                    *(float2*)(C + off) = o;
                }
            }
        }
    } else {
        float rs[2][2] = {}, rq[2][2] = {};
#pragma unroll
        for (int ni = 0; ni < 8; ni++) {
            const int col = colW + ni * 8;
            float bx = bias[col], by = bias[col + 1];
#pragma unroll
            for (int mi = 0; mi < 2; mi++) {
#pragma unroll
                for (int half = 0; half < 2; half++) {
                    int r = row0 + mi * 16 + half * 8;
                    size_t off = (size_t)r * 128 + col;
                    float2 rr = *(const float2*)(R + off);
                    float vx = d[mi][ni][half * 2 + 0] + bx + rr.x;
                    float vy = d[mi][ni][half * 2 + 1] + by + rr.y;
                    d[mi][ni][half * 2 + 0] = vx;
                    d[mi][ni][half * 2 + 1] = vy;
                    rs[mi][half] += vx + vy;
                    rq[mi][half] += vx * vx + vy * vy;
                }
            }
        }
#pragma unroll
        for (int mi = 0; mi < 2; mi++)
#pragma unroll
            for (int half = 0; half < 2; half++) {
#pragma unroll
                for (int o2 = 1; o2 <= 2; o2 <<= 1) {
                    rs[mi][half] += __shfl_xor_sync(0xffffffffu, rs[mi][half], o2);
                    rq[mi][half] += __shfl_xor_sync(0xffffffffu, rq[mi][half], o2);
                }
            }
        float2* part = (float2*)(sm + NSTAGE * 2 * GSTAGE);
        __syncthreads();
        if (tig == 0) {
#pragma unroll
            for (int mi = 0; mi < 2; mi++)
#pragma unroll
                for (int half = 0; half < 2; half++) {
                    int rl = warpM * 32 + gID + mi * 16 + half * 8;
                    float2 p = { rs[mi][half], rq[mi][half] };
                    part[warpN * 128 + rl] = p;
                }
        }
        __syncthreads();
        float mean_r[2][2], rstd_r[2][2];
#pragma unroll
        for (int mi = 0; mi < 2; mi++)
#pragma unroll
            for (int half = 0; half < 2; half++) {
                int rl = warpM * 32 + gID + mi * 16 + half * 8;
                float2 p0 = part[rl], p1 = part[128 + rl];
                float s2 = p0.x + p1.x, q = p0.y + p1.y;
                float mean = s2 * (1.0f / 128.0f);
                float var  = q * (1.0f / 128.0f) - mean * mean;
                mean_r[mi][half] = mean;
                rstd_r[mi][half] = rsqrtf(var + 1e-5f);
            }
#pragma unroll
        for (int ni = 0; ni < 8; ni++) {
            const int col = colW + ni * 8;
            float2 ge = __ldg((const float2*)(lng + col));
            float2 be = __ldg((const float2*)(lnb + col));
#pragma unroll
            for (int mi = 0; mi < 2; mi++) {
#pragma unroll
                for (int half = 0; half < 2; half++) {
                    int r = row0 + mi * 16 + half * 8;
                    size_t off = (size_t)r * 128 + col;
                    float vx = d[mi][ni][half * 2 + 0];
                    float vy = d[mi][ni][half * 2 + 1];
                    float2 o = { vx, vy };
                    *(float2*)(C + off) = o;
                    float m = mean_r[mi][half], rstd = rstd_r[mi][half];
                    float2 h;
                    h.x = rnd_tf32((vx - m) * rstd * ge.x + be.x);
                    h.y = rnd_tf32((vy - m) * rstd * ge.y + be.y);
                    *(float2*)(C2 + off) = h;
                }
            }
        }
    }
}

// ---------------- ONE transpose+round kernel for all weights -----------------
// mlp2T additionally emitted as bf16 into out_b (same [l][N,K] layout).
__global__ void transpose_all(const float* __restrict__ qkv_w,
                              const float* __restrict__ proj_w,
                              const float* __restrict__ mlp_w1,
                              const float* __restrict__ mlp_w2,
                              const float* __restrict__ ds_w,
                              float* __restrict__ out,
                              __nv_bfloat16* __restrict__ out_b)
{
    int i = blockIdx.x * 256 + threadIdx.x;
    const float* in; int K, N, base;
    if (i < 98304)       { base = 0;      in = qkv_w;  K = 128; N = 384; }
    else if (i < 131072) { base = 98304;  in = proj_w; K = 128; N = 128; }
    else if (i < 262144) { base = 131072; in = mlp_w1; K = 128; N = 512; }
    else if (i < 393216) { base = 262144; in = mlp_w2; K = 512; N = 128; }
    else                 { base = 393216; in = ds_w;   K = 512; N = 256; }
    int r = i - base;
    int per = K * N;
    int l = r / per; r -= l * per;
    int n = r / K, k = r - n * K;
    float v = in[(size_t)l * per + k * N + n];
    out[i] = __uint_as_float(f2tf32(v));
    if (base == 262144)                  // mlp2 region -> bf16 copy
        out_b[i - 262144] = __float2bfloat16_rn(v);
}

// ------------------------------ LayerNorm (D=128), one warp per token -------
__global__ void __launch_bounds__(256)
ln128_kernel(const float* __restrict__ in, float* __restrict__ out,
             const float* __restrict__ g, const float* __restrict__ b)
{
    int warp = (blockIdx.x * blockDim.x + threadIdx.x) >> 5;
    int lane = threadIdx.x & 31;
    const float4 v = ((const float4*)(in + (size_t)warp * 128))[lane];
    float s = v.x + v.y + v.z + v.w;
#pragma unroll
    for (int o = 16; o; o >>= 1) s += __shfl_xor_sync(0xffffffffu, s, o);
    float mean = s * (1.0f / 128.0f);
    float dx = v.x - mean, dy = v.y - mean, dz = v.z - mean, dw = v.w - mean;
    float q = dx * dx + dy * dy + dz * dz + dw * dw;
#pragma unroll
    for (int o = 16; o; o >>= 1) q += __shfl_xor_sync(0xffffffffu, q, o);
    float rstd = rsqrtf(q * (1.0f / 128.0f) + 1e-5f);
    float4 gg = ((const float4*)g)[lane];
    float4 bb = ((const float4*)b)[lane];
    float4 r;
    r.x = rnd_tf32(dx * rstd * gg.x + bb.x);
    r.y = rnd_tf32(dy * rstd * gg.y + bb.y);
    r.z = rnd_tf32(dz * rstd * gg.z + bb.z);
    r.w = rnd_tf32(dw * rstd * gg.w + bb.w);
    ((float4*)(out + (size_t)warp * 128))[lane] = r;
}

// ------------------------------ Window attention (tensor-core, reg softmax) --
__global__ void __launch_bounds__(128)
attn_kernel(const float* __restrict__ qkv, float* __restrict__ o,
            int shift, int use_mask)
{
    __shared__ float buf[4320];
    __shared__ float vt[32 * 60];
    __shared__ int   tok[64];
    __shared__ int   regn[64];
    float* qs = buf;
    float* ks = buf + 2304;
    float* sc = buf;

    const int tid  = threadIdx.x;
    const int wid  = tid >> 5, lane = tid & 31;
    const int gID  = lane >> 2, tig = lane & 3;
    const int head = blockIdx.x;
    const int bg   = blockIdx.y;
    const int b    = bg >> 6;
    const int g    = bg & 63;
    const int gy   = g >> 3, gx = g & 7;

    const uint32_t bufB = smem_u32(buf);
    const uint32_t ksB  = bufB + 2304 * 4;
    const uint32_t vtB  = smem_u32(vt);
    const int lane8 = lane & 7, sel = lane >> 3;
    const int aRow = wid * 16 + lane8 + ((sel & 1) << 3);
    const int aCol = (sel >> 1) << 2;
    const int bRow = lane8 + ((sel >> 1) << 3);
    const int bCol = (sel & 1) << 2;

    if (tid < 64) {
        regn[tid] = 0;
        if (tid < 49) {
            int wy = tid / 7, wx = tid - (tid / 7) * 7;
            int ph = gy * 7 + wy, pw = gx * 7 + wx;
            int hh = ph + shift; if (hh >= 56) hh -= 56;
            int ww = pw + shift; if (ww >= 56) ww -= 56;
            tok[tid] = b * 3136 + hh * 56 + ww;
            int rh = (ph < 49) ? 0 : ((ph < 53) ? 1 : 2);
            int rw = (pw < 49) ? 0 : ((pw < 53) ? 1 : 2);
            regn[tid] = rh * 3 + rw;
        }
    }
    for (int i = tid; i < 540; i += 128) qs[49 * 36 + i] = 0.f;
    for (int i = tid; i < 252; i += 128) ks[49 * 36 + i] = 0.f;
    for (int i = tid; i < 224; i += 128) {
        int c = i / 7, j = 49 + (i - c * 7);
        vt[c * 60 + j] = 0.f;
    }
    __syncthreads();

    for (int i = tid; i < 49 * 8; i += 128) {
        int r = i >> 3, c4 = (i & 7) << 2;
        const float* base = qkv + (size_t)tok[r] * 384 + head * 32 + c4;
        float4 q4 = *(const float4*)(base);
        float4 k4 = *(const float4*)(base + 128);
        float4 v4 = *(const float4*)(base + 256);
        float4 qr = { rnd_tf32(q4.x), rnd_tf32(q4.y), rnd_tf32(q4.z), rnd_tf32(q4.w) };
        float4 kr = { rnd_tf32(k4.x), rnd_tf32(k4.y), rnd_tf32(k4.z), rnd_tf32(k4.w) };
        *(float4*)&qs[r * 36 + c4] = qr;
        *(float4*)&ks[r * 36 + c4] = kr;
        vt[(c4 + 0) * 60 + r] = rnd_tf32(v4.x);
        vt[(c4 + 1) * 60 + r] = rnd_tf32(v4.y);
        vt[(c4 + 2) * 60 + r] = rnd_tf32(v4.z);
        vt[(c4 + 3) * 60 + r] = rnd_tf32(v4.w);
    }
    __syncthreads();

    const int r0 = wid * 16 + gID;

    float d[7][4];
#pragma unroll
    for (int ni = 0; ni < 7; ni++)
#pragma unroll
        for (int e = 0; e < 4; e++) d[ni][e] = 0.f;

    {
        const uint32_t aB = bufB + (uint32_t)(aRow * 36 + aCol) * 4;
        const uint32_t bB = ksB + (uint32_t)(bRow * 36 + bCol) * 4;
#pragma unroll
        for (int kstep = 0; kstep < 4; kstep++) {
            const uint32_t kb = (uint32_t)(kstep << 5);
            uint32_t af[4], bf[7][2];
            LDMX4(af[0], af[1], af[2], af[3], aB + kb);
#pragma unroll
            for (int p = 0; p < 3; p++)
                LDMX4(bf[2 * p][0], bf[2 * p][1], bf[2 * p + 1][0], bf[2 * p + 1][1],
                      bB + kb + (uint32_t)(p * 16 * 36 * 4));
            LDMX2(bf[6][0], bf[6][1], bB + kb + (uint32_t)(48 * 36 * 4));
#pragma unroll
            for (int ni = 0; ni < 7; ni++)
                MMA_TF32(d[ni], af, bf[ni]);
        }
    }
    __syncthreads();

    const float scale = 0.17677669529663689f;
    {
        int rj[7][2];
        if (use_mask) {
#pragma unroll
            for (int ni = 0; ni < 7; ni++) {
                int j0 = ni * 8 + (tig << 1);
                rj[ni][0] = (j0 < 49) ? regn[j0] : -1;
                rj[ni][1] = (j0 + 1 < 49) ? regn[j0 + 1] : -1;
            }
        }
#pragma unroll
        for (int rr = 0; rr < 2; rr++) {
            const int row = r0 + rr * 8;
            const int rgn = use_mask ? regn[row] : 0;
            float m = -1e30f;
#pragma unroll
            for (int ni = 0; ni < 7; ni++) {
#pragma unroll
                for (int e2 = 0; e2 < 2; e2++) {
                    int j = ni * 8 + (tig << 1) + e2;
                    float val;
                    if (j < 49) {
                        val = d[ni][rr * 2 + e2] * scale;
                        if (use_mask && rgn != rj[ni][e2]) val -= 100.f;
                    } else val = -1e30f;
                    d[ni][rr * 2 + e2] = val;
                    m = fmaxf(m, val);
                }
            }
            m = fmaxf(m, __shfl_xor_sync(0xffffffffu, m, 1));
            m = fmaxf(m, __shfl_xor_sync(0xffffffffu, m, 2));
            float sum = 0.f;
#pragma unroll
            for (int ni = 0; ni < 7; ni++) {
#pragma unroll
                for (int e2 = 0; e2 < 2; e2++) {
                    float e = __expf(d[ni][rr * 2 + e2] - m);
                    d[ni][rr * 2 + e2] = e;
                    sum += e;
                }
            }
            sum += __shfl_xor_sync(0xffffffffu, sum, 1);
            sum += __shfl_xor_sync(0xffffffffu, sum, 2);
            float inv = 1.0f / sum;
#pragma unroll
            for (int ni = 0; ni < 7; ni++) {
#pragma unroll
                for (int e2 = 0; e2 < 2; e2++) {
                    int j = ni * 8 + (tig << 1) + e2;
                    sc[row * 60 + j] = rnd_tf32(d[ni][rr * 2 + e2] * inv);
                }
            }
        }
    }
    __syncwarp();

    float d2[4][4];
#pragma unroll
    for (int ni = 0; ni < 4; ni++)
#pragma unroll
        for (int e = 0; e < 4; e++) d2[ni][e] = 0.f;

    {
        const uint32_t aB = bufB + (uint32_t)(aRow * 60 + aCol) * 4;
        const uint32_t bB = vtB + (uint32_t)(bRow * 60 + bCol) * 4;
#pragma unroll
        for (int kstep = 0; kstep < 7; kstep++) {
            const uint32_t kb = (uint32_t)(kstep << 5);
            uint32_t af[4], bf[4][2];
            LDMX4(af[0], af[1], af[2], af[3], aB + kb);
#pragma unroll
            for (int p = 0; p < 2; p++)
                LDMX4(bf[2 * p][0], bf[2 * p][1], bf[2 * p + 1][0], bf[2 * p + 1][1],
                      bB + kb + (uint32_t)(p * 16 * 60 * 4));
#pragma unroll
            for (int ni = 0; ni < 4; ni++)
                MMA_TF32(d2[ni], af, bf[ni]);
        }
    }

#pragma unroll
    for (int ni = 0; ni < 4; ni++) {
#pragma unroll
        for (int e = 0; e < 4; e++) {
            int row = r0 + ((e >= 2) ? 8 : 0);
            if (row < 49) {
                int c = ni * 8 + (tig << 1) + (e & 1);
                o[(size_t)tok[row] * 128 + head * 32 + c] = rnd_tf32(d2[ni][e]);
            }
        }
    }
}

// ------------------------------ 2x2 patch merge + LN(512) -------------------
__global__ void __launch_bounds__(256)
merge_ln_kernel(const float* __restrict__ x, float* __restrict__ y,
                const float* __restrict__ g, const float* __restrict__ b)
{
    int warp = (blockIdx.x * blockDim.x + threadIdx.x) >> 5;
    int lane = threadIdx.x & 31;
    int bI = warp / 784;
    int r  = warp - bI * 784;
    int i  = r / 28;
    int j  = r - i * 28;
    int grp = lane >> 3;
    int hh  = grp >> 1, ww = grp & 1;
    int d0  = (lane & 7) << 4;
    const float* src =
        x + (((size_t)(bI * 56 + 2 * i + hh)) * 56 + (2 * j + ww)) * 128 + d0;

    float v[16];
#pragma unroll
    for (int t = 0; t < 4; t++) {
        float4 f = ((const float4*)src)[t];
        v[t * 4 + 0] = f.x; v[t * 4 + 1] = f.y; v[t * 4 + 2] = f.z; v[t * 4 + 3] = f.w;
    }
    float s = 0.f;
#pragma unroll
    for (int t = 0; t < 16; t++) s += v[t];
#pragma unroll
    for (int o = 16; o; o >>= 1) s += __shfl_xor_sync(0xffffffffu, s, o);
    float mean = s * (1.0f / 512.0f);
    float q = 0.f;
#pragma unroll
    for (int t = 0; t < 16; t++) { float dd = v[t] - mean; q += dd * dd; }
#pragma unroll
    for (int o = 16; o; o >>= 1) q += __shfl_xor_sync(0xffffffffu, q, o);
    float rstd = rsqrtf(q * (1.0f / 512.0f) + 1e-5f);

    int c0 = lane << 4;
    float* dst = y + (size_t)warp * 512 + c0;
#pragma unroll
    for (int t = 0; t < 4; t++) {
        float4 gg = ((const float4*)(g + c0))[t];
        float4 bb = ((const float4*)(b + c0))[t];
        float4 out;
        out.x = rnd_tf32((v[t * 4 + 0] - mean) * rstd * gg.x + bb.x);
        out.y = rnd_tf32((v[t * 4 + 1] - mean) * rstd * gg.y + bb.y);
        out.z = rnd_tf32((v[t * 4 + 2] - mean) * rstd * gg.z + bb.z);
        out.w = rnd_tf32((v[t * 4 + 3] - mean) * rstd * gg.w + bb.w);
        ((float4*)dst)[t] = out;
    }
}

// ---------------------------------------------------------------------------
extern "C" void kernel_launch(void* const* d_in, const int* in_sizes, int n_in,
                              void* d_out, int out_size)
{
    const float* x       = (const float*)d_in[0];
    const float* ln1_g   = (const float*)d_in[1];
    const float* ln1_b   = (const float*)d_in[2];
    const float* qkv_w   = (const float*)d_in[3];
    const float* qkv_b   = (const float*)d_in[4];
    const float* proj_w  = (const float*)d_in[5];
    const float* proj_b  = (const float*)d_in[6];
    const float* ln2_g   = (const float*)d_in[7];
    const float* ln2_b   = (const float*)d_in[8];
    const float* mlp_w1  = (const float*)d_in[9];
    const float* mlp_b1  = (const float*)d_in[10];
    const float* mlp_w2  = (const float*)d_in[11];
    const float* mlp_b2  = (const float*)d_in[12];
    const float* dsn_g   = (const float*)d_in[13];
    const float* dsn_b   = (const float*)d_in[14];
    const float* ds_w    = (const float*)d_in[15];
    float* out           = (float*)d_out;

    float *gx, *gh, *gq, *go, *gds, *gwt;
    __nv_bfloat16 *ghb, *gwtb;
    cudaGetSymbolAddress((void**)&gx,   g_x);
    cudaGetSymbolAddress((void**)&gh,   g_h);
    cudaGetSymbolAddress((void**)&gq,   g_qkv);
    cudaGetSymbolAddress((void**)&go,   g_o);
    cudaGetSymbolAddress((void**)&ghb,  g_hidb);
    cudaGetSymbolAddress((void**)&gds,  g_ds);
    cudaGetSymbolAddress((void**)&gwt,  g_wt);
    cudaGetSymbolAddress((void**)&gwtb, g_wtb);

    cudaFuncSetAttribute(gemm_mma<false, false, false>, cudaFuncAttributeMaxDynamicSharedMemorySize, GEMM_SMEM);
    cudaFuncSetAttribute(gemm_mma<false, true, false>,  cudaFuncAttributeMaxDynamicSharedMemorySize, GEMM_SMEM);
    cudaFuncSetAttribute(gemm_mma<true, false, false>,  cudaFuncAttributeMaxDynamicSharedMemorySize, GEMM_SMEM);
    cudaFuncSetAttribute(gemm_mma<false, true, true>,   cudaFuncAttributeMaxDynamicSharedMemorySize, GEMM_SMEM_LN);
    cudaFuncSetAttribute(gemm_bf16<false>, cudaFuncAttributeMaxDynamicSharedMemorySize, GEMM_SMEM);
    cudaFuncSetAttribute(gemm_bf16<true>,  cudaFuncAttributeMaxDynamicSharedMemorySize, GEMM_SMEM_LN);

    transpose_all<<<524288 / 256, 256>>>(qkv_w, proj_w, mlp_w1, mlp_w2, ds_w, gwt, gwtb);

    const dim3 attnGrid(4, 4096);

    // ---- layer 0
    ln128_kernel<<<TOK / 8, 256>>>(x, gh, ln1_g, ln1_b);
    gemm_mma<false, false, false><<<dim3(3, TOK / 128), 256, GEMM_SMEM>>>(
        gh, gwt + 0, qkv_b, nullptr, gq, 384, 128, nullptr, nullptr, nullptr);
    attn_kernel<<<attnGrid, 128>>>(gq, go, 0, 0);
    gemm_mma<false, true, true><<<dim3(1, TOK / 128), 256, GEMM_SMEM_LN>>>(
        go, gwt + 98304, proj_b, x, gx, 128, 128, ln2_g, ln2_b, gh);
    gemm_mma<true, false, false><<<dim3(4, TOK / 128), 256, GEMM_SMEM>>>(
        gh, gwt + 131072, mlp_b1, nullptr, (float*)ghb, 512, 128, nullptr, nullptr, nullptr);
    gemm_bf16<true><<<dim3(1, TOK / 128), 256, GEMM_SMEM_LN>>>(
        ghb, gwtb, mlp_b2, gx, gx, 128, 512, ln1_g + 128, ln1_b + 128, gh);

    // ---- layer 1 (shifted)
    gemm_mma<false, false, false><<<dim3(3, TOK / 128), 256, GEMM_SMEM>>>(
        gh, gwt + 49152, qkv_b + 384, nullptr, gq, 384, 128, nullptr, nullptr, nullptr);
    attn_kernel<<<attnGrid, 128>>>(gq, go, 3, 1);
    gemm_mma<false, true, true><<<dim3(1, TOK / 128), 256, GEMM_SMEM_LN>>>(
        go, gwt + 98304 + 16384, proj_b + 128, gx, gx, 128, 128, ln2_g + 128, ln2_b + 128, gh);
    gemm_mma<true, false, false><<<dim3(4, TOK / 128), 256, GEMM_SMEM>>>(
        gh, gwt + 131072 + 65536, mlp_b1 + 512, nullptr, (float*)ghb, 512, 128, nullptr, nullptr, nullptr);
    gemm_bf16<false><<<dim3(1, TOK / 128), 256, GEMM_SMEM>>>(
        ghb, gwtb + 65536, mlp_b2 + 128, gx, gx, 128, 512, nullptr, nullptr, nullptr);

    // ---- downsample (tf32 — output-facing precision)
    merge_ln_kernel<<<DSTOK / 8, 256>>>(gx, gds, dsn_g, dsn_b);
    gemm_mma<false, false, false><<<dim3(2, DSTOK / 128), 256, GEMM_SMEM>>>(
        gds, gwt + 393216, nullptr, nullptr, out, 256, 512, nullptr, nullptr, nullptr);
}

// round 17
// speedup vs baseline: 2.1430x; 1.0127x over previous
#include <cuda_runtime.h>
#include <cuda_bf16.h>
#include <cstdint>
#include <math.h>

// ---------------------------------------------------------------------------
// Swin stage on GB300 (compute_103: mma.sync path).
// R17: bf16 QKV stream + full-bf16 attention (m16n8k16); MLP2 bf16 (R16).
//      Residual stream, proj/QKV/MLP1/downsample GEMM math stay tf32/fp32.
// ---------------------------------------------------------------------------

#define TOK 200704          // 64*56*56
#define DSTOK 50176         // 64*28*28

__device__ float g_x  [(size_t)TOK * 128];
__device__ float g_h  [(size_t)TOK * 128];
__device__ __nv_bfloat16 g_qkvb[(size_t)TOK * 384];
__device__ float g_o  [(size_t)TOK * 128];
__device__ __nv_bfloat16 g_hidb[(size_t)TOK * 512];
__device__ float g_ds [(size_t)DSTOK * 512];
__device__ float g_wt [524288];          // transposed weights [N,K] K-major, tf32
__device__ __nv_bfloat16 g_wtb[131072];  // mlp2T bf16 [l][N=128,K=512]

__device__ __forceinline__ uint32_t f2tf32(float f) {
    uint32_t u; asm("cvt.rna.tf32.f32 %0, %1;" : "=r"(u) : "f"(f)); return u;
}
__device__ __forceinline__ float rnd_tf32(float f) {
    return __uint_as_float(f2tf32(f));
}
__device__ __forceinline__ uint32_t smem_u32(const void* p) {
    uint32_t a;
    asm("{ .reg .u64 t; cvta.to.shared.u64 t, %1; cvt.u32.u64 %0, t; }" : "=r"(a) : "l"(p));
    return a;
}
__device__ __forceinline__ uint32_t pack_bf16x2(float x, float y) {
    return ((uint32_t)__bfloat16_as_ushort(__float2bfloat16_rn(y)) << 16) |
           (uint32_t)__bfloat16_as_ushort(__float2bfloat16_rn(x));
}

#define CP_ASYNC16(dst, src) \
    asm volatile("cp.async.cg.shared.global [%0], [%1], 16;" :: "r"(dst), "l"(src))
#define CP_COMMIT() asm volatile("cp.async.commit_group;" ::: "memory")
#define CP_WAITG(n) asm volatile("cp.async.wait_group %0;" :: "n"(n) : "memory")

#define MMA_TF32(d, a, b) \
    asm volatile("mma.sync.aligned.m16n8k8.row.col.f32.tf32.tf32.f32 " \
        "{%0,%1,%2,%3}, {%4,%5,%6,%7}, {%8,%9}, {%0,%1,%2,%3};" \
        : "+f"((d)[0]), "+f"((d)[1]), "+f"((d)[2]), "+f"((d)[3]) \
        : "r"((a)[0]), "r"((a)[1]), "r"((a)[2]), "r"((a)[3]), \
          "r"((b)[0]), "r"((b)[1]))

#define MMA_BF16(d, a, b) \
    asm volatile("mma.sync.aligned.m16n8k16.row.col.f32.bf16.bf16.f32 " \
        "{%0,%1,%2,%3}, {%4,%5,%6,%7}, {%8,%9}, {%0,%1,%2,%3};" \
        : "+f"((d)[0]), "+f"((d)[1]), "+f"((d)[2]), "+f"((d)[3]) \
        : "r"((a)[0]), "r"((a)[1]), "r"((a)[2]), "r"((a)[3]), \
          "r"((b)[0]), "r"((b)[1]))

#define LDMX4(r0, r1, r2, r3, addr) \
    asm volatile("ldmatrix.sync.aligned.m8n8.x4.shared.b16 {%0,%1,%2,%3}, [%4];" \
        : "=r"(r0), "=r"(r1), "=r"(r2), "=r"(r3) : "r"(addr))
#define LDMX2(r0, r1, addr) \
    asm volatile("ldmatrix.sync.aligned.m8n8.x2.shared.b16 {%0,%1}, [%2];" \
        : "=r"(r0), "=r"(r1) : "r"(addr))

__device__ __forceinline__ float gelu_tanh(float v) {
    float u = 0.7978845608028654f * (v + 0.044715f * v * v * v);
    return 0.5f * v * (1.0f + tanhf(u));
}

// ===================== tf32 mma GEMM, 3-stage cp.async, swizzled smem ========
// GELU=true -> C stored bf16 (MLP hidden). B16O=true -> C stored bf16 (QKV out).
#define GSTAGE 4096
#define NSTAGE 3
#define GEMM_SMEM    (NSTAGE * 2 * GSTAGE * 4)        // 98304 bytes
#define GEMM_SMEM_LN (GEMM_SMEM + 2 * 128 * 8)

template <bool GELU, bool RES, bool LNOUT, bool B16O>
__global__ void __launch_bounds__(256, 2)
gemm_mma(const float* __restrict__ A, const float* __restrict__ WT,
         const float* __restrict__ bias, const float* __restrict__ R,
         float* __restrict__ C, int N, int K,
         const float* __restrict__ lng, const float* __restrict__ lnb,
         float* __restrict__ C2)
{
    extern __shared__ float sm[];
    const uint32_t sm0 = smem_u32(sm);
    const int tid  = threadIdx.x;
    const int wid  = tid >> 5, lane = tid & 31;
    const int gID  = lane >> 2, tig = lane & 3;
    const int warpM = wid & 3, warpN = wid >> 2;
    const int rowBase = blockIdx.y << 7;
    const int colBase = blockIdx.x << 7;
    const int lr = tid >> 3;
    const int lu = tid & 7;

    const float* Ab  = A  + (size_t)(rowBase + lr) * K + (lu << 2);
    const float* Wb  = WT + (size_t)(colBase + lr) * K + (lu << 2);
    const uint32_t dstA = sm0 + (uint32_t)(lr * 128) + ((uint32_t)(lu ^ (lr & 7)) << 4);
    const uint32_t dstB = dstA + GSTAGE * 4;

    const int lane8 = lane & 7, sel = lane >> 3;
    const int aRowF = warpM * 32 + lane8 + ((sel & 1) << 3);
    const int ac2   = sel >> 1;
    const int bRowF = warpN * 64 + lane8 + ((sel >> 1) << 3);
    const int bc2   = sel & 1;
    const int aSw   = aRowF & 7, bSw = bRowF & 7;

    float d[2][8][4];
#pragma unroll
    for (int mi = 0; mi < 2; mi++)
#pragma unroll
        for (int ni = 0; ni < 8; ni++)
#pragma unroll
            for (int e = 0; e < 4; e++) d[mi][ni][e] = 0.f;

    const int nch = K >> 5;

#define ISSUE(c_, s_) do {                                                   \
        const int k0_ = (c_) << 5;                                          \
        const uint32_t so_ = (uint32_t)(s_) * (2 * GSTAGE * 4);             \
        _Pragma("unroll")                                                    \
        for (int i_ = 0; i_ < 4; i_++) {                                     \
            CP_ASYNC16(dstA + so_ + i_ * 4096,                               \
                       Ab + (size_t)(i_ << 5) * K + k0_);                    \
            CP_ASYNC16(dstB + so_ + i_ * 4096,                               \
                       Wb + (size_t)(i_ << 5) * K + k0_);                    \
        }                                                                    \
        CP_COMMIT();                                                         \
    } while (0)

    ISSUE(0, 0);
    ISSUE(1, 1);

    int s = 0, sNext = 2;
    for (int c = 0; c < nch; c++) {
        if (c == nch - 1) { CP_WAITG(0); } else { CP_WAITG(1); }
        __syncthreads();
        if (c + 2 < nch) {
            ISSUE(c + 2, sNext);
            sNext = (sNext == NSTAGE - 1) ? 0 : sNext + 1;
        }
        const uint32_t stA = sm0 + (uint32_t)s * (2 * GSTAGE * 4);
        const uint32_t aBase = stA + (uint32_t)(aRowF * 128);
        const uint32_t bBase = stA + GSTAGE * 4 + (uint32_t)(bRowF * 128);
#pragma unroll
        for (int ks = 0; ks < 4; ks++) {
            const uint32_t uA = (uint32_t)(((ks << 1) + ac2) ^ aSw) << 4;
            const uint32_t uB = (uint32_t)(((ks << 1) + bc2) ^ bSw) << 4;
            uint32_t af[2][4], bf[8][2];
#pragma unroll
            for (int mi = 0; mi < 2; mi++)
                LDMX4(af[mi][0], af[mi][1], af[mi][2], af[mi][3],
                      aBase + uA + (uint32_t)(mi * 2048));
#pragma unroll
            for (int p = 0; p < 4; p++)
                LDMX4(bf[2 * p][0], bf[2 * p][1], bf[2 * p + 1][0], bf[2 * p + 1][1],
                      bBase + uB + (uint32_t)(p * 2048));
#pragma unroll
            for (int mi = 0; mi < 2; mi++)
#pragma unroll
                for (int ni = 0; ni < 8; ni++)
                    MMA_TF32(d[mi][ni], af[mi], bf[ni]);
        }
        s = (s == NSTAGE - 1) ? 0 : s + 1;
    }
#undef ISSUE

    const int row0 = rowBase + warpM * 32 + gID;
    const int colW = colBase + warpN * 64 + (tig << 1);

    if (!LNOUT) {
#pragma unroll
        for (int ni = 0; ni < 8; ni++) {
            const int col = colW + ni * 8;
            float bx = 0.f, by = 0.f;
            if (bias) { bx = bias[col]; by = bias[col + 1]; }
#pragma unroll
            for (int mi = 0; mi < 2; mi++) {
#pragma unroll
                for (int half = 0; half < 2; half++) {
                    int r = row0 + mi * 16 + half * 8;
                    float vx = d[mi][ni][half * 2 + 0] + bx;
                    float vy = d[mi][ni][half * 2 + 1] + by;
                    size_t off = (size_t)r * N + col;
                    if (GELU) {
                        uint32_t pk = pack_bf16x2(gelu_tanh(vx), gelu_tanh(vy));
                        *(uint32_t*)((__nv_bfloat16*)C + off) = pk;
                    } else if (B16O) {
                        uint32_t pk = pack_bf16x2(vx, vy);
                        *(uint32_t*)((__nv_bfloat16*)C + off) = pk;
                    } else {
                        if (RES) {
                            float2 rr = *(const float2*)(R + off);
                            vx += rr.x; vy += rr.y;
                        }
                        float2 o = { vx, vy };
                        *(float2*)(C + off) = o;
                    }
                }
            }
        }
    } else {
        float rs[2][2] = {}, rq[2][2] = {};
#pragma unroll
        for (int ni = 0; ni < 8; ni++) {
            const int col = colW + ni * 8;
            float bx = bias[col], by = bias[col + 1];
#pragma unroll
            for (int mi = 0; mi < 2; mi++) {
#pragma unroll
                for (int half = 0; half < 2; half++) {
                    int r = row0 + mi * 16 + half * 8;
                    size_t off = (size_t)r * 128 + col;
                    float2 rr = *(const float2*)(R + off);
                    float vx = d[mi][ni][half * 2 + 0] + bx + rr.x;
                    float vy = d[mi][ni][half * 2 + 1] + by + rr.y;
                    d[mi][ni][half * 2 + 0] = vx;
                    d[mi][ni][half * 2 + 1] = vy;
                    rs[mi][half] += vx + vy;
                    rq[mi][half] += vx * vx + vy * vy;
                }
            }
        }
#pragma unroll
        for (int mi = 0; mi < 2; mi++)
#pragma unroll
            for (int half = 0; half < 2; half++) {
#pragma unroll
                for (int o2 = 1; o2 <= 2; o2 <<= 1) {
                    rs[mi][half] += __shfl_xor_sync(0xffffffffu, rs[mi][half], o2);
                    rq[mi][half] += __shfl_xor_sync(0xffffffffu, rq[mi][half], o2);
                }
            }
        float2* part = (float2*)(sm + NSTAGE * 2 * GSTAGE);
        __syncthreads();
        if (tig == 0) {
#pragma unroll
            for (int mi = 0; mi < 2; mi++)
#pragma unroll
                for (int half = 0; half < 2; half++) {
                    int rl = warpM * 32 + gID + mi * 16 + half * 8;
                    float2 p = { rs[mi][half], rq[mi][half] };
                    part[warpN * 128 + rl] = p;
                }
        }
        __syncthreads();
        float mean_r[2][2], rstd_r[2][2];
#pragma unroll
        for (int mi = 0; mi < 2; mi++)
#pragma unroll
            for (int half = 0; half < 2; half++) {
                int rl = warpM * 32 + gID + mi * 16 + half * 8;
                float2 p0 = part[rl], p1 = part[128 + rl];
                float s2 = p0.x + p1.x, q = p0.y + p1.y;
                float mean = s2 * (1.0f / 128.0f);
                float var  = q * (1.0f / 128.0f) - mean * mean;
                mean_r[mi][half] = mean;
                rstd_r[mi][half] = rsqrtf(var + 1e-5f);
            }
#pragma unroll
        for (int ni = 0; ni < 8; ni++) {
            const int col = colW + ni * 8;
            float2 ge = __ldg((const float2*)(lng + col));
            float2 be = __ldg((const float2*)(lnb + col));
#pragma unroll
            for (int mi = 0; mi < 2; mi++) {
#pragma unroll
                for (int half = 0; half < 2; half++) {
                    int r = row0 + mi * 16 + half * 8;
                    size_t off = (size_t)r * 128 + col;
                    float vx = d[mi][ni][half * 2 + 0];
                    float vy = d[mi][ni][half * 2 + 1];
                    float2 o = { vx, vy };
                    *(float2*)(C + off) = o;
                    float m = mean_r[mi][half], rstd = rstd_r[mi][half];
                    float2 h;
                    h.x = rnd_tf32((vx - m) * rstd * ge.x + be.x);
                    h.y = rnd_tf32((vy - m) * rstd * ge.y + be.y);
                    *(float2*)(C2 + off) = h;
                }
            }
        }
    }
}

// ===================== bf16 mma GEMM (MLP2), K-chunks of 64 ==================
template <bool LNOUT>
__global__ void __launch_bounds__(256, 2)
gemm_bf16(const __nv_bfloat16* __restrict__ A, const __nv_bfloat16* __restrict__ WT,
          const float* __restrict__ bias, const float* __restrict__ R,
          float* __restrict__ C, int N, int K,
          const float* __restrict__ lng, const float* __restrict__ lnb,
          float* __restrict__ C2)
{
    extern __shared__ float sm[];
    const uint32_t sm0 = smem_u32(sm);
    const int tid  = threadIdx.x;
    const int wid  = tid >> 5, lane = tid & 31;
    const int gID  = lane >> 2, tig = lane & 3;
    const int warpM = wid & 3, warpN = wid >> 2;
    const int rowBase = blockIdx.y << 7;
    const int colBase = blockIdx.x << 7;
    const int lr = tid >> 3;
    const int lu = tid & 7;

    const __nv_bfloat16* Ab = A  + (size_t)(rowBase + lr) * K + (lu << 3);
    const __nv_bfloat16* Wb = WT + (size_t)(colBase + lr) * K + (lu << 3);
    const uint32_t dstA = sm0 + (uint32_t)(lr * 128) + ((uint32_t)(lu ^ (lr & 7)) << 4);
    const uint32_t dstB = dstA + GSTAGE * 4;

    const int lane8 = lane & 7, sel = lane >> 3;
    const int aRowF = warpM * 32 + lane8 + ((sel & 1) << 3);
    const int ac2   = sel >> 1;
    const int bRowF = warpN * 64 + lane8 + ((sel >> 1) << 3);
    const int bc2   = sel & 1;
    const int aSw   = aRowF & 7, bSw = bRowF & 7;

    float d[2][8][4];
#pragma unroll
    for (int mi = 0; mi < 2; mi++)
#pragma unroll
        for (int ni = 0; ni < 8; ni++)
#pragma unroll
            for (int e = 0; e < 4; e++) d[mi][ni][e] = 0.f;

    const int nch = K >> 6;

#define ISSUEB(c_, s_) do {                                                  \
        const int k0_ = (c_) << 6;                                          \
        const uint32_t so_ = (uint32_t)(s_) * (2 * GSTAGE * 4);             \
        _Pragma("unroll")                                                    \
        for (int i_ = 0; i_ < 4; i_++) {                                     \
            CP_ASYNC16(dstA + so_ + i_ * 4096,                               \
                       Ab + (size_t)(i_ << 5) * K + k0_);                    \
            CP_ASYNC16(dstB + so_ + i_ * 4096,                               \
                       Wb + (size_t)(i_ << 5) * K + k0_);                    \
        }                                                                    \
        CP_COMMIT();                                                         \
    } while (0)

    ISSUEB(0, 0);
    ISSUEB(1, 1);

    int s = 0, sNext = 2;
    for (int c = 0; c < nch; c++) {
        if (c == nch - 1) { CP_WAITG(0); } else { CP_WAITG(1); }
        __syncthreads();
        if (c + 2 < nch) {
            ISSUEB(c + 2, sNext);
            sNext = (sNext == NSTAGE - 1) ? 0 : sNext + 1;
        }
        const uint32_t stA = sm0 + (uint32_t)s * (2 * GSTAGE * 4);
        const uint32_t aBase = stA + (uint32_t)(aRowF * 128);
        const uint32_t bBase = stA + GSTAGE * 4 + (uint32_t)(bRowF * 128);
#pragma unroll
        for (int ks = 0; ks < 4; ks++) {
            const uint32_t uA = (uint32_t)(((ks << 1) + ac2) ^ aSw) << 4;
            const uint32_t uB = (uint32_t)(((ks << 1) + bc2) ^ bSw) << 4;
            uint32_t af[2][4], bf[8][2];
#pragma unroll
            for (int mi = 0; mi < 2; mi++)
                LDMX4(af[mi][0], af[mi][1], af[mi][2], af[mi][3],
                      aBase + uA + (uint32_t)(mi * 2048));
#pragma unroll
            for (int p = 0; p < 4; p++)
                LDMX4(bf[2 * p][0], bf[2 * p][1], bf[2 * p + 1][0], bf[2 * p + 1][1],
                      bBase + uB + (uint32_t)(p * 2048));
#pragma unroll
            for (int mi = 0; mi < 2; mi++)
#pragma unroll
                for (int ni = 0; ni < 8; ni++)
                    MMA_BF16(d[mi][ni], af[mi], bf[ni]);
        }
        s = (s == NSTAGE - 1) ? 0 : s + 1;
    }
#undef ISSUEB

    const int row0 = rowBase + warpM * 32 + gID;
    const int colW = colBase + warpN * 64 + (tig << 1);

    if (!LNOUT) {
#pragma unroll
        for (int ni = 0; ni < 8; ni++) {
            const int col = colW + ni * 8;
            float bx = bias[col], by = bias[col + 1];
#pragma unroll
            for (int mi = 0; mi < 2; mi++) {
#pragma unroll
                for (int half = 0; half < 2; half++) {
                    int r = row0 + mi * 16 + half * 8;
                    size_t off = (size_t)r * N + col;
                    float2 rr = *(const float2*)(R + off);
                    float2 o = { d[mi][ni][half * 2 + 0] + bx + rr.x,
                                 d[mi][ni][half * 2 + 1] + by + rr.y };
                    *(float2*)(C + off) = o;
                }
            }
        }
    } else {
        float rs[2][2] = {}, rq[2][2] = {};
#pragma unroll
        for (int ni = 0; ni < 8; ni++) {
            const int col = colW + ni * 8;
            float bx = bias[col], by = bias[col + 1];
#pragma unroll
            for (int mi = 0; mi < 2; mi++) {
#pragma unroll
                for (int half = 0; half < 2; half++) {
                    int r = row0 + mi * 16 + half * 8;
                    size_t off = (size_t)r * 128 + col;
                    float2 rr = *(const float2*)(R + off);
                    float vx = d[mi][ni][half * 2 + 0] + bx + rr.x;
                    float vy = d[mi][ni][half * 2 + 1] + by + rr.y;
                    d[mi][ni][half * 2 + 0] = vx;
                    d[mi][ni][half * 2 + 1] = vy;
                    rs[mi][half] += vx + vy;
                    rq[mi][half] += vx * vx + vy * vy;
                }
            }
        }
#pragma unroll
        for (int mi = 0; mi < 2; mi++)
#pragma unroll
            for (int half = 0; half < 2; half++) {
#pragma unroll
                for (int o2 = 1; o2 <= 2; o2 <<= 1) {
                    rs[mi][half] += __shfl_xor_sync(0xffffffffu, rs[mi][half], o2);
                    rq[mi][half] += __shfl_xor_sync(0xffffffffu, rq[mi][half], o2);
                }
            }
        float2* part = (float2*)(sm + NSTAGE * 2 * GSTAGE);
        __syncthreads();
        if (tig == 0) {
#pragma unroll
            for (int mi = 0; mi < 2; mi++)
#pragma unroll
                for (int half = 0; half < 2; half++) {
                    int rl = warpM * 32 + gID + mi * 16 + half * 8;
                    float2 p = { rs[mi][half], rq[mi][half] };
                    part[warpN * 128 + rl] = p;
                }
        }
        __syncthreads();
        float mean_r[2][2], rstd_r[2][2];
#pragma unroll
        for (int mi = 0; mi < 2; mi++)
#pragma unroll
            for (int half = 0; half < 2; half++) {
                int rl = warpM * 32 + gID + mi * 16 + half * 8;
                float2 p0 = part[rl], p1 = part[128 + rl];
                float s2 = p0.x + p1.x, q = p0.y + p1.y;
                float mean = s2 * (1.0f / 128.0f);
                float var  = q * (1.0f / 128.0f) - mean * mean;
                mean_r[mi][half] = mean;
                rstd_r[mi][half] = rsqrtf(var + 1e-5f);
            }
#pragma unroll
        for (int ni = 0; ni < 8; ni++) {
            const int col = colW + ni * 8;
            float2 ge = __ldg((const float2*)(lng + col));
            float2 be = __ldg((const float2*)(lnb + col));
#pragma unroll
            for (int mi = 0; mi < 2; mi++) {
#pragma unroll
                for (int half = 0; half < 2; half++) {
                    int r = row0 + mi * 16 + half * 8;
                    size_t off = (size_t)r * 128 + col;
                    float vx = d[mi][ni][half * 2 + 0];
                    float vy = d[mi][ni][half * 2 + 1];
                    float2 o = { vx, vy };
                    *(float2*)(C + off) = o;
                    float m = mean_r[mi][half], rstd = rstd_r[mi][half];
                    float2 h;
                    h.x = rnd_tf32((vx - m) * rstd * ge.x + be.x);
                    h.y = rnd_tf32((vy - m) * rstd * ge.y + be.y);
                    *(float2*)(C2 + off) = h;
                }
            }
        }
    }
}

// ---------------- ONE transpose+round kernel for all weights -----------------
__global__ void transpose_all(const float* __restrict__ qkv_w,
                              const float* __restrict__ proj_w,
                              const float* __restrict__ mlp_w1,
                              const float* __restrict__ mlp_w2,
                              const float* __restrict__ ds_w,
                              float* __restrict__ out,
                              __nv_bfloat16* __restrict__ out_b)
{
    int i = blockIdx.x * 256 + threadIdx.x;
    const float* in; int K, N, base;
    if (i < 98304)       { base = 0;      in = qkv_w;  K = 128; N = 384; }
    else if (i < 131072) { base = 98304;  in = proj_w; K = 128; N = 128; }
    else if (i < 262144) { base = 131072; in = mlp_w1; K = 128; N = 512; }
    else if (i < 393216) { base = 262144; in = mlp_w2; K = 512; N = 128; }
    else                 { base = 393216; in = ds_w;   K = 512; N = 256; }
    int r = i - base;
    int per = K * N;
    int l = r / per; r -= l * per;
    int n = r / K, k = r - n * K;
    float v = in[(size_t)l * per + k * N + n];
    out[i] = __uint_as_float(f2tf32(v));
    if (base == 262144)
        out_b[i - 262144] = __float2bfloat16_rn(v);
}

// ------------------------------ LayerNorm (D=128), one warp per token -------
__global__ void __launch_bounds__(256)
ln128_kernel(const float* __restrict__ in, float* __restrict__ out,
             const float* __restrict__ g, const float* __restrict__ b)
{
    int warp = (blockIdx.x * blockDim.x + threadIdx.x) >> 5;
    int lane = threadIdx.x & 31;
    const float4 v = ((const float4*)(in + (size_t)warp * 128))[lane];
    float s = v.x + v.y + v.z + v.w;
#pragma unroll
    for (int o = 16; o; o >>= 1) s += __shfl_xor_sync(0xffffffffu, s, o);
    float mean = s * (1.0f / 128.0f);
    float dx = v.x - mean, dy = v.y - mean, dz = v.z - mean, dw = v.w - mean;
    float q = dx * dx + dy * dy + dz * dz + dw * dw;
#pragma unroll
    for (int o = 16; o; o >>= 1) q += __shfl_xor_sync(0xffffffffu, q, o);
    float rstd = rsqrtf(q * (1.0f / 128.0f) + 1e-5f);
    float4 gg = ((const float4*)g)[lane];
    float4 bb = ((const float4*)b)[lane];
    float4 r;
    r.x = rnd_tf32(dx * rstd * gg.x + bb.x);
    r.y = rnd_tf32(dy * rstd * gg.y + bb.y);
    r.z = rnd_tf32(dz * rstd * gg.z + bb.z);
    r.w = rnd_tf32(dw * rstd * gg.w + bb.w);
    ((float4*)(out + (size_t)warp * 128))[lane] = r;
}

// ------------------------------ Window attention (bf16 tensor-core) ----------
// qkv is bf16. qs/ks: 40-bf16 rows (80B); vt/sc: 72-bf16 rows (144B).
// sc (64x72) aliases qs+ks (64*40 + 56*40 = 4800 >= 64*72=4608).
__global__ void __launch_bounds__(128)
attn_kernel(const __nv_bfloat16* __restrict__ qkv, float* __restrict__ o,
            int shift, int use_mask)
{
    __shared__ __nv_bfloat16 buf[4800];       // qs @0 (64*40), ks @2560 (56*40); sc alias @0
    __shared__ __nv_bfloat16 vt[32 * 72];
    __shared__ int tok[64];
    __shared__ int regn[64];
    __nv_bfloat16* qs = buf;
    __nv_bfloat16* ks = buf + 64 * 40;
    __nv_bfloat16* sc = buf;

    const int tid  = threadIdx.x;
    const int wid  = tid >> 5, lane = tid & 31;
    const int gID  = lane >> 2, tig = lane & 3;
    const int head = blockIdx.x;
    const int bg   = blockIdx.y;
    const int b    = bg >> 6;
    const int g    = bg & 63;
    const int gy   = g >> 3, gx = g & 7;

    const uint32_t qsB = smem_u32(buf);
    const uint32_t ksB = qsB + 64 * 40 * 2;
    const uint32_t vtB = smem_u32(vt);
    const int lane8 = lane & 7, sel = lane >> 3;
    const int aRow  = wid * 16 + lane8 + ((sel & 1) << 3);
    const int aColB = (sel >> 1) << 4;        // bytes (8 bf16)
    const int bRow  = lane8 + ((sel >> 1) << 3);
    const int bColB = (sel & 1) << 4;

    if (tid < 64) {
        regn[tid] = 0;
        if (tid < 49) {
            int wy = tid / 7, wx = tid - (tid / 7) * 7;
            int ph = gy * 7 + wy, pw = gx * 7 + wx;
            int hh = ph + shift; if (hh >= 56) hh -= 56;
            int ww = pw + shift; if (ww >= 56) ww -= 56;
            tok[tid] = b * 3136 + hh * 56 + ww;
            int rh = (ph < 49) ? 0 : ((ph < 53) ? 1 : 2);
            int rw = (pw < 49) ? 0 : ((pw < 53) ? 1 : 2);
            regn[tid] = rh * 3 + rw;
        }
    }
    // zero pads: qs rows 49..63 (15*40=600), ks rows 49..55 (280), vt cols 49..63 (32*15=480)
    for (int i = tid; i < 600; i += 128) qs[49 * 40 + i] = __float2bfloat16_rn(0.f);
    for (int i = tid; i < 280; i += 128) ks[49 * 40 + i] = __float2bfloat16_rn(0.f);
    for (int i = tid; i < 480; i += 128) {
        int c = i / 15, j = 49 + (i - c * 15);
        vt[c * 72 + j] = __float2bfloat16_rn(0.f);
    }
    __syncthreads();

    // load: 49 rows x 12 x 16B segments (q/k vector store; v transposed scalar)
    for (int i = tid; i < 49 * 12; i += 128) {
        int r = i / 12, seg = i - r * 12;
        int which = seg >> 2, part = seg & 3;       // 0=q 1=k 2=v; 16B part
        const __nv_bfloat16* base =
            qkv + (size_t)tok[r] * 384 + which * 128 + head * 32 + part * 8;
        uint4 val = *(const uint4*)base;
        if (which == 0) {
            *(uint4*)&qs[r * 40 + part * 8] = val;
        } else if (which == 1) {
            *(uint4*)&ks[r * 40 + part * 8] = val;
        } else {
            __nv_bfloat16 vv[8];
            *(uint4*)vv = val;
#pragma unroll
            for (int u = 0; u < 8; u++)
                vt[(part * 8 + u) * 72 + r] = vv[u];
        }
    }
    __syncthreads();

    const int r0 = wid * 16 + gID;

    // ---- QK^T (bf16, K=32 -> 2 k16 steps)
    float d[7][4];
#pragma unroll
    for (int ni = 0; ni < 7; ni++)
#pragma unroll
        for (int e = 0; e < 4; e++) d[ni][e] = 0.f;

    {
        const uint32_t aB = qsB + (uint32_t)(aRow * 80) + aColB;
        const uint32_t bB = ksB + (uint32_t)(bRow * 80) + bColB;
#pragma unroll
        for (int kstep = 0; kstep < 2; kstep++) {
            const uint32_t kb = (uint32_t)(kstep << 5);     // 16 bf16 = 32B
            uint32_t af[4], bf[7][2];
            LDMX4(af[0], af[1], af[2], af[3], aB + kb);
#pragma unroll
            for (int p = 0; p < 3; p++)
                LDMX4(bf[2 * p][0], bf[2 * p][1], bf[2 * p + 1][0], bf[2 * p + 1][1],
                      bB + kb + (uint32_t)(p * 16 * 80));
            LDMX2(bf[6][0], bf[6][1], bB + kb + (uint32_t)(48 * 80));
#pragma unroll
            for (int ni = 0; ni < 7; ni++)
                MMA_BF16(d[ni], af, bf[ni]);
        }
    }
    __syncthreads();   // QK reads of qs/ks done before sc overlays them

    // ---- in-register softmax; weights stored bf16 into sc
    const float scale = 0.17677669529663689f;
    {
        int rj[7][2];
        if (use_mask) {
#pragma unroll
            for (int ni = 0; ni < 7; ni++) {
                int j0 = ni * 8 + (tig << 1);
                rj[ni][0] = (j0 < 49) ? regn[j0] : -1;
                rj[ni][1] = (j0 + 1 < 49) ? regn[j0 + 1] : -1;
            }
        }
#pragma unroll
        for (int rr = 0; rr < 2; rr++) {
            const int row = r0 + rr * 8;
            const int rgn = use_mask ? regn[row] : 0;
            float m = -1e30f;
#pragma unroll
            for (int ni = 0; ni < 7; ni++) {
#pragma unroll
                for (int e2 = 0; e2 < 2; e2++) {
                    int j = ni * 8 + (tig << 1) + e2;
                    float val;
                    if (j < 49) {
                        val = d[ni][rr * 2 + e2] * scale;
                        if (use_mask && rgn != rj[ni][e2]) val -= 100.f;
                    } else val = -1e30f;
                    d[ni][rr * 2 + e2] = val;
                    m = fmaxf(m, val);
                }
            }
            m = fmaxf(m, __shfl_xor_sync(0xffffffffu, m, 1));
            m = fmaxf(m, __shfl_xor_sync(0xffffffffu, m, 2));
            float sum = 0.f;
#pragma unroll
            for (int ni = 0; ni < 7; ni++) {
#pragma unroll
                for (int e2 = 0; e2 < 2; e2++) {
                    float e = __expf(d[ni][rr * 2 + e2] - m);
                    d[ni][rr * 2 + e2] = e;
                    sum += e;
                }
            }
            sum += __shfl_xor_sync(0xffffffffu, sum, 1);
            sum += __shfl_xor_sync(0xffffffffu, sum, 2);
            float inv = 1.0f / sum;
#pragma unroll
            for (int ni = 0; ni < 7; ni++) {
                int j = ni * 8 + (tig << 1);
                uint32_t pk = pack_bf16x2(d[ni][rr * 2 + 0] * inv,
                                          d[ni][rr * 2 + 1] * inv);
                *(uint32_t*)&sc[row * 72 + j] = pk;
            }
        }
    }
    __syncwarp();   // AV A-fragment reads only this warp's sc rows

    // ---- AV (bf16, K=64 padded -> 4 k16 steps)
    float d2[4][4];
#pragma unroll
    for (int ni = 0; ni < 4; ni++)
#pragma unroll
        for (int e = 0; e < 4; e++) d2[ni][e] = 0.f;

    {
        const uint32_t aB = qsB + (uint32_t)(aRow * 144) + aColB;   // sc alias
        const uint32_t bB = vtB + (uint32_t)(bRow * 144) + bColB;
#pragma unroll
        for (int kstep = 0; kstep < 4; kstep++) {
            const uint32_t kb = (uint32_t)(kstep << 5);
            uint32_t af[4], bf[4][2];
            LDMX4(af[0], af[1], af[2], af[3], aB + kb);
#pragma unroll
            for (int p = 0; p < 2; p++)
                LDMX4(bf[2 * p][0], bf[2 * p][1], bf[2 * p + 1][0], bf[2 * p + 1][1],
                      bB + kb + (uint32_t)(p * 16 * 144));
#pragma unroll
            for (int ni = 0; ni < 4; ni++)
                MMA_BF16(d2[ni], af, bf[ni]);
        }
    }

#pragma unroll
    for (int ni = 0; ni < 4; ni++) {
#pragma unroll
        for (int e = 0; e < 4; e++) {
            int row = r0 + ((e >= 2) ? 8 : 0);
            if (row < 49) {
                int c = ni * 8 + (tig << 1) + (e & 1);
                o[(size_t)tok[row] * 128 + head * 32 + c] = rnd_tf32(d2[ni][e]);
            }
        }
    }
}

// ------------------------------ 2x2 patch merge + LN(512) -------------------
__global__ void __launch_bounds__(256)
merge_ln_kernel(const float* __restrict__ x, float* __restrict__ y,
                const float* __restrict__ g, const float* __restrict__ b)
{
    int warp = (blockIdx.x * blockDim.x + threadIdx.x) >> 5;
    int lane = threadIdx.x & 31;
    int bI = warp / 784;
    int r  = warp - bI * 784;
    int i  = r / 28;
    int j  = r - i * 28;
    int grp = lane >> 3;
    int hh  = grp >> 1, ww = grp & 1;
    int d0  = (lane & 7) << 4;
    const float* src =
        x + (((size_t)(bI * 56 + 2 * i + hh)) * 56 + (2 * j + ww)) * 128 + d0;

    float v[16];
#pragma unroll
    for (int t = 0; t < 4; t++) {
        float4 f = ((const float4*)src)[t];
        v[t * 4 + 0] = f.x; v[t * 4 + 1] = f.y; v[t * 4 + 2] = f.z; v[t * 4 + 3] = f.w;
    }
    float s = 0.f;
#pragma unroll
    for (int t = 0; t < 16; t++) s += v[t];
#pragma unroll
    for (int o = 16; o; o >>= 1) s += __shfl_xor_sync(0xffffffffu, s, o);
    float mean = s * (1.0f / 512.0f);
    float q = 0.f;
#pragma unroll
    for (int t = 0; t < 16; t++) { float dd = v[t] - mean; q += dd * dd; }
#pragma unroll
    for (int o = 16; o; o >>= 1) q += __shfl_xor_sync(0xffffffffu, q, o);
    float rstd = rsqrtf(q * (1.0f / 512.0f) + 1e-5f);

    int c0 = lane << 4;
    float* dst = y + (size_t)warp * 512 + c0;
#pragma unroll
    for (int t = 0; t < 4; t++) {
        float4 gg = ((const float4*)(g + c0))[t];
        float4 bb = ((const float4*)(b + c0))[t];
        float4 out;
        out.x = rnd_tf32((v[t * 4 + 0] - mean) * rstd * gg.x + bb.x);
        out.y = rnd_tf32((v[t * 4 + 1] - mean) * rstd * gg.y + bb.y);
        out.z = rnd_tf32((v[t * 4 + 2] - mean) * rstd * gg.z + bb.z);
        out.w = rnd_tf32((v[t * 4 + 3] - mean) * rstd * gg.w + bb.w);
        ((float4*)dst)[t] = out;
    }
}

// ---------------------------------------------------------------------------
extern "C" void kernel_launch(void* const* d_in, const int* in_sizes, int n_in,
                              void* d_out, int out_size)
{
    const float* x       = (const float*)d_in[0];
    const float* ln1_g   = (const float*)d_in[1];
    const float* ln1_b   = (const float*)d_in[2];
    const float* qkv_w   = (const float*)d_in[3];
    const float* qkv_b   = (const float*)d_in[4];
    const float* proj_w  = (const float*)d_in[5];
    const float* proj_b  = (const float*)d_in[6];
    const float* ln2_g   = (const float*)d_in[7];
    const float* ln2_b   = (const float*)d_in[8];
    const float* mlp_w1  = (const float*)d_in[9];
    const float* mlp_b1  = (const float*)d_in[10];
    const float* mlp_w2  = (const float*)d_in[11];
    const float* mlp_b2  = (const float*)d_in[12];
    const float* dsn_g   = (const float*)d_in[13];
    const float* dsn_b   = (const float*)d_in[14];
    const float* ds_w    = (const float*)d_in[15];
    float* out           = (float*)d_out;

    float *gx, *gh, *go, *gds, *gwt;
    __nv_bfloat16 *gqb, *ghb, *gwtb;
    cudaGetSymbolAddress((void**)&gx,   g_x);
    cudaGetSymbolAddress((void**)&gh,   g_h);
    cudaGetSymbolAddress((void**)&gqb,  g_qkvb);
    cudaGetSymbolAddress((void**)&go,   g_o);
    cudaGetSymbolAddress((void**)&ghb,  g_hidb);
    cudaGetSymbolAddress((void**)&gds,  g_ds);
    cudaGetSymbolAddress((void**)&gwt,  g_wt);
    cudaGetSymbolAddress((void**)&gwtb, g_wtb);

    cudaFuncSetAttribute(gemm_mma<false, false, false, false>, cudaFuncAttributeMaxDynamicSharedMemorySize, GEMM_SMEM);
    cudaFuncSetAttribute(gemm_mma<false, false, false, true>,  cudaFuncAttributeMaxDynamicSharedMemorySize, GEMM_SMEM);
    cudaFuncSetAttribute(gemm_mma<false, true, false, false>,  cudaFuncAttributeMaxDynamicSharedMemorySize, GEMM_SMEM);
    cudaFuncSetAttribute(gemm_mma<true, false, false, false>,  cudaFuncAttributeMaxDynamicSharedMemorySize, GEMM_SMEM);
    cudaFuncSetAttribute(gemm_mma<false, true, true, false>,   cudaFuncAttributeMaxDynamicSharedMemorySize, GEMM_SMEM_LN);
    cudaFuncSetAttribute(gemm_bf16<false>, cudaFuncAttributeMaxDynamicSharedMemorySize, GEMM_SMEM);
    cudaFuncSetAttribute(gemm_bf16<true>,  cudaFuncAttributeMaxDynamicSharedMemorySize, GEMM_SMEM_LN);

    transpose_all<<<524288 / 256, 256>>>(qkv_w, proj_w, mlp_w1, mlp_w2, ds_w, gwt, gwtb);

    const dim3 attnGrid(4, 4096);

    // ---- layer 0
    ln128_kernel<<<TOK / 8, 256>>>(x, gh, ln1_g, ln1_b);
    gemm_mma<false, false, false, true><<<dim3(3, TOK / 128), 256, GEMM_SMEM>>>(
        gh, gwt + 0, qkv_b, nullptr, (float*)gqb, 384, 128, nullptr, nullptr, nullptr);
    attn_kernel<<<attnGrid, 128>>>(gqb, go, 0, 0);
    gemm_mma<false, true, true, false><<<dim3(1, TOK / 128), 256, GEMM_SMEM_LN>>>(
        go, gwt + 98304, proj_b, x, gx, 128, 128, ln2_g, ln2_b, gh);
    gemm_mma<true, false, false, false><<<dim3(4, TOK / 128), 256, GEMM_SMEM>>>(
        gh, gwt + 131072, mlp_b1, nullptr, (float*)ghb, 512, 128, nullptr, nullptr, nullptr);
    gemm_bf16<true><<<dim3(1, TOK / 128), 256, GEMM_SMEM_LN>>>(
        ghb, gwtb, mlp_b2, gx, gx, 128, 512, ln1_g + 128, ln1_b + 128, gh);

    // ---- layer 1 (shifted)
    gemm_mma<false, false, false, true><<<dim3(3, TOK / 128), 256, GEMM_SMEM>>>(
        gh, gwt + 49152, qkv_b + 384, nullptr, (float*)gqb, 384, 128, nullptr, nullptr, nullptr);
    attn_kernel<<<attnGrid, 128>>>(gqb, go, 3, 1);
    gemm_mma<false, true, true, false><<<dim3(1, TOK / 128), 256, GEMM_SMEM_LN>>>(
        go, gwt + 98304 + 16384, proj_b + 128, gx, gx, 128, 128, ln2_g + 128, ln2_b + 128, gh);
    gemm_mma<true, false, false, false><<<dim3(4, TOK / 128), 256, GEMM_SMEM>>>(
        gh, gwt + 131072 + 65536, mlp_b1 + 512, nullptr, (float*)ghb, 512, 128, nullptr, nullptr, nullptr);
    gemm_bf16<false><<<dim3(1, TOK / 128), 256, GEMM_SMEM>>>(
        ghb, gwtb + 65536, mlp_b2 + 128, gx, gx, 128, 512, nullptr, nullptr, nullptr);

    // ---- downsample (tf32 — output-facing precision)
    merge_ln_kernel<<<DSTOK / 8, 256>>>(gx, gds, dsn_g, dsn_b);
    gemm_mma<false, false, false, false><<<dim3(2, DSTOK / 128), 256, GEMM_SMEM>>>(
        gds, gwt + 393216, nullptr, nullptr, out, 256, 512, nullptr, nullptr, nullptr);
}